// round 5
// baseline (speedup 1.0000x reference)
#include <cuda_runtime.h>
#include <cuda_bf16.h>
#include <math.h>
#include <stdint.h>

#define E_DIM 512
#define T_DIM 1024
#define B_DIM 8
#define H_DIM 8
#define D_DIM 64
#define WIN   128
#define ROWS  (B_DIM * T_DIM)   // 8192
#define QKV_W (3 * E_DIM)       // 1536
#define K_DIM 512
#define KC    32                          // K per chunk (32 bf16 hi + 32 lo = 128B row)
#define NCHUNK (K_DIM / KC)               // 16
#define ATILE_BYTES (128 * 128)           // 16 KB  (rows: [hi 64B | lo 64B])
#define STAGE_BYTES (2 * ATILE_BYTES)     // A-tile + W-tile = 32 KB
#define NSTAGE 3
#define SMEM_GEMM (NSTAGE * STAGE_BYTES)  // 96 KB -> 2 CTAs/SM

// -------------------- scratch (__device__ globals) -------------------------
__device__ __nv_bfloat16 g_xn_hi [ROWS * E_DIM];
__device__ __nv_bfloat16 g_xn_lo [ROWS * E_DIM];
__device__ float         g_qkv   [ROWS * QKV_W];
__device__ __nv_bfloat16 g_ctx_hi[ROWS * E_DIM];
__device__ __nv_bfloat16 g_ctx_lo[ROWS * E_DIM];
__device__ __nv_bfloat16 g_win_hi[QKV_W * E_DIM];
__device__ __nv_bfloat16 g_win_lo[QKV_W * E_DIM];
__device__ __nv_bfloat16 g_wout_hi[E_DIM * E_DIM];
__device__ __nv_bfloat16 g_wout_lo[E_DIM * E_DIM];

// ============================ helpers ======================================
__device__ __forceinline__ uint32_t smem_u32(const void* p) {
    uint32_t a;
    asm("{ .reg .u64 t; cvta.to.shared.u64 t, %1; cvt.u32.u64 %0, t; }" : "=r"(a) : "l"(p));
    return a;
}
__device__ __forceinline__ void cp16(uint32_t dst, const void* src) {
    asm volatile("cp.async.cg.shared.global [%0], [%1], 16;" :: "r"(dst), "l"(src));
}
#define CP_COMMIT() asm volatile("cp.async.commit_group;" ::: "memory")
#define CP_WAIT2()  asm volatile("cp.async.wait_group 2;" ::: "memory")
#define CP_WAIT1()  asm volatile("cp.async.wait_group 1;" ::: "memory")
#define CP_WAIT0()  asm volatile("cp.async.wait_group 0;" ::: "memory")

#define LDSM4(R, addr)                                                          \
    asm volatile("ldmatrix.sync.aligned.m8n8.x4.shared.b16 {%0,%1,%2,%3}, [%4];" \
        : "=r"((R)[0]), "=r"((R)[1]), "=r"((R)[2]), "=r"((R)[3]) : "r"(addr))

#define MMA16816(D, A, B0, B1)                                                  \
    asm volatile("mma.sync.aligned.m16n8k16.row.col.f32.bf16.bf16.f32 "         \
        "{%0,%1,%2,%3},{%4,%5,%6,%7},{%8,%9},{%0,%1,%2,%3};"                    \
        : "+f"((D)[0]), "+f"((D)[1]), "+f"((D)[2]), "+f"((D)[3])                \
        : "r"((A)[0]), "r"((A)[1]), "r"((A)[2]), "r"((A)[3]), "r"(B0), "r"(B1))

__device__ __forceinline__ void split_bf16(float x, __nv_bfloat16& h, __nv_bfloat16& l) {
    h = __float2bfloat16(x);
    l = __float2bfloat16(x - __bfloat162float(h));
}

// ======================= LayerNorm -> bf16 hi/lo ===========================
__global__ __launch_bounds__(128) void ln_kernel(const float* __restrict__ x,
                                                 const float* __restrict__ gamma,
                                                 const float* __restrict__ beta) {
    const int row = blockIdx.x;
    const int tid = threadIdx.x;
    const float4 v = reinterpret_cast<const float4*>(x + (size_t)row * E_DIM)[tid];
    float s  = v.x + v.y + v.z + v.w;
    float ss = v.x * v.x + v.y * v.y + v.z * v.z + v.w * v.w;
    #pragma unroll
    for (int o = 16; o > 0; o >>= 1) {
        s  += __shfl_down_sync(0xffffffffu, s,  o);
        ss += __shfl_down_sync(0xffffffffu, ss, o);
    }
    __shared__ float sh_s[4], sh_ss[4], sh_mu, sh_rstd;
    const int w = tid >> 5, lane = tid & 31;
    if (lane == 0) { sh_s[w] = s; sh_ss[w] = ss; }
    __syncthreads();
    if (tid == 0) {
        float ts  = sh_s[0] + sh_s[1] + sh_s[2] + sh_s[3];
        float tss = sh_ss[0] + sh_ss[1] + sh_ss[2] + sh_ss[3];
        float mu  = ts * (1.0f / E_DIM);
        float var = tss * (1.0f / E_DIM) - mu * mu;
        sh_mu = mu; sh_rstd = rsqrtf(var + 1e-5f);
    }
    __syncthreads();
    const float mu = sh_mu, rstd = sh_rstd;
    const float4 g  = reinterpret_cast<const float4*>(gamma)[tid];
    const float4 be = reinterpret_cast<const float4*>(beta)[tid];
    float o[4];
    o[0] = (v.x - mu) * rstd * g.x + be.x;
    o[1] = (v.y - mu) * rstd * g.y + be.y;
    o[2] = (v.z - mu) * rstd * g.z + be.z;
    o[3] = (v.w - mu) * rstd * g.w + be.w;
    __nv_bfloat16 h[4], l[4];
    #pragma unroll
    for (int i = 0; i < 4; i++) split_bf16(o[i], h[i], l[i]);
    __nv_bfloat162* oh = reinterpret_cast<__nv_bfloat162*>(g_xn_hi + (size_t)row * E_DIM);
    __nv_bfloat162* ol = reinterpret_cast<__nv_bfloat162*>(g_xn_lo + (size_t)row * E_DIM);
    oh[2 * tid + 0] = __halves2bfloat162(h[0], h[1]);
    oh[2 * tid + 1] = __halves2bfloat162(h[2], h[3]);
    ol[2 * tid + 0] = __halves2bfloat162(l[0], l[1]);
    ol[2 * tid + 1] = __halves2bfloat162(l[2], l[3]);
}

// ===================== weight fp32 -> bf16 hi/lo (vectorized) ==============
__global__ __launch_bounds__(256) void conv_split(const float* __restrict__ src,
                                                  __nv_bfloat16* __restrict__ hi,
                                                  __nv_bfloat16* __restrict__ lo, int n4) {
    const int i = blockIdx.x * 256 + threadIdx.x;
    if (i < n4) {
        const float4 v = reinterpret_cast<const float4*>(src)[i];
        __nv_bfloat16 h[4], l[4];
        split_bf16(v.x, h[0], l[0]);
        split_bf16(v.y, h[1], l[1]);
        split_bf16(v.z, h[2], l[2]);
        split_bf16(v.w, h[3], l[3]);
        __nv_bfloat162* oh = reinterpret_cast<__nv_bfloat162*>(hi);
        __nv_bfloat162* ol = reinterpret_cast<__nv_bfloat162*>(lo);
        oh[2 * i + 0] = __halves2bfloat162(h[0], h[1]);
        oh[2 * i + 1] = __halves2bfloat162(h[2], h[3]);
        ol[2 * i + 0] = __halves2bfloat162(l[0], l[1]);
        ol[2 * i + 1] = __halves2bfloat162(l[2], l[3]);
    }
}

// ===================== bf16x3 GEMM via mma.sync (HMMA) =====================
// C[m,n] = bias[n] + sum_k A[m,k]*W[n,k]; A [M,K] rm, W [N,K] rm.
// CTA tile 128x128; 8 warps 2(M) x 4(N); warp tile 64x32.
// Stage (32 KB): A-tile rows [Ah(kc..kc+32)|Al(...)] 128B + W-tile same.
// 3 stages -> 96 KB smem -> 2 CTAs/SM for sync/latency overlap.
__global__ __launch_bounds__(256, 2)
void gemm_mma(const __nv_bfloat16* __restrict__ Ah, const __nv_bfloat16* __restrict__ Al,
              const __nv_bfloat16* __restrict__ Wh, const __nv_bfloat16* __restrict__ Wl,
              const float* __restrict__ bias, float* __restrict__ C, const int N) {
    extern __shared__ char smem[];
    const uint32_t sbase = smem_u32(smem);
    const int tid  = threadIdx.x;
    const int wid  = tid >> 5;
    const int lane = tid & 31;
    const int bn = blockIdx.x * 128;
    const int bm = blockIdx.y * 128;

    // loader: thread t -> tile (t>>7): 0=A,1=W; row (t&127); 8 cp16 (4 hi + 4 lo)
    const int ltile = tid >> 7;
    const int lrow  = tid & 127;
    const __nv_bfloat16* srcH = ltile ? (Wh + (size_t)(bn + lrow) * K_DIM)
                                      : (Ah + (size_t)(bm + lrow) * K_DIM);
    const __nv_bfloat16* srcL = ltile ? (Wl + (size_t)(bn + lrow) * K_DIM)
                                      : (Al + (size_t)(bm + lrow) * K_DIM);
    const uint32_t tbase = (uint32_t)ltile * ATILE_BYTES;
    uint32_t st_hi[4], st_lo[4];
    #pragma unroll
    for (int v = 0; v < 4; v++) {
        uint32_t offh = (uint32_t)lrow * 128u + (uint32_t)v * 16u;
        uint32_t offl = offh + 64u;
        st_hi[v] = tbase + (offh ^ ((offh >> 3) & 0x70u));
        st_lo[v] = tbase + (offl ^ ((offl >> 3) & 0x70u));
    }

    auto load_stage = [&](int s, int c) {
        const uint32_t st = sbase + (uint32_t)s * STAGE_BYTES;
        const int kc = c * KC;
        #pragma unroll
        for (int v = 0; v < 4; v++) {
            cp16(st + st_hi[v], srcH + kc + v * 8);
            cp16(st + st_lo[v], srcL + kc + v * 8);
        }
        CP_COMMIT();
    };

    // per-warp ldmatrix addressing
    const int wm = (wid & 1) * 64;
    const int wn = (wid >> 1) * 32;
    uint32_t a_rowoff[4], a_mask[4];
    #pragma unroll
    for (int mi = 0; mi < 4; mi++) {
        const uint32_t r = (uint32_t)(wm + mi * 16 + (lane & 15));
        a_rowoff[mi] = r * 128u;
        a_mask[mi]   = (a_rowoff[mi] >> 3) & 0x70u;
    }
    const uint32_t a_kb = ((uint32_t)lane >> 4) * 16u;
    const int b_lrow = (lane & 7) + ((lane >> 4) << 3);
    uint32_t b_rowoff[2], b_mask[2];
    #pragma unroll
    for (int np = 0; np < 2; np++) {
        const uint32_t r = (uint32_t)(wn + np * 16 + b_lrow);
        b_rowoff[np] = r * 128u;
        b_mask[np]   = (b_rowoff[np] >> 3) & 0x70u;
    }
    const uint32_t b_kb = (((uint32_t)lane >> 3) & 1u) * 16u;

    float acc[4][4][4];
    #pragma unroll
    for (int mi = 0; mi < 4; mi++)
        #pragma unroll
        for (int ni = 0; ni < 4; ni++)
            #pragma unroll
            for (int r = 0; r < 4; r++) acc[mi][ni][r] = 0.0f;

    load_stage(0, 0);
    load_stage(1, 1);
    load_stage(2, 2);

    for (int c = 0; c < NCHUNK; c++) {
        const int s = c % NSTAGE;
        const uint32_t st = sbase + (uint32_t)s * STAGE_BYTES;
        if (c <= NCHUNK - 3)      CP_WAIT2();
        else if (c == NCHUNK - 2) CP_WAIT1();
        else                      CP_WAIT0();
        __syncthreads();

        #pragma unroll
        for (int ks = 0; ks < 2; ks++) {
            const uint32_t akb_h = (uint32_t)ks * 32u + a_kb;       // hi bytes 0..63
            const uint32_t bkb_h = (uint32_t)ks * 32u + b_kb;
            uint32_t ah[4][4], al[4][4], bh[2][4], bl[2][4];
            #pragma unroll
            for (int mi = 0; mi < 4; mi++) {
                LDSM4(ah[mi], st + a_rowoff[mi] + (akb_h ^ a_mask[mi]));
                LDSM4(al[mi], st + a_rowoff[mi] + ((akb_h + 64u) ^ a_mask[mi]));
            }
            #pragma unroll
            for (int np = 0; np < 2; np++) {
                LDSM4(bh[np], st + ATILE_BYTES + b_rowoff[np] + (bkb_h ^ b_mask[np]));
                LDSM4(bl[np], st + ATILE_BYTES + b_rowoff[np] + ((bkb_h + 64u) ^ b_mask[np]));
            }
            // term-major: 16 independent MMAs between accumulator reuse
            #pragma unroll
            for (int mi = 0; mi < 4; mi++)
                #pragma unroll
                for (int ni = 0; ni < 4; ni++) {
                    const int np = ni >> 1, po = (ni & 1) * 2;
                    MMA16816(acc[mi][ni], ah[mi], bh[np][po], bh[np][po + 1]);
                }
            #pragma unroll
            for (int mi = 0; mi < 4; mi++)
                #pragma unroll
                for (int ni = 0; ni < 4; ni++) {
                    const int np = ni >> 1, po = (ni & 1) * 2;
                    MMA16816(acc[mi][ni], ah[mi], bl[np][po], bl[np][po + 1]);
                }
            #pragma unroll
            for (int mi = 0; mi < 4; mi++)
                #pragma unroll
                for (int ni = 0; ni < 4; ni++) {
                    const int np = ni >> 1, po = (ni & 1) * 2;
                    MMA16816(acc[mi][ni], al[mi], bh[np][po], bh[np][po + 1]);
                }
        }

        __syncthreads();
        if (c + NSTAGE < NCHUNK) load_stage(s, c + NSTAGE);
    }

    const int gid = lane >> 2;
    const int tig = lane & 3;
    float bv[4][2];
    #pragma unroll
    for (int ni = 0; ni < 4; ni++) {
        const int col = bn + wn + ni * 8 + tig * 2;
        bv[ni][0] = bias[col];
        bv[ni][1] = bias[col + 1];
    }
    #pragma unroll
    for (int mi = 0; mi < 4; mi++) {
        const int row0 = bm + wm + mi * 16 + gid;
        float* C0 = C + (size_t)row0 * N;
        float* C1 = C + (size_t)(row0 + 8) * N;
        #pragma unroll
        for (int ni = 0; ni < 4; ni++) {
            const int col = bn + wn + ni * 8 + tig * 2;
            float2 o0, o1;
            o0.x = acc[mi][ni][0] + bv[ni][0];
            o0.y = acc[mi][ni][1] + bv[ni][1];
            o1.x = acc[mi][ni][2] + bv[ni][0];
            o1.y = acc[mi][ni][3] + bv[ni][1];
            *reinterpret_cast<float2*>(C0 + col) = o0;
            *reinterpret_cast<float2*>(C1 + col) = o1;
        }
    }
}

// ===================== Windowed causal attention ==========================
// 4 threads per query (16 dims each); 512 threads = 128 queries per block.
// KV rows padded: 4 quarters of 20 floats (16 data + 4 pad) -> stride 80;
// quarter offsets hit disjoint bank groups (0-3, 20-23, 8-11, 28-31).
#define KV_STRIDE 80
#define ATTN_SMEM (2 * 128 * KV_STRIDE * 4)     // 81920 B

__global__ __launch_bounds__(512) void attn_kernel(const float* __restrict__ qkv) {
    extern __shared__ float smemf[];
    float* Ksb = smemf;
    float* Vsb = smemf + 128 * KV_STRIDE;

    const int qt   = blockIdx.x * 128;
    const int h    = blockIdx.y;
    const int b    = blockIdx.z;
    const int tid  = threadIdx.x;
    const int ql   = tid >> 2;                   // local query 0..127
    const int quar = tid & 3;                    // 16-dim quarter
    const int i    = qt + ql;
    const int warp = tid >> 5;
    const int wq   = qt + (warp << 3);           // warp covers 8 queries

    const float* qp = qkv + (size_t)(b * T_DIM + i) * QKV_W + h * D_DIM + quar * 16;
    float4 q[4], acc[4];
    #pragma unroll
    for (int d = 0; d < 4; d++) {
        q[d] = reinterpret_cast<const float4*>(qp)[d];
        acc[d] = make_float4(0.f, 0.f, 0.f, 0.f);
    }
    float l = 0.0f;

    for (int cs = qt - WIN; cs < qt + 128; cs += 128) {
        __syncthreads();
        const int j = cs + ql;
        if (j >= 0) {
            const float* kp = qkv + (size_t)(b * T_DIM + j) * QKV_W + E_DIM + h * D_DIM + quar * 16;
            float4* kd = reinterpret_cast<float4*>(Ksb + ql * KV_STRIDE + quar * 20);
            float4* vd = reinterpret_cast<float4*>(Vsb + ql * KV_STRIDE + quar * 20);
            #pragma unroll
            for (int d = 0; d < 4; d++) {
                kd[d] = reinterpret_cast<const float4*>(kp)[d];
                vd[d] = reinterpret_cast<const float4*>(kp + E_DIM)[d];
            }
        }
        __syncthreads();

        int ulo = cs;       if (wq - WIN > ulo) ulo = wq - WIN;  if (ulo < 0) ulo = 0;
        int uhi = cs + 127; if (wq + 7 < uhi) uhi = wq + 7;

        #pragma unroll 2
        for (int jj = ulo; jj <= uhi; jj++) {
            const float4* kr = reinterpret_cast<const float4*>(
                Ksb + (jj - cs) * KV_STRIDE + quar * 20);
            float s0 = 0.f, s1 = 0.f;
            #pragma unroll
            for (int d = 0; d < 4; d += 2) {
                const float4 k0 = kr[d], k1 = kr[d + 1];
                s0 += q[d].x   * k0.x + q[d].y   * k0.y + q[d].z   * k0.z + q[d].w   * k0.w;
                s1 += q[d+1].x * k1.x + q[d+1].y * k1.y + q[d+1].z * k1.z + q[d+1].w * k1.w;
            }
            float s = s0 + s1;
            s += __shfl_xor_sync(0xffffffffu, s, 1);
            s += __shfl_xor_sync(0xffffffffu, s, 2);
            const bool ok = (jj <= i) && (jj >= i - WIN);
            const float p = ok ? __expf(s * 0.125f) : 0.0f;
            l += p;
            const float4* vr = reinterpret_cast<const float4*>(
                Vsb + (jj - cs) * KV_STRIDE + quar * 20);
            #pragma unroll
            for (int d = 0; d < 4; d++) {
                const float4 vv = vr[d];
                acc[d].x = fmaf(p, vv.x, acc[d].x);
                acc[d].y = fmaf(p, vv.y, acc[d].y);
                acc[d].z = fmaf(p, vv.z, acc[d].z);
                acc[d].w = fmaf(p, vv.w, acc[d].w);
            }
        }
    }

    const float rinv = 1.0f / l;
    const size_t obase = (size_t)(b * T_DIM + i) * E_DIM + h * D_DIM + quar * 16;
    __nv_bfloat162* oh = reinterpret_cast<__nv_bfloat162*>(g_ctx_hi + obase);
    __nv_bfloat162* ol = reinterpret_cast<__nv_bfloat162*>(g_ctx_lo + obase);
    #pragma unroll
    for (int d = 0; d < 4; d++) {
        float o[4] = {acc[d].x * rinv, acc[d].y * rinv, acc[d].z * rinv, acc[d].w * rinv};
        __nv_bfloat16 h4[4], l4[4];
        #pragma unroll
        for (int t = 0; t < 4; t++) split_bf16(o[t], h4[t], l4[t]);
        oh[2 * d + 0] = __halves2bfloat162(h4[0], h4[1]);
        oh[2 * d + 1] = __halves2bfloat162(h4[2], h4[3]);
        ol[2 * d + 0] = __halves2bfloat162(l4[0], l4[1]);
        ol[2 * d + 1] = __halves2bfloat162(l4[2], l4[3]);
    }
}

// ============================== launch ====================================
extern "C" void kernel_launch(void* const* d_in, const int* in_sizes, int n_in,
                              void* d_out, int out_size) {
    const float* x     = (const float*)d_in[0];
    const float* gamma = (const float*)d_in[2];
    const float* beta  = (const float*)d_in[3];
    const float* w_in  = (const float*)d_in[4];
    const float* b_in  = (const float*)d_in[5];
    const float* w_out = (const float*)d_in[6];
    const float* b_out = (const float*)d_in[7];
    float* out = (float*)d_out;

    __nv_bfloat16 *xn_hi, *xn_lo, *ctx_hi, *ctx_lo, *win_hi, *win_lo, *wout_hi, *wout_lo;
    float* qkv;
    cudaGetSymbolAddress((void**)&xn_hi,  g_xn_hi);
    cudaGetSymbolAddress((void**)&xn_lo,  g_xn_lo);
    cudaGetSymbolAddress((void**)&qkv,    g_qkv);
    cudaGetSymbolAddress((void**)&ctx_hi, g_ctx_hi);
    cudaGetSymbolAddress((void**)&ctx_lo, g_ctx_lo);
    cudaGetSymbolAddress((void**)&win_hi, g_win_hi);
    cudaGetSymbolAddress((void**)&win_lo, g_win_lo);
    cudaGetSymbolAddress((void**)&wout_hi, g_wout_hi);
    cudaGetSymbolAddress((void**)&wout_lo, g_wout_lo);

    cudaFuncSetAttribute(gemm_mma, cudaFuncAttributeMaxDynamicSharedMemorySize, SMEM_GEMM);
    cudaFuncSetAttribute(attn_kernel, cudaFuncAttributeMaxDynamicSharedMemorySize, ATTN_SMEM);

    ln_kernel<<<ROWS, 128>>>(x, gamma, beta);
    conv_split<<<(QKV_W * E_DIM / 4 + 255) / 256, 256>>>(w_in, win_hi, win_lo, QKV_W * E_DIM / 4);
    conv_split<<<(E_DIM * E_DIM / 4 + 255) / 256, 256>>>(w_out, wout_hi, wout_lo, E_DIM * E_DIM / 4);
    gemm_mma<<<dim3(QKV_W / 128, ROWS / 128), 256, SMEM_GEMM>>>(
        xn_hi, xn_lo, win_hi, win_lo, b_in, qkv, QKV_W);
    attn_kernel<<<dim3(T_DIM / 128, H_DIM, B_DIM), 512, ATTN_SMEM>>>(qkv);
    gemm_mma<<<dim3(E_DIM / 128, ROWS / 128), 256, SMEM_GEMM>>>(
        ctx_hi, ctx_lo, wout_hi, wout_lo, b_out, out, E_DIM);
}

// round 6
// speedup vs baseline: 1.1590x; 1.1590x over previous
#include <cuda_runtime.h>
#include <cuda_bf16.h>
#include <math.h>
#include <stdint.h>

#define E_DIM 512
#define T_DIM 1024
#define B_DIM 8
#define H_DIM 8
#define D_DIM 64
#define WIN   128
#define ROWS  (B_DIM * T_DIM)   // 8192
#define QKV_W (3 * E_DIM)       // 1536
#define K_DIM 512
#define KC    64                          // K per chunk
#define NCHUNK (K_DIM / KC)               // 8
// stage layout: [A0 16K][A1 16K][W0 32K][W1 32K]; rows are 128B = [hi 64B | lo 64B] per 32-K
#define A_SUB  16384
#define W_SUB  32768
#define W_OFF  32768
#define STAGE_BYTES (W_OFF + 2 * W_SUB)   // 96 KB
#define NSTAGE 2
#define SMEM_GEMM (NSTAGE * STAGE_BYTES)  // 192 KB

// -------------------- scratch (__device__ globals) -------------------------
__device__ __nv_bfloat16 g_xn_hi [ROWS * E_DIM];
__device__ __nv_bfloat16 g_xn_lo [ROWS * E_DIM];
__device__ float         g_qkv   [ROWS * QKV_W];
__device__ __nv_bfloat16 g_ctx_hi[ROWS * E_DIM];
__device__ __nv_bfloat16 g_ctx_lo[ROWS * E_DIM];
__device__ __nv_bfloat16 g_win_hi[QKV_W * E_DIM];
__device__ __nv_bfloat16 g_win_lo[QKV_W * E_DIM];
__device__ __nv_bfloat16 g_wout_hi[E_DIM * E_DIM];
__device__ __nv_bfloat16 g_wout_lo[E_DIM * E_DIM];

// ============================ helpers ======================================
__device__ __forceinline__ uint32_t smem_u32(const void* p) {
    uint32_t a;
    asm("{ .reg .u64 t; cvta.to.shared.u64 t, %1; cvt.u32.u64 %0, t; }" : "=r"(a) : "l"(p));
    return a;
}
__device__ __forceinline__ void cp16(uint32_t dst, const void* src) {
    asm volatile("cp.async.cg.shared.global [%0], [%1], 16;" :: "r"(dst), "l"(src));
}
#define CP_COMMIT() asm volatile("cp.async.commit_group;" ::: "memory")
#define CP_WAIT1()  asm volatile("cp.async.wait_group 1;" ::: "memory")
#define CP_WAIT0()  asm volatile("cp.async.wait_group 0;" ::: "memory")

#define LDSM4(R, addr)                                                          \
    asm volatile("ldmatrix.sync.aligned.m8n8.x4.shared.b16 {%0,%1,%2,%3}, [%4];" \
        : "=r"((R)[0]), "=r"((R)[1]), "=r"((R)[2]), "=r"((R)[3]) : "r"(addr))

#define MMA16816(D, A, B0, B1)                                                  \
    asm volatile("mma.sync.aligned.m16n8k16.row.col.f32.bf16.bf16.f32 "         \
        "{%0,%1,%2,%3},{%4,%5,%6,%7},{%8,%9},{%0,%1,%2,%3};"                    \
        : "+f"((D)[0]), "+f"((D)[1]), "+f"((D)[2]), "+f"((D)[3])                \
        : "r"((A)[0]), "r"((A)[1]), "r"((A)[2]), "r"((A)[3]), "r"(B0), "r"(B1))

__device__ __forceinline__ void split_bf16(float x, __nv_bfloat16& h, __nv_bfloat16& l) {
    h = __float2bfloat16(x);
    l = __float2bfloat16(x - __bfloat162float(h));
}
__device__ __forceinline__ uint32_t swz(uint32_t off) {
    return off ^ ((off >> 3) & 0x70u);
}

// ======================= LayerNorm -> bf16 hi/lo ===========================
__global__ __launch_bounds__(128) void ln_kernel(const float* __restrict__ x,
                                                 const float* __restrict__ gamma,
                                                 const float* __restrict__ beta) {
    const int row = blockIdx.x;
    const int tid = threadIdx.x;
    const float4 v = reinterpret_cast<const float4*>(x + (size_t)row * E_DIM)[tid];
    float s  = v.x + v.y + v.z + v.w;
    float ss = v.x * v.x + v.y * v.y + v.z * v.z + v.w * v.w;
    #pragma unroll
    for (int o = 16; o > 0; o >>= 1) {
        s  += __shfl_down_sync(0xffffffffu, s,  o);
        ss += __shfl_down_sync(0xffffffffu, ss, o);
    }
    __shared__ float sh_s[4], sh_ss[4], sh_mu, sh_rstd;
    const int w = tid >> 5, lane = tid & 31;
    if (lane == 0) { sh_s[w] = s; sh_ss[w] = ss; }
    __syncthreads();
    if (tid == 0) {
        float ts  = sh_s[0] + sh_s[1] + sh_s[2] + sh_s[3];
        float tss = sh_ss[0] + sh_ss[1] + sh_ss[2] + sh_ss[3];
        float mu  = ts * (1.0f / E_DIM);
        float var = tss * (1.0f / E_DIM) - mu * mu;
        sh_mu = mu; sh_rstd = rsqrtf(var + 1e-5f);
    }
    __syncthreads();
    const float mu = sh_mu, rstd = sh_rstd;
    const float4 g  = reinterpret_cast<const float4*>(gamma)[tid];
    const float4 be = reinterpret_cast<const float4*>(beta)[tid];
    float o[4];
    o[0] = (v.x - mu) * rstd * g.x + be.x;
    o[1] = (v.y - mu) * rstd * g.y + be.y;
    o[2] = (v.z - mu) * rstd * g.z + be.z;
    o[3] = (v.w - mu) * rstd * g.w + be.w;
    __nv_bfloat16 h[4], l[4];
    #pragma unroll
    for (int i = 0; i < 4; i++) split_bf16(o[i], h[i], l[i]);
    __nv_bfloat162* oh = reinterpret_cast<__nv_bfloat162*>(g_xn_hi + (size_t)row * E_DIM);
    __nv_bfloat162* ol = reinterpret_cast<__nv_bfloat162*>(g_xn_lo + (size_t)row * E_DIM);
    oh[2 * tid + 0] = __halves2bfloat162(h[0], h[1]);
    oh[2 * tid + 1] = __halves2bfloat162(h[2], h[3]);
    ol[2 * tid + 0] = __halves2bfloat162(l[0], l[1]);
    ol[2 * tid + 1] = __halves2bfloat162(l[2], l[3]);
}

// ===================== weight fp32 -> bf16 hi/lo (vectorized) ==============
__global__ __launch_bounds__(256) void conv_split(const float* __restrict__ src,
                                                  __nv_bfloat16* __restrict__ hi,
                                                  __nv_bfloat16* __restrict__ lo, int n4) {
    const int i = blockIdx.x * 256 + threadIdx.x;
    if (i < n4) {
        const float4 v = reinterpret_cast<const float4*>(src)[i];
        __nv_bfloat16 h[4], l[4];
        split_bf16(v.x, h[0], l[0]);
        split_bf16(v.y, h[1], l[1]);
        split_bf16(v.z, h[2], l[2]);
        split_bf16(v.w, h[3], l[3]);
        __nv_bfloat162* oh = reinterpret_cast<__nv_bfloat162*>(hi);
        __nv_bfloat162* ol = reinterpret_cast<__nv_bfloat162*>(lo);
        oh[2 * i + 0] = __halves2bfloat162(h[0], h[1]);
        oh[2 * i + 1] = __halves2bfloat162(h[2], h[3]);
        ol[2 * i + 0] = __halves2bfloat162(l[0], l[1]);
        ol[2 * i + 1] = __halves2bfloat162(l[2], l[3]);
    }
}

// ===================== bf16x3 GEMM via mma.sync (HMMA) =====================
// C[m,n] = bias[n] + sum_k A[m,k]*W[n,k]; A [M,K] rm, W [N,K] rm.
// CTA tile 128x256; 8 warps 2(M) x 4(N); warp tile 64x64; 2-stage cp.async.
__global__ __launch_bounds__(256)
void gemm_mma(const __nv_bfloat16* __restrict__ Ah, const __nv_bfloat16* __restrict__ Al,
              const __nv_bfloat16* __restrict__ Wh, const __nv_bfloat16* __restrict__ Wl,
              const float* __restrict__ bias, float* __restrict__ C, const int N) {
    extern __shared__ char smem[];
    const uint32_t sbase = smem_u32(smem);
    const int tid  = threadIdx.x;
    const int wid  = tid >> 5;
    const int lane = tid & 31;
    const int bn = blockIdx.x * 256;
    const int bm = blockIdx.y * 128;

    // ---- loaders: each thread does 24 cp16 per stage ----
    // A: thread t -> row t>>1, k-subtile t&1 (8 cp16)
    const int arow = tid >> 1;
    const int asub = tid & 1;
    const __nv_bfloat16* aH = Ah + (size_t)(bm + arow) * K_DIM + asub * 32;
    const __nv_bfloat16* aL = Al + (size_t)(bm + arow) * K_DIM + asub * 32;
    uint32_t a_st[8];
    #pragma unroll
    for (int v = 0; v < 4; v++) {
        const uint32_t offh = (uint32_t)arow * 128u + (uint32_t)v * 16u;
        a_st[v]     = (uint32_t)asub * A_SUB + swz(offh);
        a_st[4 + v] = (uint32_t)asub * A_SUB + swz(offh + 64u);
    }
    // W: thread t -> row t, both subtiles (16 cp16)
    const __nv_bfloat16* wH = Wh + (size_t)(bn + tid) * K_DIM;
    const __nv_bfloat16* wL = Wl + (size_t)(bn + tid) * K_DIM;
    uint32_t w_st[16];
    #pragma unroll
    for (int sub = 0; sub < 2; sub++)
        #pragma unroll
        for (int v = 0; v < 4; v++) {
            const uint32_t offh = (uint32_t)tid * 128u + (uint32_t)v * 16u;
            w_st[sub * 8 + v]     = W_OFF + sub * W_SUB + swz(offh);
            w_st[sub * 8 + 4 + v] = W_OFF + sub * W_SUB + swz(offh + 64u);
        }

    auto load_stage = [&](int s, int c) {
        const uint32_t st = sbase + (uint32_t)s * STAGE_BYTES;
        const int kc = c * KC;
        #pragma unroll
        for (int v = 0; v < 4; v++) {
            cp16(st + a_st[v],     aH + kc + v * 8);
            cp16(st + a_st[4 + v], aL + kc + v * 8);
        }
        #pragma unroll
        for (int sub = 0; sub < 2; sub++)
            #pragma unroll
            for (int v = 0; v < 4; v++) {
                cp16(st + w_st[sub * 8 + v],     wH + kc + sub * 32 + v * 8);
                cp16(st + w_st[sub * 8 + 4 + v], wL + kc + sub * 32 + v * 8);
            }
        CP_COMMIT();
    };

    // ---- per-warp ldmatrix addressing ----
    const int wm = (wid & 1) * 64;
    const int wn = (wid >> 1) * 64;
    uint32_t a_rowoff[4], a_mask[4];
    #pragma unroll
    for (int mi = 0; mi < 4; mi++) {
        const uint32_t r = (uint32_t)(wm + mi * 16 + (lane & 15));
        a_rowoff[mi] = r * 128u;
        a_mask[mi]   = (a_rowoff[mi] >> 3) & 0x70u;
    }
    const uint32_t a_kb = ((uint32_t)lane >> 4) * 16u;
    const int b_lrow = (lane & 7) + ((lane >> 4) << 3);
    uint32_t b_rowoff[4], b_mask[4];
    #pragma unroll
    for (int np = 0; np < 4; np++) {
        const uint32_t r = (uint32_t)(wn + np * 16 + b_lrow);
        b_rowoff[np] = r * 128u;
        b_mask[np]   = (b_rowoff[np] >> 3) & 0x70u;
    }
    const uint32_t b_kb = (((uint32_t)lane >> 3) & 1u) * 16u;

    float acc[4][8][4];
    #pragma unroll
    for (int mi = 0; mi < 4; mi++)
        #pragma unroll
        for (int ni = 0; ni < 8; ni++)
            #pragma unroll
            for (int r = 0; r < 4; r++) acc[mi][ni][r] = 0.0f;

    load_stage(0, 0);
    load_stage(1, 1);

    for (int c = 0; c < NCHUNK; c++) {
        const int s = c & 1;
        const uint32_t st = sbase + (uint32_t)s * STAGE_BYTES;
        if (c + 2 <= NCHUNK) { if (c + 2 < NCHUNK || c == NCHUNK - 2) CP_WAIT1(); }
        if (c == NCHUNK - 1) CP_WAIT0();
        __syncthreads();

        #pragma unroll
        for (int ks = 0; ks < 4; ks++) {
            const uint32_t Ab = st + (uint32_t)(ks >> 1) * A_SUB;
            const uint32_t Wb = st + W_OFF + (uint32_t)(ks >> 1) * W_SUB;
            const uint32_t akb = (uint32_t)(ks & 1) * 32u + a_kb;
            const uint32_t bkb = (uint32_t)(ks & 1) * 32u + b_kb;
            uint32_t ah[4][4], al[4][4], bh[4][4], bl[4][4];
            #pragma unroll
            for (int mi = 0; mi < 4; mi++) {
                LDSM4(ah[mi], Ab + a_rowoff[mi] + (akb ^ a_mask[mi]));
                LDSM4(al[mi], Ab + a_rowoff[mi] + ((akb + 64u) ^ a_mask[mi]));
            }
            #pragma unroll
            for (int np = 0; np < 4; np++) {
                LDSM4(bh[np], Wb + b_rowoff[np] + (bkb ^ b_mask[np]));
                LDSM4(bl[np], Wb + b_rowoff[np] + ((bkb + 64u) ^ b_mask[np]));
            }
            // term-major: 32 independent MMAs between accumulator reuse
            #pragma unroll
            for (int mi = 0; mi < 4; mi++)
                #pragma unroll
                for (int ni = 0; ni < 8; ni++) {
                    const int np = ni >> 1, po = (ni & 1) * 2;
                    MMA16816(acc[mi][ni], ah[mi], bh[np][po], bh[np][po + 1]);
                }
            #pragma unroll
            for (int mi = 0; mi < 4; mi++)
                #pragma unroll
                for (int ni = 0; ni < 8; ni++) {
                    const int np = ni >> 1, po = (ni & 1) * 2;
                    MMA16816(acc[mi][ni], ah[mi], bl[np][po], bl[np][po + 1]);
                }
            #pragma unroll
            for (int mi = 0; mi < 4; mi++)
                #pragma unroll
                for (int ni = 0; ni < 8; ni++) {
                    const int np = ni >> 1, po = (ni & 1) * 2;
                    MMA16816(acc[mi][ni], al[mi], bh[np][po], bh[np][po + 1]);
                }
        }

        __syncthreads();
        if (c + 2 < NCHUNK) load_stage(s, c + 2);
    }

    // ---- epilogue ----
    const int gid = lane >> 2;
    const int tig = lane & 3;
    #pragma unroll
    for (int mi = 0; mi < 4; mi++) {
        const int row0 = bm + wm + mi * 16 + gid;
        float* C0 = C + (size_t)row0 * N;
        float* C1 = C + (size_t)(row0 + 8) * N;
        #pragma unroll
        for (int ni = 0; ni < 8; ni++) {
            const int col = bn + wn + ni * 8 + tig * 2;
            const float b0 = bias[col], b1 = bias[col + 1];
            float2 o0, o1;
            o0.x = acc[mi][ni][0] + b0;
            o0.y = acc[mi][ni][1] + b1;
            o1.x = acc[mi][ni][2] + b0;
            o1.y = acc[mi][ni][3] + b1;
            *reinterpret_cast<float2*>(C0 + col) = o0;
            *reinterpret_cast<float2*>(C1 + col) = o1;
        }
    }
}

// ===================== Windowed causal attention ==========================
// 2 threads per query (each owns 32 of 64 dims); 256 threads = 128 queries.
#define KV_STRIDE 72
#define ATTN_SMEM (2 * 128 * KV_STRIDE * 4)     // 73728 B

__global__ __launch_bounds__(256) void attn_kernel(const float* __restrict__ qkv) {
    extern __shared__ float smemf[];
    float* Ksb = smemf;
    float* Vsb = smemf + 128 * KV_STRIDE;

    const int qt  = blockIdx.x * 128;
    const int h   = blockIdx.y;
    const int b   = blockIdx.z;
    const int tid = threadIdx.x;
    const int ql  = tid >> 1;
    const int half = tid & 1;
    const int i   = qt + ql;
    const int warp = tid >> 5;
    const int wq   = qt + (warp << 4);

    const float* qp = qkv + (size_t)(b * T_DIM + i) * QKV_W + h * D_DIM + half * 32;
    float4 q[8], acc[8];
    #pragma unroll
    for (int d = 0; d < 8; d++) {
        q[d] = reinterpret_cast<const float4*>(qp)[d];
        acc[d] = make_float4(0.f, 0.f, 0.f, 0.f);
    }
    float l = 0.0f;

    for (int cs = qt - WIN; cs < qt + 128; cs += 128) {
        __syncthreads();
        const int j = cs + ql;
        if (j >= 0) {
            const float* kp = qkv + (size_t)(b * T_DIM + j) * QKV_W + E_DIM + h * D_DIM + half * 32;
            float4* kd = reinterpret_cast<float4*>(Ksb + ql * KV_STRIDE + half * 36);
            float4* vd = reinterpret_cast<float4*>(Vsb + ql * KV_STRIDE + half * 36);
            #pragma unroll
            for (int d = 0; d < 8; d++) {
                kd[d] = reinterpret_cast<const float4*>(kp)[d];
                vd[d] = reinterpret_cast<const float4*>(kp + E_DIM)[d];
            }
        }
        __syncthreads();

        int ulo = cs;       if (wq - WIN > ulo) ulo = wq - WIN;  if (ulo < 0) ulo = 0;
        int uhi = cs + 127; if (wq + 15 < uhi) uhi = wq + 15;

        for (int jj = ulo; jj <= uhi; jj++) {
            const float4* kr = reinterpret_cast<const float4*>(
                Ksb + (jj - cs) * KV_STRIDE + half * 36);
            float s0 = 0.f, s1 = 0.f;
            #pragma unroll
            for (int d = 0; d < 8; d += 2) {
                const float4 k0 = kr[d], k1 = kr[d + 1];
                s0 += q[d].x   * k0.x + q[d].y   * k0.y + q[d].z   * k0.z + q[d].w   * k0.w;
                s1 += q[d+1].x * k1.x + q[d+1].y * k1.y + q[d+1].z * k1.z + q[d+1].w * k1.w;
            }
            const float sp = s0 + s1;
            const float s = sp + __shfl_xor_sync(0xffffffffu, sp, 1);
            const bool ok = (jj <= i) && (jj >= i - WIN);
            const float p = ok ? __expf(s * 0.125f) : 0.0f;
            l += p;
            const float4* vr = reinterpret_cast<const float4*>(
                Vsb + (jj - cs) * KV_STRIDE + half * 36);
            #pragma unroll
            for (int d = 0; d < 8; d++) {
                const float4 vv = vr[d];
                acc[d].x = fmaf(p, vv.x, acc[d].x);
                acc[d].y = fmaf(p, vv.y, acc[d].y);
                acc[d].z = fmaf(p, vv.z, acc[d].z);
                acc[d].w = fmaf(p, vv.w, acc[d].w);
            }
        }
    }

    const float rinv = 1.0f / l;
    const size_t obase = (size_t)(b * T_DIM + i) * E_DIM + h * D_DIM + half * 32;
    __nv_bfloat162* oh = reinterpret_cast<__nv_bfloat162*>(g_ctx_hi + obase);
    __nv_bfloat162* ol = reinterpret_cast<__nv_bfloat162*>(g_ctx_lo + obase);
    #pragma unroll
    for (int d = 0; d < 8; d++) {
        float o[4] = {acc[d].x * rinv, acc[d].y * rinv, acc[d].z * rinv, acc[d].w * rinv};
        __nv_bfloat16 h4[4], l4[4];
        #pragma unroll
        for (int t = 0; t < 4; t++) split_bf16(o[t], h4[t], l4[t]);
        oh[2 * d + 0] = __halves2bfloat162(h4[0], h4[1]);
        oh[2 * d + 1] = __halves2bfloat162(h4[2], h4[3]);
        ol[2 * d + 0] = __halves2bfloat162(l4[0], l4[1]);
        ol[2 * d + 1] = __halves2bfloat162(l4[2], l4[3]);
    }
}

// ============================== launch ====================================
extern "C" void kernel_launch(void* const* d_in, const int* in_sizes, int n_in,
                              void* d_out, int out_size) {
    const float* x     = (const float*)d_in[0];
    const float* gamma = (const float*)d_in[2];
    const float* beta  = (const float*)d_in[3];
    const float* w_in  = (const float*)d_in[4];
    const float* b_in  = (const float*)d_in[5];
    const float* w_out = (const float*)d_in[6];
    const float* b_out = (const float*)d_in[7];
    float* out = (float*)d_out;

    __nv_bfloat16 *xn_hi, *xn_lo, *ctx_hi, *ctx_lo, *win_hi, *win_lo, *wout_hi, *wout_lo;
    float* qkv;
    cudaGetSymbolAddress((void**)&xn_hi,  g_xn_hi);
    cudaGetSymbolAddress((void**)&xn_lo,  g_xn_lo);
    cudaGetSymbolAddress((void**)&qkv,    g_qkv);
    cudaGetSymbolAddress((void**)&ctx_hi, g_ctx_hi);
    cudaGetSymbolAddress((void**)&ctx_lo, g_ctx_lo);
    cudaGetSymbolAddress((void**)&win_hi, g_win_hi);
    cudaGetSymbolAddress((void**)&win_lo, g_win_lo);
    cudaGetSymbolAddress((void**)&wout_hi, g_wout_hi);
    cudaGetSymbolAddress((void**)&wout_lo, g_wout_lo);

    cudaFuncSetAttribute(gemm_mma, cudaFuncAttributeMaxDynamicSharedMemorySize, SMEM_GEMM);
    cudaFuncSetAttribute(attn_kernel, cudaFuncAttributeMaxDynamicSharedMemorySize, ATTN_SMEM);

    ln_kernel<<<ROWS, 128>>>(x, gamma, beta);
    conv_split<<<(QKV_W * E_DIM / 4 + 255) / 256, 256>>>(w_in, win_hi, win_lo, QKV_W * E_DIM / 4);
    conv_split<<<(E_DIM * E_DIM / 4 + 255) / 256, 256>>>(w_out, wout_hi, wout_lo, E_DIM * E_DIM / 4);
    gemm_mma<<<dim3(QKV_W / 256, ROWS / 128), 256, SMEM_GEMM>>>(
        xn_hi, xn_lo, win_hi, win_lo, b_in, qkv, QKV_W);
    attn_kernel<<<dim3(T_DIM / 128, H_DIM, B_DIM), 256, ATTN_SMEM>>>(qkv);
    gemm_mma<<<dim3(E_DIM / 256, ROWS / 128), 256, SMEM_GEMM>>>(
        ctx_hi, ctx_lo, wout_hi, wout_lo, b_out, out, E_DIM);
}

// round 7
// speedup vs baseline: 1.5757x; 1.3595x over previous
#include <cuda_runtime.h>
#include <cuda_fp16.h>
#include <math.h>
#include <stdint.h>

#define E_DIM 512
#define T_DIM 1024
#define B_DIM 8
#define H_DIM 8
#define D_DIM 64
#define WIN   128
#define ROWS  (B_DIM * T_DIM)   // 8192
#define QKV_W (3 * E_DIM)       // 1536
#define K_DIM 512
#define KC    64                          // K per chunk (64 fp16 = 128B rows)
#define NCHUNK (K_DIM / KC)               // 8
#define TILE_BYTES (128 * 128)            // 16 KB per tile
#define WH_OFF TILE_BYTES                 // W_hi tile offset in stage
#define WL_OFF (2 * TILE_BYTES)           // W_lo tile offset
#define STAGE_BYTES (3 * TILE_BYTES)      // A + Wh + Wl = 48 KB
#define NSTAGE 2
#define SMEM_GEMM (NSTAGE * STAGE_BYTES)  // 96 KB -> 2 CTAs/SM

// -------------------- scratch (__device__ globals) -------------------------
__device__ __half g_xn  [ROWS * E_DIM];
__device__ float  g_qkv [ROWS * QKV_W];
__device__ __half g_ctx [ROWS * E_DIM];
__device__ __half g_win_hi[QKV_W * E_DIM];
__device__ __half g_win_lo[QKV_W * E_DIM];
__device__ __half g_wout_hi[E_DIM * E_DIM];
__device__ __half g_wout_lo[E_DIM * E_DIM];

// ============================ helpers ======================================
__device__ __forceinline__ uint32_t smem_u32(const void* p) {
    uint32_t a;
    asm("{ .reg .u64 t; cvta.to.shared.u64 t, %1; cvt.u32.u64 %0, t; }" : "=r"(a) : "l"(p));
    return a;
}
__device__ __forceinline__ void cp16(uint32_t dst, const void* src) {
    asm volatile("cp.async.cg.shared.global [%0], [%1], 16;" :: "r"(dst), "l"(src));
}
#define CP_COMMIT() asm volatile("cp.async.commit_group;" ::: "memory")
#define CP_WAIT1()  asm volatile("cp.async.wait_group 1;" ::: "memory")
#define CP_WAIT0()  asm volatile("cp.async.wait_group 0;" ::: "memory")

#define LDSM4(R, addr)                                                          \
    asm volatile("ldmatrix.sync.aligned.m8n8.x4.shared.b16 {%0,%1,%2,%3}, [%4];" \
        : "=r"((R)[0]), "=r"((R)[1]), "=r"((R)[2]), "=r"((R)[3]) : "r"(addr))

#define MMA16816H(D, A, B0, B1)                                                 \
    asm volatile("mma.sync.aligned.m16n8k16.row.col.f32.f16.f16.f32 "           \
        "{%0,%1,%2,%3},{%4,%5,%6,%7},{%8,%9},{%0,%1,%2,%3};"                    \
        : "+f"((D)[0]), "+f"((D)[1]), "+f"((D)[2]), "+f"((D)[3])                \
        : "r"((A)[0]), "r"((A)[1]), "r"((A)[2]), "r"((A)[3]), "r"(B0), "r"(B1))

__device__ __forceinline__ void split_fp16(float x, __half& h, __half& l) {
    h = __float2half(x);
    l = __float2half(x - __half2float(h));
}
__device__ __forceinline__ uint32_t swz(uint32_t off) {
    return off ^ ((off >> 3) & 0x70u);
}

// ======================= LayerNorm -> fp16 =================================
__global__ __launch_bounds__(128) void ln_kernel(const float* __restrict__ x,
                                                 const float* __restrict__ gamma,
                                                 const float* __restrict__ beta) {
    const int row = blockIdx.x;
    const int tid = threadIdx.x;
    const float4 v = reinterpret_cast<const float4*>(x + (size_t)row * E_DIM)[tid];
    float s  = v.x + v.y + v.z + v.w;
    float ss = v.x * v.x + v.y * v.y + v.z * v.z + v.w * v.w;
    #pragma unroll
    for (int o = 16; o > 0; o >>= 1) {
        s  += __shfl_down_sync(0xffffffffu, s,  o);
        ss += __shfl_down_sync(0xffffffffu, ss, o);
    }
    __shared__ float sh_s[4], sh_ss[4], sh_mu, sh_rstd;
    const int w = tid >> 5, lane = tid & 31;
    if (lane == 0) { sh_s[w] = s; sh_ss[w] = ss; }
    __syncthreads();
    if (tid == 0) {
        float ts  = sh_s[0] + sh_s[1] + sh_s[2] + sh_s[3];
        float tss = sh_ss[0] + sh_ss[1] + sh_ss[2] + sh_ss[3];
        float mu  = ts * (1.0f / E_DIM);
        float var = tss * (1.0f / E_DIM) - mu * mu;
        sh_mu = mu; sh_rstd = rsqrtf(var + 1e-5f);
    }
    __syncthreads();
    const float mu = sh_mu, rstd = sh_rstd;
    const float4 g  = reinterpret_cast<const float4*>(gamma)[tid];
    const float4 be = reinterpret_cast<const float4*>(beta)[tid];
    float2 a, b;
    a.x = (v.x - mu) * rstd * g.x + be.x;
    a.y = (v.y - mu) * rstd * g.y + be.y;
    b.x = (v.z - mu) * rstd * g.z + be.z;
    b.y = (v.w - mu) * rstd * g.w + be.w;
    __half2* o = reinterpret_cast<__half2*>(g_xn + (size_t)row * E_DIM);
    o[2 * tid + 0] = __float22half2_rn(a);
    o[2 * tid + 1] = __float22half2_rn(b);
}

// ===================== weight fp32 -> fp16 hi/lo ===========================
__global__ __launch_bounds__(256) void conv_split(const float* __restrict__ src,
                                                  __half* __restrict__ hi,
                                                  __half* __restrict__ lo, int n4) {
    const int i = blockIdx.x * 256 + threadIdx.x;
    if (i < n4) {
        const float4 v = reinterpret_cast<const float4*>(src)[i];
        __half h[4], l[4];
        split_fp16(v.x, h[0], l[0]);
        split_fp16(v.y, h[1], l[1]);
        split_fp16(v.z, h[2], l[2]);
        split_fp16(v.w, h[3], l[3]);
        __half2* oh = reinterpret_cast<__half2*>(hi);
        __half2* ol = reinterpret_cast<__half2*>(lo);
        oh[2 * i + 0] = __halves2half2(h[0], h[1]);
        oh[2 * i + 1] = __halves2half2(h[2], h[3]);
        ol[2 * i + 0] = __halves2half2(l[0], l[1]);
        ol[2 * i + 1] = __halves2half2(l[2], l[3]);
    }
}

// ===================== fp16x2 GEMM via mma.sync (HMMA) =====================
// C[m,n] = bias[n] + sum_k A[m,k]*W[n,k]; A [M,K] fp16, W [N,K] fp16 hi+lo.
// CTA tile 128x128; 8 warps 2(M) x 4(N); warp tile 64x32; 2-stage cp.async;
// stage = [A 16K][Wh 16K][Wl 16K] = 48 KB; 2 CTAs/SM.
__global__ __launch_bounds__(256, 2)
void gemm_mma(const __half* __restrict__ A,
              const __half* __restrict__ Wh, const __half* __restrict__ Wl,
              const float* __restrict__ bias, float* __restrict__ C, const int N) {
    extern __shared__ char smem[];
    const uint32_t sbase = smem_u32(smem);
    const int tid  = threadIdx.x;
    const int wid  = tid >> 5;
    const int lane = tid & 31;
    const int bn = blockIdx.x * 128;
    const int bm = blockIdx.y * 128;

    // ---- loaders: thread t -> row t>>1, half (t&1); 4 cp16 per tile ----
    const int lrow  = tid >> 1;
    const int lhalf = tid & 1;
    const __half* aS  = A  + (size_t)(bm + lrow) * K_DIM + lhalf * 32;
    const __half* wHS = Wh + (size_t)(bn + lrow) * K_DIM + lhalf * 32;
    const __half* wLS = Wl + (size_t)(bn + lrow) * K_DIM + lhalf * 32;
    uint32_t st_off[4];
    #pragma unroll
    for (int v = 0; v < 4; v++) {
        const uint32_t off = (uint32_t)lrow * 128u + (uint32_t)lhalf * 64u + (uint32_t)v * 16u;
        st_off[v] = swz(off);
    }

    auto load_stage = [&](int s, int c) {
        const uint32_t st = sbase + (uint32_t)s * STAGE_BYTES;
        const int kc = c * KC;
        #pragma unroll
        for (int v = 0; v < 4; v++) {
            cp16(st + st_off[v],          aS  + kc + v * 8);
            cp16(st + WH_OFF + st_off[v], wHS + kc + v * 8);
            cp16(st + WL_OFF + st_off[v], wLS + kc + v * 8);
        }
        CP_COMMIT();
    };

    // ---- per-warp ldmatrix addressing (R4-proven geometry) ----
    const int wm = (wid & 1) * 64;
    const int wn = (wid >> 1) * 32;
    uint32_t a_rowoff[4], a_mask[4];
    #pragma unroll
    for (int mi = 0; mi < 4; mi++) {
        const uint32_t r = (uint32_t)(wm + mi * 16 + (lane & 15));
        a_rowoff[mi] = r * 128u;
        a_mask[mi]   = (a_rowoff[mi] >> 3) & 0x70u;
    }
    const uint32_t a_kb = ((uint32_t)lane >> 4) * 16u;
    const int b_lrow = (lane & 7) + ((lane >> 4) << 3);
    uint32_t b_rowoff[2], b_mask[2];
    #pragma unroll
    for (int np = 0; np < 2; np++) {
        const uint32_t r = (uint32_t)(wn + np * 16 + b_lrow);
        b_rowoff[np] = r * 128u;
        b_mask[np]   = (b_rowoff[np] >> 3) & 0x70u;
    }
    const uint32_t b_kb = (((uint32_t)lane >> 3) & 1u) * 16u;

    float acc[4][4][4];
    #pragma unroll
    for (int mi = 0; mi < 4; mi++)
        #pragma unroll
        for (int ni = 0; ni < 4; ni++)
            #pragma unroll
            for (int r = 0; r < 4; r++) acc[mi][ni][r] = 0.0f;

    load_stage(0, 0);
    load_stage(1, 1);

    for (int c = 0; c < NCHUNK; c++) {
        const int s = c & 1;
        const uint32_t st = sbase + (uint32_t)s * STAGE_BYTES;
        if (c < NCHUNK - 1) CP_WAIT1(); else CP_WAIT0();
        __syncthreads();

        #pragma unroll
        for (int ks = 0; ks < 4; ks++) {
            const uint32_t akb = (uint32_t)ks * 32u + a_kb;
            const uint32_t bkb = (uint32_t)ks * 32u + b_kb;
            uint32_t ar[4][4], bh[2][4], bl[2][4];
            #pragma unroll
            for (int mi = 0; mi < 4; mi++)
                LDSM4(ar[mi], st + a_rowoff[mi] + (akb ^ a_mask[mi]));
            #pragma unroll
            for (int np = 0; np < 2; np++) {
                LDSM4(bh[np], st + WH_OFF + b_rowoff[np] + (bkb ^ b_mask[np]));
                LDSM4(bl[np], st + WL_OFF + b_rowoff[np] + (bkb ^ b_mask[np]));
            }
            // term-major: 16 independent MMAs between accumulator reuse
            #pragma unroll
            for (int mi = 0; mi < 4; mi++)
                #pragma unroll
                for (int ni = 0; ni < 4; ni++) {
                    const int np = ni >> 1, po = (ni & 1) * 2;
                    MMA16816H(acc[mi][ni], ar[mi], bh[np][po], bh[np][po + 1]);
                }
            #pragma unroll
            for (int mi = 0; mi < 4; mi++)
                #pragma unroll
                for (int ni = 0; ni < 4; ni++) {
                    const int np = ni >> 1, po = (ni & 1) * 2;
                    MMA16816H(acc[mi][ni], ar[mi], bl[np][po], bl[np][po + 1]);
                }
        }

        __syncthreads();
        if (c + 2 < NCHUNK) load_stage(s, c + 2);
    }

    // ---- epilogue ----
    const int gid = lane >> 2;
    const int tig = lane & 3;
    #pragma unroll
    for (int mi = 0; mi < 4; mi++) {
        const int row0 = bm + wm + mi * 16 + gid;
        float* C0 = C + (size_t)row0 * N;
        float* C1 = C + (size_t)(row0 + 8) * N;
        #pragma unroll
        for (int ni = 0; ni < 4; ni++) {
            const int col = bn + wn + ni * 8 + tig * 2;
            const float b0 = bias[col], b1 = bias[col + 1];
            float2 o0, o1;
            o0.x = acc[mi][ni][0] + b0;
            o0.y = acc[mi][ni][1] + b1;
            o1.x = acc[mi][ni][2] + b0;
            o1.y = acc[mi][ni][3] + b1;
            *reinterpret_cast<float2*>(C0 + col) = o0;
            *reinterpret_cast<float2*>(C1 + col) = o1;
        }
    }
}

// ===================== Windowed causal attention ==========================
// 2 threads per query (each owns 32 of 64 dims); 256 threads = 128 queries.
#define KV_STRIDE 72
#define ATTN_SMEM (2 * 128 * KV_STRIDE * 4)     // 73728 B

__global__ __launch_bounds__(256) void attn_kernel(const float* __restrict__ qkv) {
    extern __shared__ float smemf[];
    float* Ksb = smemf;
    float* Vsb = smemf + 128 * KV_STRIDE;

    const int qt  = blockIdx.x * 128;
    const int h   = blockIdx.y;
    const int b   = blockIdx.z;
    const int tid = threadIdx.x;
    const int ql  = tid >> 1;
    const int half = tid & 1;
    const int i   = qt + ql;
    const int warp = tid >> 5;
    const int wq   = qt + (warp << 4);

    const float* qp = qkv + (size_t)(b * T_DIM + i) * QKV_W + h * D_DIM + half * 32;
    float4 q[8], acc[8];
    #pragma unroll
    for (int d = 0; d < 8; d++) {
        q[d] = reinterpret_cast<const float4*>(qp)[d];
        acc[d] = make_float4(0.f, 0.f, 0.f, 0.f);
    }
    float l = 0.0f;

    for (int cs = qt - WIN; cs < qt + 128; cs += 128) {
        __syncthreads();
        const int j = cs + ql;
        if (j >= 0) {
            const float* kp = qkv + (size_t)(b * T_DIM + j) * QKV_W + E_DIM + h * D_DIM + half * 32;
            float4* kd = reinterpret_cast<float4*>(Ksb + ql * KV_STRIDE + half * 36);
            float4* vd = reinterpret_cast<float4*>(Vsb + ql * KV_STRIDE + half * 36);
            #pragma unroll
            for (int d = 0; d < 8; d++) {
                kd[d] = reinterpret_cast<const float4*>(kp)[d];
                vd[d] = reinterpret_cast<const float4*>(kp + E_DIM)[d];
            }
        }
        __syncthreads();

        int ulo = cs;       if (wq - WIN > ulo) ulo = wq - WIN;  if (ulo < 0) ulo = 0;
        int uhi = cs + 127; if (wq + 15 < uhi) uhi = wq + 15;

        for (int jj = ulo; jj <= uhi; jj++) {
            const float4* kr = reinterpret_cast<const float4*>(
                Ksb + (jj - cs) * KV_STRIDE + half * 36);
            float s0 = 0.f, s1 = 0.f;
            #pragma unroll
            for (int d = 0; d < 8; d += 2) {
                const float4 k0 = kr[d], k1 = kr[d + 1];
                s0 += q[d].x   * k0.x + q[d].y   * k0.y + q[d].z   * k0.z + q[d].w   * k0.w;
                s1 += q[d+1].x * k1.x + q[d+1].y * k1.y + q[d+1].z * k1.z + q[d+1].w * k1.w;
            }
            const float sp = s0 + s1;
            const float s = sp + __shfl_xor_sync(0xffffffffu, sp, 1);
            const bool ok = (jj <= i) && (jj >= i - WIN);
            const float p = ok ? __expf(s * 0.125f) : 0.0f;
            l += p;
            const float4* vr = reinterpret_cast<const float4*>(
                Vsb + (jj - cs) * KV_STRIDE + half * 36);
            #pragma unroll
            for (int d = 0; d < 8; d++) {
                const float4 vv = vr[d];
                acc[d].x = fmaf(p, vv.x, acc[d].x);
                acc[d].y = fmaf(p, vv.y, acc[d].y);
                acc[d].z = fmaf(p, vv.z, acc[d].z);
                acc[d].w = fmaf(p, vv.w, acc[d].w);
            }
        }
    }

    const float rinv = 1.0f / l;
    __half2* oc = reinterpret_cast<__half2*>(
        g_ctx + (size_t)(b * T_DIM + i) * E_DIM + h * D_DIM + half * 32);
    #pragma unroll
    for (int d = 0; d < 8; d++) {
        float2 p0, p1;
        p0.x = acc[d].x * rinv; p0.y = acc[d].y * rinv;
        p1.x = acc[d].z * rinv; p1.y = acc[d].w * rinv;
        oc[2 * d + 0] = __float22half2_rn(p0);
        oc[2 * d + 1] = __float22half2_rn(p1);
    }
}

// ============================== launch ====================================
extern "C" void kernel_launch(void* const* d_in, const int* in_sizes, int n_in,
                              void* d_out, int out_size) {
    const float* x     = (const float*)d_in[0];
    const float* gamma = (const float*)d_in[2];
    const float* beta  = (const float*)d_in[3];
    const float* w_in  = (const float*)d_in[4];
    const float* b_in  = (const float*)d_in[5];
    const float* w_out = (const float*)d_in[6];
    const float* b_out = (const float*)d_in[7];
    float* out = (float*)d_out;

    __half *xn, *ctx, *win_hi, *win_lo, *wout_hi, *wout_lo;
    float* qkv;
    cudaGetSymbolAddress((void**)&xn,      g_xn);
    cudaGetSymbolAddress((void**)&qkv,     g_qkv);
    cudaGetSymbolAddress((void**)&ctx,     g_ctx);
    cudaGetSymbolAddress((void**)&win_hi,  g_win_hi);
    cudaGetSymbolAddress((void**)&win_lo,  g_win_lo);
    cudaGetSymbolAddress((void**)&wout_hi, g_wout_hi);
    cudaGetSymbolAddress((void**)&wout_lo, g_wout_lo);

    cudaFuncSetAttribute(gemm_mma, cudaFuncAttributeMaxDynamicSharedMemorySize, SMEM_GEMM);
    cudaFuncSetAttribute(attn_kernel, cudaFuncAttributeMaxDynamicSharedMemorySize, ATTN_SMEM);

    ln_kernel<<<ROWS, 128>>>(x, gamma, beta);
    conv_split<<<(QKV_W * E_DIM / 4 + 255) / 256, 256>>>(w_in, win_hi, win_lo, QKV_W * E_DIM / 4);
    conv_split<<<(E_DIM * E_DIM / 4 + 255) / 256, 256>>>(w_out, wout_hi, wout_lo, E_DIM * E_DIM / 4);
    gemm_mma<<<dim3(QKV_W / 128, ROWS / 128), 256, SMEM_GEMM>>>(
        xn, win_hi, win_lo, b_in, qkv, QKV_W);
    attn_kernel<<<dim3(T_DIM / 128, H_DIM, B_DIM), 256, ATTN_SMEM>>>(qkv);
    gemm_mma<<<dim3(E_DIM / 128, ROWS / 128), 256, SMEM_GEMM>>>(
        ctx, wout_hi, wout_lo, b_out, out, E_DIM);
}

// round 8
// speedup vs baseline: 2.4528x; 1.5566x over previous
#include <cuda_runtime.h>
#include <cuda_fp16.h>
#include <math.h>
#include <stdint.h>

#define E_DIM 512
#define T_DIM 1024
#define B_DIM 8
#define H_DIM 8
#define D_DIM 64
#define WIN   128
#define ROWS  (B_DIM * T_DIM)   // 8192
#define QKV_W (3 * E_DIM)       // 1536
#define K_DIM 512
#define KC    64
#define NCHUNK (K_DIM / KC)               // 8
#define TILE_BYTES (128 * 128)
#define WH_OFF TILE_BYTES
#define WL_OFF (2 * TILE_BYTES)
#define STAGE_BYTES (3 * TILE_BYTES)      // 48 KB
#define SMEM_GEMM (2 * STAGE_BYTES)       // 96 KB -> 2 CTAs/SM

// -------------------- scratch (__device__ globals) -------------------------
__device__ __half g_xn  [ROWS * E_DIM];
__device__ float  g_qkv [ROWS * QKV_W];
__device__ __half g_ctx [ROWS * E_DIM];
__device__ __half g_win_hi[QKV_W * E_DIM];
__device__ __half g_win_lo[QKV_W * E_DIM];
__device__ __half g_wout_hi[E_DIM * E_DIM];
__device__ __half g_wout_lo[E_DIM * E_DIM];

// ============================ helpers ======================================
__device__ __forceinline__ uint32_t smem_u32(const void* p) {
    uint32_t a;
    asm("{ .reg .u64 t; cvta.to.shared.u64 t, %1; cvt.u32.u64 %0, t; }" : "=r"(a) : "l"(p));
    return a;
}
__device__ __forceinline__ void cp16(uint32_t dst, const void* src) {
    asm volatile("cp.async.cg.shared.global [%0], [%1], 16;" :: "r"(dst), "l"(src));
}
#define CP_COMMIT() asm volatile("cp.async.commit_group;" ::: "memory")
#define CP_WAIT1()  asm volatile("cp.async.wait_group 1;" ::: "memory")
#define CP_WAIT0()  asm volatile("cp.async.wait_group 0;" ::: "memory")

#define LDSM4(R, addr)                                                          \
    asm volatile("ldmatrix.sync.aligned.m8n8.x4.shared.b16 {%0,%1,%2,%3}, [%4];" \
        : "=r"((R)[0]), "=r"((R)[1]), "=r"((R)[2]), "=r"((R)[3]) : "r"(addr))

#define LDSM4T(R, addr)                                                         \
    asm volatile("ldmatrix.sync.aligned.m8n8.x4.trans.shared.b16 {%0,%1,%2,%3}, [%4];" \
        : "=r"((R)[0]), "=r"((R)[1]), "=r"((R)[2]), "=r"((R)[3]) : "r"(addr))

#define MMA16816H(D, A, B0, B1)                                                 \
    asm volatile("mma.sync.aligned.m16n8k16.row.col.f32.f16.f16.f32 "           \
        "{%0,%1,%2,%3},{%4,%5,%6,%7},{%8,%9},{%0,%1,%2,%3};"                    \
        : "+f"((D)[0]), "+f"((D)[1]), "+f"((D)[2]), "+f"((D)[3])                \
        : "r"((A)[0]), "r"((A)[1]), "r"((A)[2]), "r"((A)[3]), "r"(B0), "r"(B1))

__device__ __forceinline__ void split_fp16(float x, __half& h, __half& l) {
    h = __float2half(x);
    l = __float2half(x - __half2float(h));
}
__device__ __forceinline__ uint32_t swz(uint32_t off) {
    return off ^ ((off >> 3) & 0x70u);
}
__device__ __forceinline__ uint32_t h2u(__half2 v) { return *reinterpret_cast<uint32_t*>(&v); }

// ======================= LayerNorm -> fp16 =================================
__global__ __launch_bounds__(128) void ln_kernel(const float* __restrict__ x,
                                                 const float* __restrict__ gamma,
                                                 const float* __restrict__ beta) {
    const int row = blockIdx.x;
    const int tid = threadIdx.x;
    const float4 v = reinterpret_cast<const float4*>(x + (size_t)row * E_DIM)[tid];
    float s  = v.x + v.y + v.z + v.w;
    float ss = v.x * v.x + v.y * v.y + v.z * v.z + v.w * v.w;
    #pragma unroll
    for (int o = 16; o > 0; o >>= 1) {
        s  += __shfl_down_sync(0xffffffffu, s,  o);
        ss += __shfl_down_sync(0xffffffffu, ss, o);
    }
    __shared__ float sh_s[4], sh_ss[4], sh_mu, sh_rstd;
    const int w = tid >> 5, lane = tid & 31;
    if (lane == 0) { sh_s[w] = s; sh_ss[w] = ss; }
    __syncthreads();
    if (tid == 0) {
        float ts  = sh_s[0] + sh_s[1] + sh_s[2] + sh_s[3];
        float tss = sh_ss[0] + sh_ss[1] + sh_ss[2] + sh_ss[3];
        float mu  = ts * (1.0f / E_DIM);
        float var = tss * (1.0f / E_DIM) - mu * mu;
        sh_mu = mu; sh_rstd = rsqrtf(var + 1e-5f);
    }
    __syncthreads();
    const float mu = sh_mu, rstd = sh_rstd;
    const float4 g  = reinterpret_cast<const float4*>(gamma)[tid];
    const float4 be = reinterpret_cast<const float4*>(beta)[tid];
    float2 a, b;
    a.x = (v.x - mu) * rstd * g.x + be.x;
    a.y = (v.y - mu) * rstd * g.y + be.y;
    b.x = (v.z - mu) * rstd * g.z + be.z;
    b.y = (v.w - mu) * rstd * g.w + be.w;
    __half2* o = reinterpret_cast<__half2*>(g_xn + (size_t)row * E_DIM);
    o[2 * tid + 0] = __float22half2_rn(a);
    o[2 * tid + 1] = __float22half2_rn(b);
}

// ===================== weight fp32 -> fp16 hi/lo ===========================
__global__ __launch_bounds__(256) void conv_split(const float* __restrict__ src,
                                                  __half* __restrict__ hi,
                                                  __half* __restrict__ lo, int n4) {
    const int i = blockIdx.x * 256 + threadIdx.x;
    if (i < n4) {
        const float4 v = reinterpret_cast<const float4*>(src)[i];
        __half h[4], l[4];
        split_fp16(v.x, h[0], l[0]);
        split_fp16(v.y, h[1], l[1]);
        split_fp16(v.z, h[2], l[2]);
        split_fp16(v.w, h[3], l[3]);
        __half2* oh = reinterpret_cast<__half2*>(hi);
        __half2* ol = reinterpret_cast<__half2*>(lo);
        oh[2 * i + 0] = __halves2half2(h[0], h[1]);
        oh[2 * i + 1] = __halves2half2(h[2], h[3]);
        ol[2 * i + 0] = __halves2half2(l[0], l[1]);
        ol[2 * i + 1] = __halves2half2(l[2], l[3]);
    }
}

// ===================== fp16x2 GEMM via mma.sync (unchanged R7) =============
__global__ __launch_bounds__(256, 2)
void gemm_mma(const __half* __restrict__ A,
              const __half* __restrict__ Wh, const __half* __restrict__ Wl,
              const float* __restrict__ bias, float* __restrict__ C, const int N) {
    extern __shared__ char smem[];
    const uint32_t sbase = smem_u32(smem);
    const int tid  = threadIdx.x;
    const int wid  = tid >> 5;
    const int lane = tid & 31;
    const int bn = blockIdx.x * 128;
    const int bm = blockIdx.y * 128;

    const int lrow  = tid >> 1;
    const int lhalf = tid & 1;
    const __half* aS  = A  + (size_t)(bm + lrow) * K_DIM + lhalf * 32;
    const __half* wHS = Wh + (size_t)(bn + lrow) * K_DIM + lhalf * 32;
    const __half* wLS = Wl + (size_t)(bn + lrow) * K_DIM + lhalf * 32;
    uint32_t st_off[4];
    #pragma unroll
    for (int v = 0; v < 4; v++) {
        const uint32_t off = (uint32_t)lrow * 128u + (uint32_t)lhalf * 64u + (uint32_t)v * 16u;
        st_off[v] = swz(off);
    }

    auto load_stage = [&](int s, int c) {
        const uint32_t st = sbase + (uint32_t)s * STAGE_BYTES;
        const int kc = c * KC;
        #pragma unroll
        for (int v = 0; v < 4; v++) {
            cp16(st + st_off[v],          aS  + kc + v * 8);
            cp16(st + WH_OFF + st_off[v], wHS + kc + v * 8);
            cp16(st + WL_OFF + st_off[v], wLS + kc + v * 8);
        }
        CP_COMMIT();
    };

    const int wm = (wid & 1) * 64;
    const int wn = (wid >> 1) * 32;
    uint32_t a_rowoff[4], a_mask[4];
    #pragma unroll
    for (int mi = 0; mi < 4; mi++) {
        const uint32_t r = (uint32_t)(wm + mi * 16 + (lane & 15));
        a_rowoff[mi] = r * 128u;
        a_mask[mi]   = (a_rowoff[mi] >> 3) & 0x70u;
    }
    const uint32_t a_kb = ((uint32_t)lane >> 4) * 16u;
    const int b_lrow = (lane & 7) + ((lane >> 4) << 3);
    uint32_t b_rowoff[2], b_mask[2];
    #pragma unroll
    for (int np = 0; np < 2; np++) {
        const uint32_t r = (uint32_t)(wn + np * 16 + b_lrow);
        b_rowoff[np] = r * 128u;
        b_mask[np]   = (b_rowoff[np] >> 3) & 0x70u;
    }
    const uint32_t b_kb = (((uint32_t)lane >> 3) & 1u) * 16u;

    float acc[4][4][4];
    #pragma unroll
    for (int mi = 0; mi < 4; mi++)
        #pragma unroll
        for (int ni = 0; ni < 4; ni++)
            #pragma unroll
            for (int r = 0; r < 4; r++) acc[mi][ni][r] = 0.0f;

    load_stage(0, 0);
    load_stage(1, 1);

    for (int c = 0; c < NCHUNK; c++) {
        const int s = c & 1;
        const uint32_t st = sbase + (uint32_t)s * STAGE_BYTES;
        if (c < NCHUNK - 1) CP_WAIT1(); else CP_WAIT0();
        __syncthreads();

        #pragma unroll
        for (int ks = 0; ks < 4; ks++) {
            const uint32_t akb = (uint32_t)ks * 32u + a_kb;
            const uint32_t bkb = (uint32_t)ks * 32u + b_kb;
            uint32_t ar[4][4], bh[2][4], bl[2][4];
            #pragma unroll
            for (int mi = 0; mi < 4; mi++)
                LDSM4(ar[mi], st + a_rowoff[mi] + (akb ^ a_mask[mi]));
            #pragma unroll
            for (int np = 0; np < 2; np++) {
                LDSM4(bh[np], st + WH_OFF + b_rowoff[np] + (bkb ^ b_mask[np]));
                LDSM4(bl[np], st + WL_OFF + b_rowoff[np] + (bkb ^ b_mask[np]));
            }
            #pragma unroll
            for (int mi = 0; mi < 4; mi++)
                #pragma unroll
                for (int ni = 0; ni < 4; ni++) {
                    const int np = ni >> 1, po = (ni & 1) * 2;
                    MMA16816H(acc[mi][ni], ar[mi], bh[np][po], bh[np][po + 1]);
                }
            #pragma unroll
            for (int mi = 0; mi < 4; mi++)
                #pragma unroll
                for (int ni = 0; ni < 4; ni++) {
                    const int np = ni >> 1, po = (ni & 1) * 2;
                    MMA16816H(acc[mi][ni], ar[mi], bl[np][po], bl[np][po + 1]);
                }
        }

        __syncthreads();
        if (c + 2 < NCHUNK) load_stage(s, c + 2);
    }

    const int gid = lane >> 2;
    const int tig = lane & 3;
    #pragma unroll
    for (int mi = 0; mi < 4; mi++) {
        const int row0 = bm + wm + mi * 16 + gid;
        float* C0 = C + (size_t)row0 * N;
        float* C1 = C + (size_t)(row0 + 8) * N;
        #pragma unroll
        for (int ni = 0; ni < 4; ni++) {
            const int col = bn + wn + ni * 8 + tig * 2;
            const float b0 = bias[col], b1 = bias[col + 1];
            float2 o0, o1;
            o0.x = acc[mi][ni][0] + b0;
            o0.y = acc[mi][ni][1] + b1;
            o1.x = acc[mi][ni][2] + b0;
            o1.y = acc[mi][ni][3] + b1;
            *reinterpret_cast<float2*>(C0 + col) = o0;
            *reinterpret_cast<float2*>(C1 + col) = o1;
        }
    }
}

// ================ Tensor-core windowed causal attention ====================
// CTA = (b, h, 128 queries); 8 warps x 16 queries. Warp keys: [wq-128, wq+16)
// = 144, processed as 3 chunks of 48. Q(x0.125)/K/V fp16 in swizzled smem
// (Q 16K, K 32K, V 32K = 80 KB). S = Q.K^T (mma), mask+expf in fp32, P packed
// from S accums (FA2 layout identity), O += P.V via ldmatrix.trans.
#define ATTN_SMEM (16384 + 32768 + 32768)

__global__ __launch_bounds__(256) void attn_mma(const float* __restrict__ qkv) {
    extern __shared__ char sm[];
    const uint32_t sbase = smem_u32(sm);
    const uint32_t Qb = sbase, Kb = sbase + 16384u, Vb = sbase + 49152u;
    char* Qp = sm; char* Kp = sm + 16384; char* Vp = sm + 49152;
    const int qt  = blockIdx.x * 128;
    const int h   = blockIdx.y;
    const int b   = blockIdx.z;
    const int tid = threadIdx.x;
    const int wid = tid >> 5;
    const int lane = tid & 31;

    // ---- load Q (scaled by 1/8, exact) ----
    if (tid < 128) {
        const int row = tid;
        const float4* src = reinterpret_cast<const float4*>(
            qkv + (size_t)(b * T_DIM + qt + row) * QKV_W + h * D_DIM);
        const uint32_t rmask = (uint32_t)(row & 7) * 16u;
        #pragma unroll
        for (int c = 0; c < 8; c++) {
            const float4 f0 = src[2 * c], f1 = src[2 * c + 1];
            uint4 pk;
            pk.x = h2u(__floats2half2_rn(f0.x * 0.125f, f0.y * 0.125f));
            pk.y = h2u(__floats2half2_rn(f0.z * 0.125f, f0.w * 0.125f));
            pk.z = h2u(__floats2half2_rn(f1.x * 0.125f, f1.y * 0.125f));
            pk.w = h2u(__floats2half2_rn(f1.z * 0.125f, f1.w * 0.125f));
            *reinterpret_cast<uint4*>(Qp + row * 128 + (int)((c * 16u) ^ rmask)) = pk;
        }
    }
    // ---- load K,V rows (256 rows: j = qt-128+row; zero-fill j<0) ----
    {
        const int row = tid;
        const int j = qt - 128 + row;
        const uint32_t rmask = (uint32_t)(row & 7) * 16u;
        if (j >= 0) {
            const float4* ks = reinterpret_cast<const float4*>(
                qkv + (size_t)(b * T_DIM + j) * QKV_W + E_DIM + h * D_DIM);
            const float4* vs = reinterpret_cast<const float4*>(
                qkv + (size_t)(b * T_DIM + j) * QKV_W + 2 * E_DIM + h * D_DIM);
            #pragma unroll
            for (int c = 0; c < 8; c++) {
                const float4 k0 = ks[2 * c], k1 = ks[2 * c + 1];
                const float4 v0 = vs[2 * c], v1 = vs[2 * c + 1];
                uint4 pk, pv;
                pk.x = h2u(__floats2half2_rn(k0.x, k0.y));
                pk.y = h2u(__floats2half2_rn(k0.z, k0.w));
                pk.z = h2u(__floats2half2_rn(k1.x, k1.y));
                pk.w = h2u(__floats2half2_rn(k1.z, k1.w));
                pv.x = h2u(__floats2half2_rn(v0.x, v0.y));
                pv.y = h2u(__floats2half2_rn(v0.z, v0.w));
                pv.z = h2u(__floats2half2_rn(v1.x, v1.y));
                pv.w = h2u(__floats2half2_rn(v1.z, v1.w));
                const int so = row * 128 + (int)((c * 16u) ^ rmask);
                *reinterpret_cast<uint4*>(Kp + so) = pk;
                *reinterpret_cast<uint4*>(Vp + so) = pv;
            }
        } else {
            const uint4 z = make_uint4(0, 0, 0, 0);
            #pragma unroll
            for (int c = 0; c < 8; c++) {
                const int so = row * 128 + (int)((c * 16u) ^ rmask);
                *reinterpret_cast<uint4*>(Kp + so) = z;
                *reinterpret_cast<uint4*>(Vp + so) = z;
            }
        }
    }
    __syncthreads();

    // ---- Q fragments (persistent) ----
    uint32_t qf[4][4];
    {
        const uint32_t arow = (uint32_t)(wid * 16 + (lane & 15));
        const uint32_t amask = (arow & 7u) * 16u;
        const uint32_t acol = ((uint32_t)lane >> 4) * 16u;
        #pragma unroll
        for (int ki = 0; ki < 4; ki++)
            LDSM4(qf[ki], Qb + arow * 128u + (((uint32_t)ki * 32u + acol) ^ amask));
    }

    float o[8][4];
    #pragma unroll
    for (int u = 0; u < 8; u++)
        #pragma unroll
        for (int r = 0; r < 4; r++) o[u][r] = 0.0f;
    float l0 = 0.0f, l1 = 0.0f;
    const int i0 = qt + wid * 16 + (lane >> 2);
    const int i1 = i0 + 8;
    const int tq = lane & 3;
    const int wr0 = wid * 16;

    const uint32_t krow_l = (uint32_t)((lane & 7) + ((lane >> 4) << 3));
    const uint32_t kcol_l = (((uint32_t)lane >> 3) & 1u) * 16u;
    const uint32_t vrow_l = (uint32_t)((lane & 7) + (((lane >> 3) & 1) << 3));
    const uint32_t vcol_l = ((uint32_t)lane >> 4) * 16u;

    #pragma unroll
    for (int c = 0; c < 3; c++) {
        const int rk0 = wr0 + 48 * c;
        const int j0 = qt - 128 + rk0;

        float st[6][4];
        #pragma unroll
        for (int u = 0; u < 6; u++)
            #pragma unroll
            for (int r = 0; r < 4; r++) st[u][r] = 0.0f;

        // S = Q.K^T over 48 keys
        #pragma unroll
        for (int ki = 0; ki < 4; ki++) {
            uint32_t kf[3][4];
            #pragma unroll
            for (int g2 = 0; g2 < 3; g2++) {
                const uint32_t row = (uint32_t)rk0 + (uint32_t)g2 * 16u + krow_l;
                LDSM4(kf[g2], Kb + row * 128u + (((uint32_t)ki * 32u + kcol_l) ^ ((row & 7u) * 16u)));
            }
            #pragma unroll
            for (int u = 0; u < 6; u++)
                MMA16816H(st[u], qf[ki], kf[u >> 1][(u & 1) * 2], kf[u >> 1][(u & 1) * 2 + 1]);
        }

        // mask + exp + pack P
        uint32_t pf[6][2];
        #pragma unroll
        for (int u = 0; u < 6; u++) {
            const int j = j0 + 8 * u + 2 * tq;
            const bool k0a = (j     <= i0) && (j     >= i0 - WIN) && (j     >= 0);
            const bool k0b = (j + 1 <= i0) && (j + 1 >= i0 - WIN) && (j + 1 >= 0);
            const bool k1a = (j     <= i1) && (j     >= i1 - WIN) && (j     >= 0);
            const bool k1b = (j + 1 <= i1) && (j + 1 >= i1 - WIN) && (j + 1 >= 0);
            const float p0 = k0a ? __expf(st[u][0]) : 0.0f;
            const float p1 = k0b ? __expf(st[u][1]) : 0.0f;
            const float p2 = k1a ? __expf(st[u][2]) : 0.0f;
            const float p3 = k1b ? __expf(st[u][3]) : 0.0f;
            l0 += p0 + p1;
            l1 += p2 + p3;
            pf[u][0] = h2u(__floats2half2_rn(p0, p1));
            pf[u][1] = h2u(__floats2half2_rn(p2, p3));
        }

        // O += P.V
        #pragma unroll
        for (int kk = 0; kk < 3; kk++) {
            uint32_t af[4] = {pf[2 * kk][0], pf[2 * kk][1], pf[2 * kk + 1][0], pf[2 * kk + 1][1]};
            const uint32_t row = (uint32_t)rk0 + (uint32_t)kk * 16u + vrow_l;
            const uint32_t rm = (row & 7u) * 16u;
            #pragma unroll
            for (int g2 = 0; g2 < 4; g2++) {
                uint32_t vf[4];
                LDSM4T(vf, Vb + row * 128u + (((uint32_t)g2 * 32u + vcol_l) ^ rm));
                MMA16816H(o[2 * g2],     af, vf[0], vf[1]);
                MMA16816H(o[2 * g2 + 1], af, vf[2], vf[3]);
            }
        }
    }

    // normalize + store fp16 ctx
    l0 += __shfl_xor_sync(0xffffffffu, l0, 1);
    l0 += __shfl_xor_sync(0xffffffffu, l0, 2);
    l1 += __shfl_xor_sync(0xffffffffu, l1, 1);
    l1 += __shfl_xor_sync(0xffffffffu, l1, 2);
    const float r0 = 1.0f / l0, r1 = 1.0f / l1;
    __half2* d0 = reinterpret_cast<__half2*>(
        g_ctx + (size_t)(b * T_DIM + i0) * E_DIM + h * D_DIM);
    __half2* d1 = reinterpret_cast<__half2*>(
        g_ctx + (size_t)(b * T_DIM + i1) * E_DIM + h * D_DIM);
    #pragma unroll
    for (int u = 0; u < 8; u++) {
        d0[4 * u + tq] = __floats2half2_rn(o[u][0] * r0, o[u][1] * r0);
        d1[4 * u + tq] = __floats2half2_rn(o[u][2] * r1, o[u][3] * r1);
    }
}

// ============================== launch ====================================
extern "C" void kernel_launch(void* const* d_in, const int* in_sizes, int n_in,
                              void* d_out, int out_size) {
    const float* x     = (const float*)d_in[0];
    const float* gamma = (const float*)d_in[2];
    const float* beta  = (const float*)d_in[3];
    const float* w_in  = (const float*)d_in[4];
    const float* b_in  = (const float*)d_in[5];
    const float* w_out = (const float*)d_in[6];
    const float* b_out = (const float*)d_in[7];
    float* out = (float*)d_out;

    __half *xn, *ctx, *win_hi, *win_lo, *wout_hi, *wout_lo;
    float* qkv;
    cudaGetSymbolAddress((void**)&xn,      g_xn);
    cudaGetSymbolAddress((void**)&qkv,     g_qkv);
    cudaGetSymbolAddress((void**)&ctx,     g_ctx);
    cudaGetSymbolAddress((void**)&win_hi,  g_win_hi);
    cudaGetSymbolAddress((void**)&win_lo,  g_win_lo);
    cudaGetSymbolAddress((void**)&wout_hi, g_wout_hi);
    cudaGetSymbolAddress((void**)&wout_lo, g_wout_lo);

    cudaFuncSetAttribute(gemm_mma, cudaFuncAttributeMaxDynamicSharedMemorySize, SMEM_GEMM);
    cudaFuncSetAttribute(attn_mma, cudaFuncAttributeMaxDynamicSharedMemorySize, ATTN_SMEM);

    ln_kernel<<<ROWS, 128>>>(x, gamma, beta);
    conv_split<<<(QKV_W * E_DIM / 4 + 255) / 256, 256>>>(w_in, win_hi, win_lo, QKV_W * E_DIM / 4);
    conv_split<<<(E_DIM * E_DIM / 4 + 255) / 256, 256>>>(w_out, wout_hi, wout_lo, E_DIM * E_DIM / 4);
    gemm_mma<<<dim3(QKV_W / 128, ROWS / 128), 256, SMEM_GEMM>>>(
        xn, win_hi, win_lo, b_in, qkv, QKV_W);
    attn_mma<<<dim3(T_DIM / 128, H_DIM, B_DIM), 256, ATTN_SMEM>>>(qkv);
    gemm_mma<<<dim3(E_DIM / 128, ROWS / 128), 256, SMEM_GEMM>>>(
        ctx, wout_hi, wout_lo, b_out, out, E_DIM);
}

// round 9
// speedup vs baseline: 2.6992x; 1.1005x over previous
#include <cuda_runtime.h>
#include <cuda_fp16.h>
#include <math.h>
#include <stdint.h>

#define E_DIM 512
#define T_DIM 1024
#define B_DIM 8
#define H_DIM 8
#define D_DIM 64
#define WIN   128
#define ROWS  (B_DIM * T_DIM)   // 8192
#define QKV_W (3 * E_DIM)       // 1536
#define K_DIM 512
#define KC    64
#define NCHUNK (K_DIM / KC)               // 8
#define TILE_BYTES (128 * 128)
#define WH_OFF TILE_BYTES
#define WL_OFF (2 * TILE_BYTES)
#define STAGE_BYTES (3 * TILE_BYTES)      // 48 KB
#define SMEM_GEMM (2 * STAGE_BYTES)       // 96 KB -> 2 CTAs/SM

// -------------------- scratch (__device__ globals) -------------------------
__device__ __half g_xn  [ROWS * E_DIM];
__device__ __half g_qkv [ROWS * QKV_W];          // fp16 now (25 MB, L2-resident)
__device__ __half g_ctx [ROWS * E_DIM];
__device__ __half g_win_hi[QKV_W * E_DIM];
__device__ __half g_win_lo[QKV_W * E_DIM];
__device__ __half g_wout_hi[E_DIM * E_DIM];
__device__ __half g_wout_lo[E_DIM * E_DIM];

// ============================ helpers ======================================
__device__ __forceinline__ uint32_t smem_u32(const void* p) {
    uint32_t a;
    asm("{ .reg .u64 t; cvta.to.shared.u64 t, %1; cvt.u32.u64 %0, t; }" : "=r"(a) : "l"(p));
    return a;
}
__device__ __forceinline__ void cp16(uint32_t dst, const void* src) {
    asm volatile("cp.async.cg.shared.global [%0], [%1], 16;" :: "r"(dst), "l"(src));
}
#define CP_COMMIT() asm volatile("cp.async.commit_group;" ::: "memory")
#define CP_WAIT1()  asm volatile("cp.async.wait_group 1;" ::: "memory")
#define CP_WAIT0()  asm volatile("cp.async.wait_group 0;" ::: "memory")

#define LDSM4(R, addr)                                                          \
    asm volatile("ldmatrix.sync.aligned.m8n8.x4.shared.b16 {%0,%1,%2,%3}, [%4];" \
        : "=r"((R)[0]), "=r"((R)[1]), "=r"((R)[2]), "=r"((R)[3]) : "r"(addr))

#define LDSM4T(R, addr)                                                         \
    asm volatile("ldmatrix.sync.aligned.m8n8.x4.trans.shared.b16 {%0,%1,%2,%3}, [%4];" \
        : "=r"((R)[0]), "=r"((R)[1]), "=r"((R)[2]), "=r"((R)[3]) : "r"(addr))

#define MMA16816H(D, A, B0, B1)                                                 \
    asm volatile("mma.sync.aligned.m16n8k16.row.col.f32.f16.f16.f32 "           \
        "{%0,%1,%2,%3},{%4,%5,%6,%7},{%8,%9},{%0,%1,%2,%3};"                    \
        : "+f"((D)[0]), "+f"((D)[1]), "+f"((D)[2]), "+f"((D)[3])                \
        : "r"((A)[0]), "r"((A)[1]), "r"((A)[2]), "r"((A)[3]), "r"(B0), "r"(B1))

__device__ __forceinline__ void split_fp16(float x, __half& h, __half& l) {
    h = __float2half(x);
    l = __float2half(x - __half2float(h));
}
__device__ __forceinline__ uint32_t swz(uint32_t off) {
    return off ^ ((off >> 3) & 0x70u);
}
__device__ __forceinline__ uint32_t h2u(__half2 v) { return *reinterpret_cast<uint32_t*>(&v); }

__device__ __forceinline__ void st_pair(float* p, float a, float b) {
    *reinterpret_cast<float2*>(p) = make_float2(a, b);
}
__device__ __forceinline__ void st_pair(__half* p, float a, float b) {
    *reinterpret_cast<__half2*>(p) = __floats2half2_rn(a, b);
}

// ======================= LayerNorm -> fp16 =================================
__global__ __launch_bounds__(128) void ln_kernel(const float* __restrict__ x,
                                                 const float* __restrict__ gamma,
                                                 const float* __restrict__ beta) {
    const int row = blockIdx.x;
    const int tid = threadIdx.x;
    const float4 v = reinterpret_cast<const float4*>(x + (size_t)row * E_DIM)[tid];
    float s  = v.x + v.y + v.z + v.w;
    float ss = v.x * v.x + v.y * v.y + v.z * v.z + v.w * v.w;
    #pragma unroll
    for (int o = 16; o > 0; o >>= 1) {
        s  += __shfl_down_sync(0xffffffffu, s,  o);
        ss += __shfl_down_sync(0xffffffffu, ss, o);
    }
    __shared__ float sh_s[4], sh_ss[4], sh_mu, sh_rstd;
    const int w = tid >> 5, lane = tid & 31;
    if (lane == 0) { sh_s[w] = s; sh_ss[w] = ss; }
    __syncthreads();
    if (tid == 0) {
        float ts  = sh_s[0] + sh_s[1] + sh_s[2] + sh_s[3];
        float tss = sh_ss[0] + sh_ss[1] + sh_ss[2] + sh_ss[3];
        float mu  = ts * (1.0f / E_DIM);
        float var = tss * (1.0f / E_DIM) - mu * mu;
        sh_mu = mu; sh_rstd = rsqrtf(var + 1e-5f);
    }
    __syncthreads();
    const float mu = sh_mu, rstd = sh_rstd;
    const float4 g  = reinterpret_cast<const float4*>(gamma)[tid];
    const float4 be = reinterpret_cast<const float4*>(beta)[tid];
    float2 a, b;
    a.x = (v.x - mu) * rstd * g.x + be.x;
    a.y = (v.y - mu) * rstd * g.y + be.y;
    b.x = (v.z - mu) * rstd * g.z + be.z;
    b.y = (v.w - mu) * rstd * g.w + be.w;
    __half2* o = reinterpret_cast<__half2*>(g_xn + (size_t)row * E_DIM);
    o[2 * tid + 0] = __float22half2_rn(a);
    o[2 * tid + 1] = __float22half2_rn(b);
}

// ===================== weight fp32 -> fp16 hi/lo ===========================
__global__ __launch_bounds__(256) void conv_split(const float* __restrict__ src,
                                                  __half* __restrict__ hi,
                                                  __half* __restrict__ lo, int n4) {
    const int i = blockIdx.x * 256 + threadIdx.x;
    if (i < n4) {
        const float4 v = reinterpret_cast<const float4*>(src)[i];
        __half h[4], l[4];
        split_fp16(v.x, h[0], l[0]);
        split_fp16(v.y, h[1], l[1]);
        split_fp16(v.z, h[2], l[2]);
        split_fp16(v.w, h[3], l[3]);
        __half2* oh = reinterpret_cast<__half2*>(hi);
        __half2* ol = reinterpret_cast<__half2*>(lo);
        oh[2 * i + 0] = __halves2half2(h[0], h[1]);
        oh[2 * i + 1] = __halves2half2(h[2], h[3]);
        ol[2 * i + 0] = __halves2half2(l[0], l[1]);
        ol[2 * i + 1] = __halves2half2(l[2], l[3]);
    }
}

// ===================== fp16x2 GEMM via mma.sync (R7 structure) =============
template <typename OT>
__global__ __launch_bounds__(256, 2)
void gemm_mma(const __half* __restrict__ A,
              const __half* __restrict__ Wh, const __half* __restrict__ Wl,
              const float* __restrict__ bias, OT* __restrict__ C, const int N) {
    extern __shared__ char smem[];
    const uint32_t sbase = smem_u32(smem);
    const int tid  = threadIdx.x;
    const int wid  = tid >> 5;
    const int lane = tid & 31;
    const int bn = blockIdx.x * 128;
    const int bm = blockIdx.y * 128;

    const int lrow  = tid >> 1;
    const int lhalf = tid & 1;
    const __half* aS  = A  + (size_t)(bm + lrow) * K_DIM + lhalf * 32;
    const __half* wHS = Wh + (size_t)(bn + lrow) * K_DIM + lhalf * 32;
    const __half* wLS = Wl + (size_t)(bn + lrow) * K_DIM + lhalf * 32;
    uint32_t st_off[4];
    #pragma unroll
    for (int v = 0; v < 4; v++) {
        const uint32_t off = (uint32_t)lrow * 128u + (uint32_t)lhalf * 64u + (uint32_t)v * 16u;
        st_off[v] = swz(off);
    }

    auto load_stage = [&](int s, int c) {
        const uint32_t st = sbase + (uint32_t)s * STAGE_BYTES;
        const int kc = c * KC;
        #pragma unroll
        for (int v = 0; v < 4; v++) {
            cp16(st + st_off[v],          aS  + kc + v * 8);
            cp16(st + WH_OFF + st_off[v], wHS + kc + v * 8);
            cp16(st + WL_OFF + st_off[v], wLS + kc + v * 8);
        }
        CP_COMMIT();
    };

    const int wm = (wid & 1) * 64;
    const int wn = (wid >> 1) * 32;
    uint32_t a_rowoff[4], a_mask[4];
    #pragma unroll
    for (int mi = 0; mi < 4; mi++) {
        const uint32_t r = (uint32_t)(wm + mi * 16 + (lane & 15));
        a_rowoff[mi] = r * 128u;
        a_mask[mi]   = (a_rowoff[mi] >> 3) & 0x70u;
    }
    const uint32_t a_kb = ((uint32_t)lane >> 4) * 16u;
    const int b_lrow = (lane & 7) + ((lane >> 4) << 3);
    uint32_t b_rowoff[2], b_mask[2];
    #pragma unroll
    for (int np = 0; np < 2; np++) {
        const uint32_t r = (uint32_t)(wn + np * 16 + b_lrow);
        b_rowoff[np] = r * 128u;
        b_mask[np]   = (b_rowoff[np] >> 3) & 0x70u;
    }
    const uint32_t b_kb = (((uint32_t)lane >> 3) & 1u) * 16u;

    float acc[4][4][4];
    #pragma unroll
    for (int mi = 0; mi < 4; mi++)
        #pragma unroll
        for (int ni = 0; ni < 4; ni++)
            #pragma unroll
            for (int r = 0; r < 4; r++) acc[mi][ni][r] = 0.0f;

    load_stage(0, 0);
    load_stage(1, 1);

    for (int c = 0; c < NCHUNK; c++) {
        const int s = c & 1;
        const uint32_t st = sbase + (uint32_t)s * STAGE_BYTES;
        if (c < NCHUNK - 1) CP_WAIT1(); else CP_WAIT0();
        __syncthreads();

        #pragma unroll
        for (int ks = 0; ks < 4; ks++) {
            const uint32_t akb = (uint32_t)ks * 32u + a_kb;
            const uint32_t bkb = (uint32_t)ks * 32u + b_kb;
            uint32_t ar[4][4], bh[2][4], bl[2][4];
            #pragma unroll
            for (int mi = 0; mi < 4; mi++)
                LDSM4(ar[mi], st + a_rowoff[mi] + (akb ^ a_mask[mi]));
            #pragma unroll
            for (int np = 0; np < 2; np++) {
                LDSM4(bh[np], st + WH_OFF + b_rowoff[np] + (bkb ^ b_mask[np]));
                LDSM4(bl[np], st + WL_OFF + b_rowoff[np] + (bkb ^ b_mask[np]));
            }
            #pragma unroll
            for (int mi = 0; mi < 4; mi++)
                #pragma unroll
                for (int ni = 0; ni < 4; ni++) {
                    const int np = ni >> 1, po = (ni & 1) * 2;
                    MMA16816H(acc[mi][ni], ar[mi], bh[np][po], bh[np][po + 1]);
                }
            #pragma unroll
            for (int mi = 0; mi < 4; mi++)
                #pragma unroll
                for (int ni = 0; ni < 4; ni++) {
                    const int np = ni >> 1, po = (ni & 1) * 2;
                    MMA16816H(acc[mi][ni], ar[mi], bl[np][po], bl[np][po + 1]);
                }
        }

        __syncthreads();
        if (c + 2 < NCHUNK) load_stage(s, c + 2);
    }

    const int gid = lane >> 2;
    const int tig = lane & 3;
    #pragma unroll
    for (int mi = 0; mi < 4; mi++) {
        const int row0 = bm + wm + mi * 16 + gid;
        OT* C0 = C + (size_t)row0 * N;
        OT* C1 = C + (size_t)(row0 + 8) * N;
        #pragma unroll
        for (int ni = 0; ni < 4; ni++) {
            const int col = bn + wn + ni * 8 + tig * 2;
            const float b0 = bias[col], b1 = bias[col + 1];
            st_pair(C0 + col, acc[mi][ni][0] + b0, acc[mi][ni][1] + b1);
            st_pair(C1 + col, acc[mi][ni][2] + b0, acc[mi][ni][3] + b1);
        }
    }
}

// ================ Tensor-core windowed causal attention ====================
// CTA = (b, h, 128 queries); 8 warps x 16 queries; warp keys [wq-128, wq+16)
// in 3 chunks of 48. qkv is fp16 -> Q/K/V land in swizzled smem via pure
// cp.async (no conversion). Scores scaled by 0.125 in fp32 before expf.
#define ATTN_SMEM (16384 + 32768 + 32768)

__global__ __launch_bounds__(256) void attn_mma(const __half* __restrict__ qkv) {
    extern __shared__ char sm[];
    const uint32_t sbase = smem_u32(sm);
    const uint32_t Qb = sbase, Kb = sbase + 16384u, Vb = sbase + 49152u;
    char* Kp = sm + 16384; char* Vp = sm + 49152;
    const int qt  = blockIdx.x * 128;
    const int h   = blockIdx.y;
    const int b   = blockIdx.z;
    const int tid = threadIdx.x;
    const int wid = tid >> 5;
    const int lane = tid & 31;

    // ---- Q rows (threads 0..127): 8 cp16 each ----
    if (tid < 128) {
        const __half* src = qkv + (size_t)(b * T_DIM + qt + tid) * QKV_W + h * D_DIM;
        const uint32_t rmask = (uint32_t)(tid & 7) * 16u;
        #pragma unroll
        for (int c = 0; c < 8; c++)
            cp16(Qb + (uint32_t)tid * 128u + (((uint32_t)c * 16u) ^ rmask), src + c * 8);
    }
    // ---- K,V rows (all 256 threads): j = qt-128+tid ----
    {
        const int j = qt - 128 + tid;
        const uint32_t rmask = (uint32_t)(tid & 7) * 16u;
        if (j >= 0) {
            const __half* ks = qkv + (size_t)(b * T_DIM + j) * QKV_W + E_DIM + h * D_DIM;
            const __half* vs = ks + E_DIM;
            #pragma unroll
            for (int c = 0; c < 8; c++) {
                const uint32_t so = (uint32_t)tid * 128u + (((uint32_t)c * 16u) ^ rmask);
                cp16(Kb + so, ks + c * 8);
                cp16(Vb + so, vs + c * 8);
            }
        } else {
            const uint4 z = make_uint4(0, 0, 0, 0);
            #pragma unroll
            for (int c = 0; c < 8; c++) {
                const uint32_t so = (uint32_t)tid * 128u + (((uint32_t)c * 16u) ^ rmask);
                *reinterpret_cast<uint4*>(Kp + so) = z;
                *reinterpret_cast<uint4*>(Vp + so) = z;
            }
        }
    }
    CP_COMMIT();
    CP_WAIT0();
    __syncthreads();

    // ---- Q fragments (persistent) ----
    uint32_t qf[4][4];
    {
        const uint32_t arow = (uint32_t)(wid * 16 + (lane & 15));
        const uint32_t amask = (arow & 7u) * 16u;
        const uint32_t acol = ((uint32_t)lane >> 4) * 16u;
        #pragma unroll
        for (int ki = 0; ki < 4; ki++)
            LDSM4(qf[ki], Qb + arow * 128u + (((uint32_t)ki * 32u + acol) ^ amask));
    }

    float o[8][4];
    #pragma unroll
    for (int u = 0; u < 8; u++)
        #pragma unroll
        for (int r = 0; r < 4; r++) o[u][r] = 0.0f;
    float l0 = 0.0f, l1 = 0.0f;
    const int i0 = qt + wid * 16 + (lane >> 2);
    const int i1 = i0 + 8;
    const int tq = lane & 3;
    const int wr0 = wid * 16;

    const uint32_t krow_l = (uint32_t)((lane & 7) + ((lane >> 4) << 3));
    const uint32_t kcol_l = (((uint32_t)lane >> 3) & 1u) * 16u;
    const uint32_t vrow_l = (uint32_t)((lane & 7) + (((lane >> 3) & 1) << 3));
    const uint32_t vcol_l = ((uint32_t)lane >> 4) * 16u;

    #pragma unroll
    for (int c = 0; c < 3; c++) {
        const int rk0 = wr0 + 48 * c;
        const int j0 = qt - 128 + rk0;

        float st[6][4];
        #pragma unroll
        for (int u = 0; u < 6; u++)
            #pragma unroll
            for (int r = 0; r < 4; r++) st[u][r] = 0.0f;

        #pragma unroll
        for (int ki = 0; ki < 4; ki++) {
            uint32_t kf[3][4];
            #pragma unroll
            for (int g2 = 0; g2 < 3; g2++) {
                const uint32_t row = (uint32_t)rk0 + (uint32_t)g2 * 16u + krow_l;
                LDSM4(kf[g2], Kb + row * 128u + (((uint32_t)ki * 32u + kcol_l) ^ ((row & 7u) * 16u)));
            }
            #pragma unroll
            for (int u = 0; u < 6; u++)
                MMA16816H(st[u], qf[ki], kf[u >> 1][(u & 1) * 2], kf[u >> 1][(u & 1) * 2 + 1]);
        }

        uint32_t pf[6][2];
        #pragma unroll
        for (int u = 0; u < 6; u++) {
            const int j = j0 + 8 * u + 2 * tq;
            const bool k0a = (j     <= i0) && (j     >= i0 - WIN) && (j     >= 0);
            const bool k0b = (j + 1 <= i0) && (j + 1 >= i0 - WIN) && (j + 1 >= 0);
            const bool k1a = (j     <= i1) && (j     >= i1 - WIN) && (j     >= 0);
            const bool k1b = (j + 1 <= i1) && (j + 1 >= i1 - WIN) && (j + 1 >= 0);
            const float p0 = k0a ? __expf(st[u][0] * 0.125f) : 0.0f;
            const float p1 = k0b ? __expf(st[u][1] * 0.125f) : 0.0f;
            const float p2 = k1a ? __expf(st[u][2] * 0.125f) : 0.0f;
            const float p3 = k1b ? __expf(st[u][3] * 0.125f) : 0.0f;
            l0 += p0 + p1;
            l1 += p2 + p3;
            pf[u][0] = h2u(__floats2half2_rn(p0, p1));
            pf[u][1] = h2u(__floats2half2_rn(p2, p3));
        }

        #pragma unroll
        for (int kk = 0; kk < 3; kk++) {
            uint32_t af[4] = {pf[2 * kk][0], pf[2 * kk][1], pf[2 * kk + 1][0], pf[2 * kk + 1][1]};
            const uint32_t row = (uint32_t)rk0 + (uint32_t)kk * 16u + vrow_l;
            const uint32_t rm = (row & 7u) * 16u;
            #pragma unroll
            for (int g2 = 0; g2 < 4; g2++) {
                uint32_t vf[4];
                LDSM4T(vf, Vb + row * 128u + (((uint32_t)g2 * 32u + vcol_l) ^ rm));
                MMA16816H(o[2 * g2],     af, vf[0], vf[1]);
                MMA16816H(o[2 * g2 + 1], af, vf[2], vf[3]);
            }
        }
    }

    l0 += __shfl_xor_sync(0xffffffffu, l0, 1);
    l0 += __shfl_xor_sync(0xffffffffu, l0, 2);
    l1 += __shfl_xor_sync(0xffffffffu, l1, 1);
    l1 += __shfl_xor_sync(0xffffffffu, l1, 2);
    const float r0 = 1.0f / l0, r1 = 1.0f / l1;
    __half2* d0 = reinterpret_cast<__half2*>(
        g_ctx + (size_t)(b * T_DIM + i0) * E_DIM + h * D_DIM);
    __half2* d1 = reinterpret_cast<__half2*>(
        g_ctx + (size_t)(b * T_DIM + i1) * E_DIM + h * D_DIM);
    #pragma unroll
    for (int u = 0; u < 8; u++) {
        d0[4 * u + tq] = __floats2half2_rn(o[u][0] * r0, o[u][1] * r0);
        d1[4 * u + tq] = __floats2half2_rn(o[u][2] * r1, o[u][3] * r1);
    }
}

// ============================== launch ====================================
extern "C" void kernel_launch(void* const* d_in, const int* in_sizes, int n_in,
                              void* d_out, int out_size) {
    const float* x     = (const float*)d_in[0];
    const float* gamma = (const float*)d_in[2];
    const float* beta  = (const float*)d_in[3];
    const float* w_in  = (const float*)d_in[4];
    const float* b_in  = (const float*)d_in[5];
    const float* w_out = (const float*)d_in[6];
    const float* b_out = (const float*)d_in[7];
    float* out = (float*)d_out;

    __half *xn, *qkvh, *ctx, *win_hi, *win_lo, *wout_hi, *wout_lo;
    cudaGetSymbolAddress((void**)&xn,      g_xn);
    cudaGetSymbolAddress((void**)&qkvh,    g_qkv);
    cudaGetSymbolAddress((void**)&ctx,     g_ctx);
    cudaGetSymbolAddress((void**)&win_hi,  g_win_hi);
    cudaGetSymbolAddress((void**)&win_lo,  g_win_lo);
    cudaGetSymbolAddress((void**)&wout_hi, g_wout_hi);
    cudaGetSymbolAddress((void**)&wout_lo, g_wout_lo);

    cudaFuncSetAttribute(gemm_mma<__half>, cudaFuncAttributeMaxDynamicSharedMemorySize, SMEM_GEMM);
    cudaFuncSetAttribute(gemm_mma<float>,  cudaFuncAttributeMaxDynamicSharedMemorySize, SMEM_GEMM);
    cudaFuncSetAttribute(attn_mma, cudaFuncAttributeMaxDynamicSharedMemorySize, ATTN_SMEM);

    ln_kernel<<<ROWS, 128>>>(x, gamma, beta);
    conv_split<<<(QKV_W * E_DIM / 4 + 255) / 256, 256>>>(w_in, win_hi, win_lo, QKV_W * E_DIM / 4);
    conv_split<<<(E_DIM * E_DIM / 4 + 255) / 256, 256>>>(w_out, wout_hi, wout_lo, E_DIM * E_DIM / 4);
    gemm_mma<__half><<<dim3(QKV_W / 128, ROWS / 128), 256, SMEM_GEMM>>>(
        xn, win_hi, win_lo, b_in, qkvh, QKV_W);
    attn_mma<<<dim3(T_DIM / 128, H_DIM, B_DIM), 256, ATTN_SMEM>>>(qkvh);
    gemm_mma<float><<<dim3(E_DIM / 128, ROWS / 128), 256, SMEM_GEMM>>>(
        ctx, wout_hi, wout_lo, b_out, out, E_DIM);
}

// round 10
// speedup vs baseline: 3.3779x; 1.2515x over previous
#include <cuda_runtime.h>
#include <cuda_fp16.h>
#include <math.h>
#include <stdint.h>

#define E_DIM 512
#define T_DIM 1024
#define B_DIM 8
#define H_DIM 8
#define D_DIM 64
#define WIN   128
#define ROWS  (B_DIM * T_DIM)   // 8192
#define QKV_W (3 * E_DIM)       // 1536
#define K_DIM 512
#define KC    64
#define NCHUNK (K_DIM / KC)               // 8
#define TILE_BYTES (128 * 128)            // 16 KB
#define SMEM_GEMM (96 * 1024)

// -------------------- scratch (__device__ globals) -------------------------
__device__ __half g_xn  [ROWS * E_DIM];
__device__ __half g_qkv [ROWS * QKV_W];
__device__ __half g_ctx [ROWS * E_DIM];
__device__ __half g_win_hi[QKV_W * E_DIM];
__device__ __half g_wout_hi[E_DIM * E_DIM];
__device__ __half g_wout_lo[E_DIM * E_DIM];

// ============================ helpers ======================================
__device__ __forceinline__ uint32_t smem_u32(const void* p) {
    uint32_t a;
    asm("{ .reg .u64 t; cvta.to.shared.u64 t, %1; cvt.u32.u64 %0, t; }" : "=r"(a) : "l"(p));
    return a;
}
__device__ __forceinline__ void cp16(uint32_t dst, const void* src) {
    asm volatile("cp.async.cg.shared.global [%0], [%1], 16;" :: "r"(dst), "l"(src));
}
#define CP_COMMIT() asm volatile("cp.async.commit_group;" ::: "memory")
#define CP_WAIT2()  asm volatile("cp.async.wait_group 2;" ::: "memory")
#define CP_WAIT1()  asm volatile("cp.async.wait_group 1;" ::: "memory")
#define CP_WAIT0()  asm volatile("cp.async.wait_group 0;" ::: "memory")

#define LDSM4(R, addr)                                                          \
    asm volatile("ldmatrix.sync.aligned.m8n8.x4.shared.b16 {%0,%1,%2,%3}, [%4];" \
        : "=r"((R)[0]), "=r"((R)[1]), "=r"((R)[2]), "=r"((R)[3]) : "r"(addr))

#define LDSM4T(R, addr)                                                         \
    asm volatile("ldmatrix.sync.aligned.m8n8.x4.trans.shared.b16 {%0,%1,%2,%3}, [%4];" \
        : "=r"((R)[0]), "=r"((R)[1]), "=r"((R)[2]), "=r"((R)[3]) : "r"(addr))

#define MMA16816H(D, A, B0, B1)                                                 \
    asm volatile("mma.sync.aligned.m16n8k16.row.col.f32.f16.f16.f32 "           \
        "{%0,%1,%2,%3},{%4,%5,%6,%7},{%8,%9},{%0,%1,%2,%3};"                    \
        : "+f"((D)[0]), "+f"((D)[1]), "+f"((D)[2]), "+f"((D)[3])                \
        : "r"((A)[0]), "r"((A)[1]), "r"((A)[2]), "r"((A)[3]), "r"(B0), "r"(B1))

__device__ __forceinline__ void split_fp16(float x, __half& h, __half& l) {
    h = __float2half(x);
    l = __float2half(x - __half2float(h));
}
__device__ __forceinline__ uint32_t swz(uint32_t off) {
    return off ^ ((off >> 3) & 0x70u);
}
__device__ __forceinline__ uint32_t h2u(__half2 v) { return *reinterpret_cast<uint32_t*>(&v); }

__device__ __forceinline__ void st_pair(float* p, float a, float b) {
    *reinterpret_cast<float2*>(p) = make_float2(a, b);
}
__device__ __forceinline__ void st_pair(__half* p, float a, float b) {
    *reinterpret_cast<__half2*>(p) = __floats2half2_rn(a, b);
}

// ======================= LayerNorm -> fp16 =================================
__global__ __launch_bounds__(128) void ln_kernel(const float* __restrict__ x,
                                                 const float* __restrict__ gamma,
                                                 const float* __restrict__ beta) {
    const int row = blockIdx.x;
    const int tid = threadIdx.x;
    const float4 v = reinterpret_cast<const float4*>(x + (size_t)row * E_DIM)[tid];
    float s  = v.x + v.y + v.z + v.w;
    float ss = v.x * v.x + v.y * v.y + v.z * v.z + v.w * v.w;
    #pragma unroll
    for (int o = 16; o > 0; o >>= 1) {
        s  += __shfl_down_sync(0xffffffffu, s,  o);
        ss += __shfl_down_sync(0xffffffffu, ss, o);
    }
    __shared__ float sh_s[4], sh_ss[4], sh_mu, sh_rstd;
    const int w = tid >> 5, lane = tid & 31;
    if (lane == 0) { sh_s[w] = s; sh_ss[w] = ss; }
    __syncthreads();
    if (tid == 0) {
        float ts  = sh_s[0] + sh_s[1] + sh_s[2] + sh_s[3];
        float tss = sh_ss[0] + sh_ss[1] + sh_ss[2] + sh_ss[3];
        float mu  = ts * (1.0f / E_DIM);
        float var = tss * (1.0f / E_DIM) - mu * mu;
        sh_mu = mu; sh_rstd = rsqrtf(var + 1e-5f);
    }
    __syncthreads();
    const float mu = sh_mu, rstd = sh_rstd;
    const float4 g  = reinterpret_cast<const float4*>(gamma)[tid];
    const float4 be = reinterpret_cast<const float4*>(beta)[tid];
    float2 a, b;
    a.x = (v.x - mu) * rstd * g.x + be.x;
    a.y = (v.y - mu) * rstd * g.y + be.y;
    b.x = (v.z - mu) * rstd * g.z + be.z;
    b.y = (v.w - mu) * rstd * g.w + be.w;
    __half2* o = reinterpret_cast<__half2*>(g_xn + (size_t)row * E_DIM);
    o[2 * tid + 0] = __float22half2_rn(a);
    o[2 * tid + 1] = __float22half2_rn(b);
}

// ===================== weight fp32 -> fp16 hi(+lo) =========================
__global__ __launch_bounds__(256) void conv_split(const float* __restrict__ src,
                                                  __half* __restrict__ hi,
                                                  __half* __restrict__ lo, int n4) {
    const int i = blockIdx.x * 256 + threadIdx.x;
    if (i < n4) {
        const float4 v = reinterpret_cast<const float4*>(src)[i];
        __half h[4], l[4];
        split_fp16(v.x, h[0], l[0]);
        split_fp16(v.y, h[1], l[1]);
        split_fp16(v.z, h[2], l[2]);
        split_fp16(v.w, h[3], l[3]);
        __half2* oh = reinterpret_cast<__half2*>(hi);
        oh[2 * i + 0] = __halves2half2(h[0], h[1]);
        oh[2 * i + 1] = __halves2half2(h[2], h[3]);
        if (lo) {
            __half2* ol = reinterpret_cast<__half2*>(lo);
            ol[2 * i + 0] = __halves2half2(l[0], l[1]);
            ol[2 * i + 1] = __halves2half2(l[2], l[3]);
        }
    }
}

// ===================== fp16 GEMM via mma.sync ==============================
// C[m,n] = bias[n] + sum_k A[m,k]*W[n,k].
// TWO=true: W = Wh + Wl (2-term, stage 48KB x 2). TWO=false: W = Wh only
// (1-term, stage 32KB x 3). CTA 128x128, 8 warps 2(M)x4(N), warp 64x32.
template <typename OT, bool TWO>
__global__ __launch_bounds__(256, 2)
void gemm_mma(const __half* __restrict__ A,
              const __half* __restrict__ Wh, const __half* __restrict__ Wl,
              const float* __restrict__ bias, OT* __restrict__ C, const int N) {
    constexpr uint32_t WH_OFF = TILE_BYTES;
    constexpr uint32_t WL_OFF = 2 * TILE_BYTES;
    constexpr uint32_t STAGE  = TWO ? (3 * TILE_BYTES) : (2 * TILE_BYTES);
    constexpr int NST = TWO ? 2 : 3;

    extern __shared__ char smem[];
    const uint32_t sbase = smem_u32(smem);
    const int tid  = threadIdx.x;
    const int wid  = tid >> 5;
    const int lane = tid & 31;
    const int bn = blockIdx.x * 128;
    const int bm = blockIdx.y * 128;

    const int lrow  = tid >> 1;
    const int lhalf = tid & 1;
    const __half* aS  = A  + (size_t)(bm + lrow) * K_DIM + lhalf * 32;
    const __half* wHS = Wh + (size_t)(bn + lrow) * K_DIM + lhalf * 32;
    const __half* wLS = TWO ? (Wl + (size_t)(bn + lrow) * K_DIM + lhalf * 32) : nullptr;
    uint32_t st_off[4];
    #pragma unroll
    for (int v = 0; v < 4; v++) {
        const uint32_t off = (uint32_t)lrow * 128u + (uint32_t)lhalf * 64u + (uint32_t)v * 16u;
        st_off[v] = swz(off);
    }

    auto load_stage = [&](int s, int c) {
        const uint32_t st = sbase + (uint32_t)s * STAGE;
        const int kc = c * KC;
        #pragma unroll
        for (int v = 0; v < 4; v++) {
            cp16(st + st_off[v],          aS  + kc + v * 8);
            cp16(st + WH_OFF + st_off[v], wHS + kc + v * 8);
            if (TWO) cp16(st + WL_OFF + st_off[v], wLS + kc + v * 8);
        }
        CP_COMMIT();
    };

    const int wm = (wid & 1) * 64;
    const int wn = (wid >> 1) * 32;
    uint32_t a_rowoff[4], a_mask[4];
    #pragma unroll
    for (int mi = 0; mi < 4; mi++) {
        const uint32_t r = (uint32_t)(wm + mi * 16 + (lane & 15));
        a_rowoff[mi] = r * 128u;
        a_mask[mi]   = (a_rowoff[mi] >> 3) & 0x70u;
    }
    const uint32_t a_kb = ((uint32_t)lane >> 4) * 16u;
    const int b_lrow = (lane & 7) + ((lane >> 4) << 3);
    uint32_t b_rowoff[2], b_mask[2];
    #pragma unroll
    for (int np = 0; np < 2; np++) {
        const uint32_t r = (uint32_t)(wn + np * 16 + b_lrow);
        b_rowoff[np] = r * 128u;
        b_mask[np]   = (b_rowoff[np] >> 3) & 0x70u;
    }
    const uint32_t b_kb = (((uint32_t)lane >> 3) & 1u) * 16u;

    float acc[4][4][4];
    #pragma unroll
    for (int mi = 0; mi < 4; mi++)
        #pragma unroll
        for (int ni = 0; ni < 4; ni++)
            #pragma unroll
            for (int r = 0; r < 4; r++) acc[mi][ni][r] = 0.0f;

    #pragma unroll
    for (int s = 0; s < NST; s++) load_stage(s, s);

    for (int c = 0; c < NCHUNK; c++) {
        const int s = c % NST;
        const uint32_t st = sbase + (uint32_t)s * STAGE;
        if (NST == 3) {
            if (c <= NCHUNK - 3)      CP_WAIT2();
            else if (c == NCHUNK - 2) CP_WAIT1();
            else                      CP_WAIT0();
        } else {
            if (c < NCHUNK - 1) CP_WAIT1(); else CP_WAIT0();
        }
        __syncthreads();

        #pragma unroll
        for (int ks = 0; ks < 4; ks++) {
            const uint32_t akb = (uint32_t)ks * 32u + a_kb;
            const uint32_t bkb = (uint32_t)ks * 32u + b_kb;
            uint32_t ar[4][4], bh[2][4], bl[2][4];
            #pragma unroll
            for (int mi = 0; mi < 4; mi++)
                LDSM4(ar[mi], st + a_rowoff[mi] + (akb ^ a_mask[mi]));
            #pragma unroll
            for (int np = 0; np < 2; np++) {
                LDSM4(bh[np], st + WH_OFF + b_rowoff[np] + (bkb ^ b_mask[np]));
                if (TWO) LDSM4(bl[np], st + WL_OFF + b_rowoff[np] + (bkb ^ b_mask[np]));
            }
            #pragma unroll
            for (int mi = 0; mi < 4; mi++)
                #pragma unroll
                for (int ni = 0; ni < 4; ni++) {
                    const int np = ni >> 1, po = (ni & 1) * 2;
                    MMA16816H(acc[mi][ni], ar[mi], bh[np][po], bh[np][po + 1]);
                }
            if (TWO) {
                #pragma unroll
                for (int mi = 0; mi < 4; mi++)
                    #pragma unroll
                    for (int ni = 0; ni < 4; ni++) {
                        const int np = ni >> 1, po = (ni & 1) * 2;
                        MMA16816H(acc[mi][ni], ar[mi], bl[np][po], bl[np][po + 1]);
                    }
            }
        }

        __syncthreads();
        if (c + NST < NCHUNK) load_stage(s, c + NST);
    }

    const int gid = lane >> 2;
    const int tig = lane & 3;
    #pragma unroll
    for (int mi = 0; mi < 4; mi++) {
        const int row0 = bm + wm + mi * 16 + gid;
        OT* C0 = C + (size_t)row0 * N;
        OT* C1 = C + (size_t)(row0 + 8) * N;
        #pragma unroll
        for (int ni = 0; ni < 4; ni++) {
            const int col = bn + wn + ni * 8 + tig * 2;
            const float b0 = bias[col], b1 = bias[col + 1];
            st_pair(C0 + col, acc[mi][ni][0] + b0, acc[mi][ni][1] + b1);
            st_pair(C1 + col, acc[mi][ni][2] + b0, acc[mi][ni][3] + b1);
        }
    }
}

// ================ Tensor-core windowed causal attention (R9) ===============
#define ATTN_SMEM (16384 + 32768 + 32768)

__global__ __launch_bounds__(256) void attn_mma(const __half* __restrict__ qkv) {
    extern __shared__ char sm[];
    const uint32_t sbase = smem_u32(sm);
    const uint32_t Qb = sbase, Kb = sbase + 16384u, Vb = sbase + 49152u;
    char* Kp = sm + 16384; char* Vp = sm + 49152;
    const int qt  = blockIdx.x * 128;
    const int h   = blockIdx.y;
    const int b   = blockIdx.z;
    const int tid = threadIdx.x;
    const int wid = tid >> 5;
    const int lane = tid & 31;

    if (tid < 128) {
        const __half* src = qkv + (size_t)(b * T_DIM + qt + tid) * QKV_W + h * D_DIM;
        const uint32_t rmask = (uint32_t)(tid & 7) * 16u;
        #pragma unroll
        for (int c = 0; c < 8; c++)
            cp16(Qb + (uint32_t)tid * 128u + (((uint32_t)c * 16u) ^ rmask), src + c * 8);
    }
    {
        const int j = qt - 128 + tid;
        const uint32_t rmask = (uint32_t)(tid & 7) * 16u;
        if (j >= 0) {
            const __half* ks = qkv + (size_t)(b * T_DIM + j) * QKV_W + E_DIM + h * D_DIM;
            const __half* vs = ks + E_DIM;
            #pragma unroll
            for (int c = 0; c < 8; c++) {
                const uint32_t so = (uint32_t)tid * 128u + (((uint32_t)c * 16u) ^ rmask);
                cp16(Kb + so, ks + c * 8);
                cp16(Vb + so, vs + c * 8);
            }
        } else {
            const uint4 z = make_uint4(0, 0, 0, 0);
            #pragma unroll
            for (int c = 0; c < 8; c++) {
                const uint32_t so = (uint32_t)tid * 128u + (((uint32_t)c * 16u) ^ rmask);
                *reinterpret_cast<uint4*>(Kp + so) = z;
                *reinterpret_cast<uint4*>(Vp + so) = z;
            }
        }
    }
    CP_COMMIT();
    CP_WAIT0();
    __syncthreads();

    uint32_t qf[4][4];
    {
        const uint32_t arow = (uint32_t)(wid * 16 + (lane & 15));
        const uint32_t amask = (arow & 7u) * 16u;
        const uint32_t acol = ((uint32_t)lane >> 4) * 16u;
        #pragma unroll
        for (int ki = 0; ki < 4; ki++)
            LDSM4(qf[ki], Qb + arow * 128u + (((uint32_t)ki * 32u + acol) ^ amask));
    }

    float o[8][4];
    #pragma unroll
    for (int u = 0; u < 8; u++)
        #pragma unroll
        for (int r = 0; r < 4; r++) o[u][r] = 0.0f;
    float l0 = 0.0f, l1 = 0.0f;
    const int i0 = qt + wid * 16 + (lane >> 2);
    const int i1 = i0 + 8;
    const int tq = lane & 3;
    const int wr0 = wid * 16;

    const uint32_t krow_l = (uint32_t)((lane & 7) + ((lane >> 4) << 3));
    const uint32_t kcol_l = (((uint32_t)lane >> 3) & 1u) * 16u;
    const uint32_t vrow_l = (uint32_t)((lane & 7) + (((lane >> 3) & 1) << 3));
    const uint32_t vcol_l = ((uint32_t)lane >> 4) * 16u;

    #pragma unroll
    for (int c = 0; c < 3; c++) {
        const int rk0 = wr0 + 48 * c;
        const int j0 = qt - 128 + rk0;

        float st[6][4];
        #pragma unroll
        for (int u = 0; u < 6; u++)
            #pragma unroll
            for (int r = 0; r < 4; r++) st[u][r] = 0.0f;

        #pragma unroll
        for (int ki = 0; ki < 4; ki++) {
            uint32_t kf[3][4];
            #pragma unroll
            for (int g2 = 0; g2 < 3; g2++) {
                const uint32_t row = (uint32_t)rk0 + (uint32_t)g2 * 16u + krow_l;
                LDSM4(kf[g2], Kb + row * 128u + (((uint32_t)ki * 32u + kcol_l) ^ ((row & 7u) * 16u)));
            }
            #pragma unroll
            for (int u = 0; u < 6; u++)
                MMA16816H(st[u], qf[ki], kf[u >> 1][(u & 1) * 2], kf[u >> 1][(u & 1) * 2 + 1]);
        }

        uint32_t pf[6][2];
        #pragma unroll
        for (int u = 0; u < 6; u++) {
            const int j = j0 + 8 * u + 2 * tq;
            const bool k0a = (j     <= i0) && (j     >= i0 - WIN) && (j     >= 0);
            const bool k0b = (j + 1 <= i0) && (j + 1 >= i0 - WIN) && (j + 1 >= 0);
            const bool k1a = (j     <= i1) && (j     >= i1 - WIN) && (j     >= 0);
            const bool k1b = (j + 1 <= i1) && (j + 1 >= i1 - WIN) && (j + 1 >= 0);
            const float p0 = k0a ? __expf(st[u][0] * 0.125f) : 0.0f;
            const float p1 = k0b ? __expf(st[u][1] * 0.125f) : 0.0f;
            const float p2 = k1a ? __expf(st[u][2] * 0.125f) : 0.0f;
            const float p3 = k1b ? __expf(st[u][3] * 0.125f) : 0.0f;
            l0 += p0 + p1;
            l1 += p2 + p3;
            pf[u][0] = h2u(__floats2half2_rn(p0, p1));
            pf[u][1] = h2u(__floats2half2_rn(p2, p3));
        }

        #pragma unroll
        for (int kk = 0; kk < 3; kk++) {
            uint32_t af[4] = {pf[2 * kk][0], pf[2 * kk][1], pf[2 * kk + 1][0], pf[2 * kk + 1][1]};
            const uint32_t row = (uint32_t)rk0 + (uint32_t)kk * 16u + vrow_l;
            const uint32_t rm = (row & 7u) * 16u;
            #pragma unroll
            for (int g2 = 0; g2 < 4; g2++) {
                uint32_t vf[4];
                LDSM4T(vf, Vb + row * 128u + (((uint32_t)g2 * 32u + vcol_l) ^ rm));
                MMA16816H(o[2 * g2],     af, vf[0], vf[1]);
                MMA16816H(o[2 * g2 + 1], af, vf[2], vf[3]);
            }
        }
    }

    l0 += __shfl_xor_sync(0xffffffffu, l0, 1);
    l0 += __shfl_xor_sync(0xffffffffu, l0, 2);
    l1 += __shfl_xor_sync(0xffffffffu, l1, 1);
    l1 += __shfl_xor_sync(0xffffffffu, l1, 2);
    const float r0 = 1.0f / l0, r1 = 1.0f / l1;
    __half2* d0 = reinterpret_cast<__half2*>(
        g_ctx + (size_t)(b * T_DIM + i0) * E_DIM + h * D_DIM);
    __half2* d1 = reinterpret_cast<__half2*>(
        g_ctx + (size_t)(b * T_DIM + i1) * E_DIM + h * D_DIM);
    #pragma unroll
    for (int u = 0; u < 8; u++) {
        d0[4 * u + tq] = __floats2half2_rn(o[u][0] * r0, o[u][1] * r0);
        d1[4 * u + tq] = __floats2half2_rn(o[u][2] * r1, o[u][3] * r1);
    }
}

// ============================== launch ====================================
extern "C" void kernel_launch(void* const* d_in, const int* in_sizes, int n_in,
                              void* d_out, int out_size) {
    const float* x     = (const float*)d_in[0];
    const float* gamma = (const float*)d_in[2];
    const float* beta  = (const float*)d_in[3];
    const float* w_in  = (const float*)d_in[4];
    const float* b_in  = (const float*)d_in[5];
    const float* w_out = (const float*)d_in[6];
    const float* b_out = (const float*)d_in[7];
    float* out = (float*)d_out;

    __half *xn, *qkvh, *ctx, *win_hi, *wout_hi, *wout_lo;
    cudaGetSymbolAddress((void**)&xn,      g_xn);
    cudaGetSymbolAddress((void**)&qkvh,    g_qkv);
    cudaGetSymbolAddress((void**)&ctx,     g_ctx);
    cudaGetSymbolAddress((void**)&win_hi,  g_win_hi);
    cudaGetSymbolAddress((void**)&wout_hi, g_wout_hi);
    cudaGetSymbolAddress((void**)&wout_lo, g_wout_lo);

    cudaFuncSetAttribute((void*)gemm_mma<__half, false>,
                         cudaFuncAttributeMaxDynamicSharedMemorySize, SMEM_GEMM);
    cudaFuncSetAttribute((void*)gemm_mma<float, true>,
                         cudaFuncAttributeMaxDynamicSharedMemorySize, SMEM_GEMM);
    cudaFuncSetAttribute(attn_mma, cudaFuncAttributeMaxDynamicSharedMemorySize, ATTN_SMEM);

    ln_kernel<<<ROWS, 128>>>(x, gamma, beta);
    conv_split<<<(QKV_W * E_DIM / 4 + 255) / 256, 256>>>(w_in, win_hi, nullptr, QKV_W * E_DIM / 4);
    conv_split<<<(E_DIM * E_DIM / 4 + 255) / 256, 256>>>(w_out, wout_hi, wout_lo, E_DIM * E_DIM / 4);
    gemm_mma<__half, false><<<dim3(QKV_W / 128, ROWS / 128), 256, SMEM_GEMM>>>(
        xn, win_hi, nullptr, b_in, qkvh, QKV_W);
    attn_mma<<<dim3(T_DIM / 128, H_DIM, B_DIM), 256, ATTN_SMEM>>>(qkvh);
    gemm_mma<float, true><<<dim3(E_DIM / 128, ROWS / 128), 256, SMEM_GEMM>>>(
        ctx, wout_hi, wout_lo, b_out, out, E_DIM);
}

// round 11
// speedup vs baseline: 3.7264x; 1.1032x over previous
#include <cuda_runtime.h>
#include <cuda_fp16.h>
#include <math.h>
#include <stdint.h>

#define E_DIM 512
#define T_DIM 1024
#define B_DIM 8
#define H_DIM 8
#define D_DIM 64
#define WIN   128
#define ROWS  (B_DIM * T_DIM)   // 8192
#define QKV_W (3 * E_DIM)       // 1536
#define K_DIM 512
#define KC    64
#define NCHUNK (K_DIM / KC)               // 8
#define TILE_BYTES (128 * 128)            // 16 KB
#define SMEM_GEMM (96 * 1024)

// -------------------- scratch (__device__ globals) -------------------------
__device__ __half g_xn  [ROWS * E_DIM];
__device__ __half g_qkv [ROWS * QKV_W];
__device__ __half g_ctx [ROWS * E_DIM];
__device__ __half g_win_hi[QKV_W * E_DIM];
__device__ __half g_wout_hi[E_DIM * E_DIM];

// ============================ helpers ======================================
__device__ __forceinline__ uint32_t smem_u32(const void* p) {
    uint32_t a;
    asm("{ .reg .u64 t; cvta.to.shared.u64 t, %1; cvt.u32.u64 %0, t; }" : "=r"(a) : "l"(p));
    return a;
}
__device__ __forceinline__ void cp16(uint32_t dst, const void* src) {
    asm volatile("cp.async.cg.shared.global [%0], [%1], 16;" :: "r"(dst), "l"(src));
}
#define CP_COMMIT() asm volatile("cp.async.commit_group;" ::: "memory")
#define CP_WAIT2()  asm volatile("cp.async.wait_group 2;" ::: "memory")
#define CP_WAIT1()  asm volatile("cp.async.wait_group 1;" ::: "memory")
#define CP_WAIT0()  asm volatile("cp.async.wait_group 0;" ::: "memory")

#define LDSM4(R, addr)                                                          \
    asm volatile("ldmatrix.sync.aligned.m8n8.x4.shared.b16 {%0,%1,%2,%3}, [%4];" \
        : "=r"((R)[0]), "=r"((R)[1]), "=r"((R)[2]), "=r"((R)[3]) : "r"(addr))

#define LDSM4T(R, addr)                                                         \
    asm volatile("ldmatrix.sync.aligned.m8n8.x4.trans.shared.b16 {%0,%1,%2,%3}, [%4];" \
        : "=r"((R)[0]), "=r"((R)[1]), "=r"((R)[2]), "=r"((R)[3]) : "r"(addr))

#define MMA16816H(D, A, B0, B1)                                                 \
    asm volatile("mma.sync.aligned.m16n8k16.row.col.f32.f16.f16.f32 "           \
        "{%0,%1,%2,%3},{%4,%5,%6,%7},{%8,%9},{%0,%1,%2,%3};"                    \
        : "+f"((D)[0]), "+f"((D)[1]), "+f"((D)[2]), "+f"((D)[3])                \
        : "r"((A)[0]), "r"((A)[1]), "r"((A)[2]), "r"((A)[3]), "r"(B0), "r"(B1))

__device__ __forceinline__ uint32_t swz(uint32_t off) {
    return off ^ ((off >> 3) & 0x70u);
}
__device__ __forceinline__ uint32_t h2u(__half2 v) { return *reinterpret_cast<uint32_t*>(&v); }

__device__ __forceinline__ void st_pair(float* p, float a, float b) {
    *reinterpret_cast<float2*>(p) = make_float2(a, b);
}
__device__ __forceinline__ void st_pair(__half* p, float a, float b) {
    *reinterpret_cast<__half2*>(p) = __floats2half2_rn(a, b);
}

// ======================= LayerNorm -> fp16 =================================
__global__ __launch_bounds__(128) void ln_kernel(const float* __restrict__ x,
                                                 const float* __restrict__ gamma,
                                                 const float* __restrict__ beta) {
    const int row = blockIdx.x;
    const int tid = threadIdx.x;
    const float4 v = reinterpret_cast<const float4*>(x + (size_t)row * E_DIM)[tid];
    float s  = v.x + v.y + v.z + v.w;
    float ss = v.x * v.x + v.y * v.y + v.z * v.z + v.w * v.w;
    #pragma unroll
    for (int o = 16; o > 0; o >>= 1) {
        s  += __shfl_down_sync(0xffffffffu, s,  o);
        ss += __shfl_down_sync(0xffffffffu, ss, o);
    }
    __shared__ float sh_s[4], sh_ss[4], sh_mu, sh_rstd;
    const int w = tid >> 5, lane = tid & 31;
    if (lane == 0) { sh_s[w] = s; sh_ss[w] = ss; }
    __syncthreads();
    if (tid == 0) {
        float ts  = sh_s[0] + sh_s[1] + sh_s[2] + sh_s[3];
        float tss = sh_ss[0] + sh_ss[1] + sh_ss[2] + sh_ss[3];
        float mu  = ts * (1.0f / E_DIM);
        float var = tss * (1.0f / E_DIM) - mu * mu;
        sh_mu = mu; sh_rstd = rsqrtf(var + 1e-5f);
    }
    __syncthreads();
    const float mu = sh_mu, rstd = sh_rstd;
    const float4 g  = reinterpret_cast<const float4*>(gamma)[tid];
    const float4 be = reinterpret_cast<const float4*>(beta)[tid];
    float2 a, b;
    a.x = (v.x - mu) * rstd * g.x + be.x;
    a.y = (v.y - mu) * rstd * g.y + be.y;
    b.x = (v.z - mu) * rstd * g.z + be.z;
    b.y = (v.w - mu) * rstd * g.w + be.w;
    __half2* o = reinterpret_cast<__half2*>(g_xn + (size_t)row * E_DIM);
    o[2 * tid + 0] = __float22half2_rn(a);
    o[2 * tid + 1] = __float22half2_rn(b);
}

// ===================== weight fp32 -> fp16 =================================
__global__ __launch_bounds__(256) void conv_h(const float* __restrict__ src,
                                              __half* __restrict__ hi, int n4) {
    const int i = blockIdx.x * 256 + threadIdx.x;
    if (i < n4) {
        const float4 v = reinterpret_cast<const float4*>(src)[i];
        __half2* oh = reinterpret_cast<__half2*>(hi);
        oh[2 * i + 0] = __floats2half2_rn(v.x, v.y);
        oh[2 * i + 1] = __floats2half2_rn(v.z, v.w);
    }
}

// ===================== fp16 GEMM via mma.sync (1-term) =====================
// C[m,n] = bias[n] + sum_k A[m,k]*Wh[n,k]. CTA 128x128, 8 warps 2(M)x4(N),
// warp 64x32, 3-stage cp.async (stage = A 16K + W 16K = 32 KB).
template <typename OT>
__global__ __launch_bounds__(256, 2)
void gemm_mma(const __half* __restrict__ A, const __half* __restrict__ Wh,
              const float* __restrict__ bias, OT* __restrict__ C, const int N) {
    constexpr uint32_t WH_OFF = TILE_BYTES;
    constexpr uint32_t STAGE  = 2 * TILE_BYTES;
    constexpr int NST = 3;

    extern __shared__ char smem[];
    const uint32_t sbase = smem_u32(smem);
    const int tid  = threadIdx.x;
    const int wid  = tid >> 5;
    const int lane = tid & 31;
    const int bn = blockIdx.x * 128;
    const int bm = blockIdx.y * 128;

    const int lrow  = tid >> 1;
    const int lhalf = tid & 1;
    const __half* aS  = A  + (size_t)(bm + lrow) * K_DIM + lhalf * 32;
    const __half* wHS = Wh + (size_t)(bn + lrow) * K_DIM + lhalf * 32;
    uint32_t st_off[4];
    #pragma unroll
    for (int v = 0; v < 4; v++) {
        const uint32_t off = (uint32_t)lrow * 128u + (uint32_t)lhalf * 64u + (uint32_t)v * 16u;
        st_off[v] = swz(off);
    }

    auto load_stage = [&](int s, int c) {
        const uint32_t st = sbase + (uint32_t)s * STAGE;
        const int kc = c * KC;
        #pragma unroll
        for (int v = 0; v < 4; v++) {
            cp16(st + st_off[v],          aS  + kc + v * 8);
            cp16(st + WH_OFF + st_off[v], wHS + kc + v * 8);
        }
        CP_COMMIT();
    };

    const int wm = (wid & 1) * 64;
    const int wn = (wid >> 1) * 32;
    uint32_t a_rowoff[4], a_mask[4];
    #pragma unroll
    for (int mi = 0; mi < 4; mi++) {
        const uint32_t r = (uint32_t)(wm + mi * 16 + (lane & 15));
        a_rowoff[mi] = r * 128u;
        a_mask[mi]   = (a_rowoff[mi] >> 3) & 0x70u;
    }
    const uint32_t a_kb = ((uint32_t)lane >> 4) * 16u;
    const int b_lrow = (lane & 7) + ((lane >> 4) << 3);
    uint32_t b_rowoff[2], b_mask[2];
    #pragma unroll
    for (int np = 0; np < 2; np++) {
        const uint32_t r = (uint32_t)(wn + np * 16 + b_lrow);
        b_rowoff[np] = r * 128u;
        b_mask[np]   = (b_rowoff[np] >> 3) & 0x70u;
    }
    const uint32_t b_kb = (((uint32_t)lane >> 3) & 1u) * 16u;

    float acc[4][4][4];
    #pragma unroll
    for (int mi = 0; mi < 4; mi++)
        #pragma unroll
        for (int ni = 0; ni < 4; ni++)
            #pragma unroll
            for (int r = 0; r < 4; r++) acc[mi][ni][r] = 0.0f;

    #pragma unroll
    for (int s = 0; s < NST; s++) load_stage(s, s);

    for (int c = 0; c < NCHUNK; c++) {
        const int s = c % NST;
        const uint32_t st = sbase + (uint32_t)s * STAGE;
        if (c <= NCHUNK - 3)      CP_WAIT2();
        else if (c == NCHUNK - 2) CP_WAIT1();
        else                      CP_WAIT0();
        __syncthreads();

        #pragma unroll
        for (int ks = 0; ks < 4; ks++) {
            const uint32_t akb = (uint32_t)ks * 32u + a_kb;
            const uint32_t bkb = (uint32_t)ks * 32u + b_kb;
            uint32_t ar[4][4], bh[2][4];
            #pragma unroll
            for (int mi = 0; mi < 4; mi++)
                LDSM4(ar[mi], st + a_rowoff[mi] + (akb ^ a_mask[mi]));
            #pragma unroll
            for (int np = 0; np < 2; np++)
                LDSM4(bh[np], st + WH_OFF + b_rowoff[np] + (bkb ^ b_mask[np]));
            #pragma unroll
            for (int mi = 0; mi < 4; mi++)
                #pragma unroll
                for (int ni = 0; ni < 4; ni++) {
                    const int np = ni >> 1, po = (ni & 1) * 2;
                    MMA16816H(acc[mi][ni], ar[mi], bh[np][po], bh[np][po + 1]);
                }
        }

        __syncthreads();
        if (c + NST < NCHUNK) load_stage(s, c + NST);
    }

    const int gid = lane >> 2;
    const int tig = lane & 3;
    #pragma unroll
    for (int mi = 0; mi < 4; mi++) {
        const int row0 = bm + wm + mi * 16 + gid;
        OT* C0 = C + (size_t)row0 * N;
        OT* C1 = C + (size_t)(row0 + 8) * N;
        #pragma unroll
        for (int ni = 0; ni < 4; ni++) {
            const int col = bn + wn + ni * 8 + tig * 2;
            const float b0 = bias[col], b1 = bias[col + 1];
            st_pair(C0 + col, acc[mi][ni][0] + b0, acc[mi][ni][1] + b1);
            st_pair(C1 + col, acc[mi][ni][2] + b0, acc[mi][ni][3] + b1);
        }
    }
}

// ================ Tensor-core windowed causal attention (R9) ===============
#define ATTN_SMEM (16384 + 32768 + 32768)

__global__ __launch_bounds__(256) void attn_mma(const __half* __restrict__ qkv) {
    extern __shared__ char sm[];
    const uint32_t sbase = smem_u32(sm);
    const uint32_t Qb = sbase, Kb = sbase + 16384u, Vb = sbase + 49152u;
    char* Kp = sm + 16384; char* Vp = sm + 49152;
    const int qt  = blockIdx.x * 128;
    const int h   = blockIdx.y;
    const int b   = blockIdx.z;
    const int tid = threadIdx.x;
    const int wid = tid >> 5;
    const int lane = tid & 31;

    if (tid < 128) {
        const __half* src = qkv + (size_t)(b * T_DIM + qt + tid) * QKV_W + h * D_DIM;
        const uint32_t rmask = (uint32_t)(tid & 7) * 16u;
        #pragma unroll
        for (int c = 0; c < 8; c++)
            cp16(Qb + (uint32_t)tid * 128u + (((uint32_t)c * 16u) ^ rmask), src + c * 8);
    }
    {
        const int j = qt - 128 + tid;
        const uint32_t rmask = (uint32_t)(tid & 7) * 16u;
        if (j >= 0) {
            const __half* ks = qkv + (size_t)(b * T_DIM + j) * QKV_W + E_DIM + h * D_DIM;
            const __half* vs = ks + E_DIM;
            #pragma unroll
            for (int c = 0; c < 8; c++) {
                const uint32_t so = (uint32_t)tid * 128u + (((uint32_t)c * 16u) ^ rmask);
                cp16(Kb + so, ks + c * 8);
                cp16(Vb + so, vs + c * 8);
            }
        } else {
            const uint4 z = make_uint4(0, 0, 0, 0);
            #pragma unroll
            for (int c = 0; c < 8; c++) {
                const uint32_t so = (uint32_t)tid * 128u + (((uint32_t)c * 16u) ^ rmask);
                *reinterpret_cast<uint4*>(Kp + so) = z;
                *reinterpret_cast<uint4*>(Vp + so) = z;
            }
        }
    }
    CP_COMMIT();
    CP_WAIT0();
    __syncthreads();

    uint32_t qf[4][4];
    {
        const uint32_t arow = (uint32_t)(wid * 16 + (lane & 15));
        const uint32_t amask = (arow & 7u) * 16u;
        const uint32_t acol = ((uint32_t)lane >> 4) * 16u;
        #pragma unroll
        for (int ki = 0; ki < 4; ki++)
            LDSM4(qf[ki], Qb + arow * 128u + (((uint32_t)ki * 32u + acol) ^ amask));
    }

    float o[8][4];
    #pragma unroll
    for (int u = 0; u < 8; u++)
        #pragma unroll
        for (int r = 0; r < 4; r++) o[u][r] = 0.0f;
    float l0 = 0.0f, l1 = 0.0f;
    const int i0 = qt + wid * 16 + (lane >> 2);
    const int i1 = i0 + 8;
    const int tq = lane & 3;
    const int wr0 = wid * 16;

    const uint32_t krow_l = (uint32_t)((lane & 7) + ((lane >> 4) << 3));
    const uint32_t kcol_l = (((uint32_t)lane >> 3) & 1u) * 16u;
    const uint32_t vrow_l = (uint32_t)((lane & 7) + (((lane >> 3) & 1) << 3));
    const uint32_t vcol_l = ((uint32_t)lane >> 4) * 16u;

    #pragma unroll
    for (int c = 0; c < 3; c++) {
        const int rk0 = wr0 + 48 * c;
        const int j0 = qt - 128 + rk0;

        float st[6][4];
        #pragma unroll
        for (int u = 0; u < 6; u++)
            #pragma unroll
            for (int r = 0; r < 4; r++) st[u][r] = 0.0f;

        #pragma unroll
        for (int ki = 0; ki < 4; ki++) {
            uint32_t kf[3][4];
            #pragma unroll
            for (int g2 = 0; g2 < 3; g2++) {
                const uint32_t row = (uint32_t)rk0 + (uint32_t)g2 * 16u + krow_l;
                LDSM4(kf[g2], Kb + row * 128u + (((uint32_t)ki * 32u + kcol_l) ^ ((row & 7u) * 16u)));
            }
            #pragma unroll
            for (int u = 0; u < 6; u++)
                MMA16816H(st[u], qf[ki], kf[u >> 1][(u & 1) * 2], kf[u >> 1][(u & 1) * 2 + 1]);
        }

        uint32_t pf[6][2];
        #pragma unroll
        for (int u = 0; u < 6; u++) {
            const int j = j0 + 8 * u + 2 * tq;
            const bool k0a = (j     <= i0) && (j     >= i0 - WIN) && (j     >= 0);
            const bool k0b = (j + 1 <= i0) && (j + 1 >= i0 - WIN) && (j + 1 >= 0);
            const bool k1a = (j     <= i1) && (j     >= i1 - WIN) && (j     >= 0);
            const bool k1b = (j + 1 <= i1) && (j + 1 >= i1 - WIN) && (j + 1 >= 0);
            const float p0 = k0a ? __expf(st[u][0] * 0.125f) : 0.0f;
            const float p1 = k0b ? __expf(st[u][1] * 0.125f) : 0.0f;
            const float p2 = k1a ? __expf(st[u][2] * 0.125f) : 0.0f;
            const float p3 = k1b ? __expf(st[u][3] * 0.125f) : 0.0f;
            l0 += p0 + p1;
            l1 += p2 + p3;
            pf[u][0] = h2u(__floats2half2_rn(p0, p1));
            pf[u][1] = h2u(__floats2half2_rn(p2, p3));
        }

        #pragma unroll
        for (int kk = 0; kk < 3; kk++) {
            uint32_t af[4] = {pf[2 * kk][0], pf[2 * kk][1], pf[2 * kk + 1][0], pf[2 * kk + 1][1]};
            const uint32_t row = (uint32_t)rk0 + (uint32_t)kk * 16u + vrow_l;
            const uint32_t rm = (row & 7u) * 16u;
            #pragma unroll
            for (int g2 = 0; g2 < 4; g2++) {
                uint32_t vf[4];
                LDSM4T(vf, Vb + row * 128u + (((uint32_t)g2 * 32u + vcol_l) ^ rm));
                MMA16816H(o[2 * g2],     af, vf[0], vf[1]);
                MMA16816H(o[2 * g2 + 1], af, vf[2], vf[3]);
            }
        }
    }

    l0 += __shfl_xor_sync(0xffffffffu, l0, 1);
    l0 += __shfl_xor_sync(0xffffffffu, l0, 2);
    l1 += __shfl_xor_sync(0xffffffffu, l1, 1);
    l1 += __shfl_xor_sync(0xffffffffu, l1, 2);
    const float r0 = 1.0f / l0, r1 = 1.0f / l1;
    __half2* d0 = reinterpret_cast<__half2*>(
        g_ctx + (size_t)(b * T_DIM + i0) * E_DIM + h * D_DIM);
    __half2* d1 = reinterpret_cast<__half2*>(
        g_ctx + (size_t)(b * T_DIM + i1) * E_DIM + h * D_DIM);
    #pragma unroll
    for (int u = 0; u < 8; u++) {
        d0[4 * u + tq] = __floats2half2_rn(o[u][0] * r0, o[u][1] * r0);
        d1[4 * u + tq] = __floats2half2_rn(o[u][2] * r1, o[u][3] * r1);
    }
}

// ============================== launch ====================================
extern "C" void kernel_launch(void* const* d_in, const int* in_sizes, int n_in,
                              void* d_out, int out_size) {
    const float* x     = (const float*)d_in[0];
    const float* gamma = (const float*)d_in[2];
    const float* beta  = (const float*)d_in[3];
    const float* w_in  = (const float*)d_in[4];
    const float* b_in  = (const float*)d_in[5];
    const float* w_out = (const float*)d_in[6];
    const float* b_out = (const float*)d_in[7];
    float* out = (float*)d_out;

    __half *xn, *qkvh, *ctx, *win_hi, *wout_hi;
    cudaGetSymbolAddress((void**)&xn,      g_xn);
    cudaGetSymbolAddress((void**)&qkvh,    g_qkv);
    cudaGetSymbolAddress((void**)&ctx,     g_ctx);
    cudaGetSymbolAddress((void**)&win_hi,  g_win_hi);
    cudaGetSymbolAddress((void**)&wout_hi, g_wout_hi);

    cudaFuncSetAttribute((void*)gemm_mma<__half>,
                         cudaFuncAttributeMaxDynamicSharedMemorySize, SMEM_GEMM);
    cudaFuncSetAttribute((void*)gemm_mma<float>,
                         cudaFuncAttributeMaxDynamicSharedMemorySize, SMEM_GEMM);
    cudaFuncSetAttribute(attn_mma, cudaFuncAttributeMaxDynamicSharedMemorySize, ATTN_SMEM);

    ln_kernel<<<ROWS, 128>>>(x, gamma, beta);
    conv_h<<<(QKV_W * E_DIM / 4 + 255) / 256, 256>>>(w_in, win_hi, QKV_W * E_DIM / 4);
    conv_h<<<(E_DIM * E_DIM / 4 + 255) / 256, 256>>>(w_out, wout_hi, E_DIM * E_DIM / 4);
    gemm_mma<__half><<<dim3(QKV_W / 128, ROWS / 128), 256, SMEM_GEMM>>>(
        xn, win_hi, b_in, qkvh, QKV_W);
    attn_mma<<<dim3(T_DIM / 128, H_DIM, B_DIM), 256, ATTN_SMEM>>>(qkvh);
    gemm_mma<float><<<dim3(E_DIM / 128, ROWS / 128), 256, SMEM_GEMM>>>(
        ctx, wout_hi, b_out, out, E_DIM);
}

// round 12
// speedup vs baseline: 3.9862x; 1.0697x over previous
#include <cuda_runtime.h>
#include <cuda_fp16.h>
#include <math.h>
#include <stdint.h>

#define E_DIM 512
#define T_DIM 1024
#define B_DIM 8
#define H_DIM 8
#define D_DIM 64
#define WIN   128
#define ROWS  (B_DIM * T_DIM)   // 8192
#define QKV_W (3 * E_DIM)       // 1536
#define K_DIM 512
#define KC    64
#define NCHUNK (K_DIM / KC)               // 8
#define TILE_BYTES (128 * 128)            // 16 KB
#define SMEM_GEMM (96 * 1024)

// -------------------- scratch (__device__ globals) -------------------------
__device__ __half g_xn  [ROWS * E_DIM];
__device__ __half g_qkv [ROWS * QKV_W];
__device__ __half g_ctx [ROWS * E_DIM];
__device__ __half g_win_hi[QKV_W * E_DIM];
__device__ __half g_wout_hi[E_DIM * E_DIM];

// ============================ helpers ======================================
__device__ __forceinline__ uint32_t smem_u32(const void* p) {
    uint32_t a;
    asm("{ .reg .u64 t; cvta.to.shared.u64 t, %1; cvt.u32.u64 %0, t; }" : "=r"(a) : "l"(p));
    return a;
}
__device__ __forceinline__ void cp16(uint32_t dst, const void* src) {
    asm volatile("cp.async.cg.shared.global [%0], [%1], 16;" :: "r"(dst), "l"(src));
}
#define CP_COMMIT() asm volatile("cp.async.commit_group;" ::: "memory")
#define CP_WAIT2()  asm volatile("cp.async.wait_group 2;" ::: "memory")
#define CP_WAIT1()  asm volatile("cp.async.wait_group 1;" ::: "memory")
#define CP_WAIT0()  asm volatile("cp.async.wait_group 0;" ::: "memory")

#define LDSM4(R, addr)                                                          \
    asm volatile("ldmatrix.sync.aligned.m8n8.x4.shared.b16 {%0,%1,%2,%3}, [%4];" \
        : "=r"((R)[0]), "=r"((R)[1]), "=r"((R)[2]), "=r"((R)[3]) : "r"(addr))

#define LDSM4T(R, addr)                                                         \
    asm volatile("ldmatrix.sync.aligned.m8n8.x4.trans.shared.b16 {%0,%1,%2,%3}, [%4];" \
        : "=r"((R)[0]), "=r"((R)[1]), "=r"((R)[2]), "=r"((R)[3]) : "r"(addr))

#define MMA16816H(D, A, B0, B1)                                                 \
    asm volatile("mma.sync.aligned.m16n8k16.row.col.f32.f16.f16.f32 "           \
        "{%0,%1,%2,%3},{%4,%5,%6,%7},{%8,%9},{%0,%1,%2,%3};"                    \
        : "+f"((D)[0]), "+f"((D)[1]), "+f"((D)[2]), "+f"((D)[3])                \
        : "r"((A)[0]), "r"((A)[1]), "r"((A)[2]), "r"((A)[3]), "r"(B0), "r"(B1))

__device__ __forceinline__ uint32_t swz(uint32_t off) {
    return off ^ ((off >> 3) & 0x70u);
}
__device__ __forceinline__ uint32_t h2u(__half2 v) { return *reinterpret_cast<uint32_t*>(&v); }

__device__ __forceinline__ void st_pair(float* p, float a, float b) {
    *reinterpret_cast<float2*>(p) = make_float2(a, b);
}
__device__ __forceinline__ void st_pair(__half* p, float a, float b) {
    *reinterpret_cast<__half2*>(p) = __floats2half2_rn(a, b);
}

// ======================= LayerNorm -> fp16 =================================
__global__ __launch_bounds__(128) void ln_kernel(const float* __restrict__ x,
                                                 const float* __restrict__ gamma,
                                                 const float* __restrict__ beta) {
    const int row = blockIdx.x;
    const int tid = threadIdx.x;
    const float4 v = reinterpret_cast<const float4*>(x + (size_t)row * E_DIM)[tid];
    float s  = v.x + v.y + v.z + v.w;
    float ss = v.x * v.x + v.y * v.y + v.z * v.z + v.w * v.w;
    #pragma unroll
    for (int o = 16; o > 0; o >>= 1) {
        s  += __shfl_down_sync(0xffffffffu, s,  o);
        ss += __shfl_down_sync(0xffffffffu, ss, o);
    }
    __shared__ float sh_s[4], sh_ss[4], sh_mu, sh_rstd;
    const int w = tid >> 5, lane = tid & 31;
    if (lane == 0) { sh_s[w] = s; sh_ss[w] = ss; }
    __syncthreads();
    if (tid == 0) {
        float ts  = sh_s[0] + sh_s[1] + sh_s[2] + sh_s[3];
        float tss = sh_ss[0] + sh_ss[1] + sh_ss[2] + sh_ss[3];
        float mu  = ts * (1.0f / E_DIM);
        float var = tss * (1.0f / E_DIM) - mu * mu;
        sh_mu = mu; sh_rstd = rsqrtf(var + 1e-5f);
    }
    __syncthreads();
    const float mu = sh_mu, rstd = sh_rstd;
    const float4 g  = reinterpret_cast<const float4*>(gamma)[tid];
    const float4 be = reinterpret_cast<const float4*>(beta)[tid];
    float2 a, b;
    a.x = (v.x - mu) * rstd * g.x + be.x;
    a.y = (v.y - mu) * rstd * g.y + be.y;
    b.x = (v.z - mu) * rstd * g.z + be.z;
    b.y = (v.w - mu) * rstd * g.w + be.w;
    __half2* o = reinterpret_cast<__half2*>(g_xn + (size_t)row * E_DIM);
    o[2 * tid + 0] = __float22half2_rn(a);
    o[2 * tid + 1] = __float22half2_rn(b);
}

// ============= weight fp32 -> fp16 (both weight matrices, one launch) ======
__global__ __launch_bounds__(256) void conv_both(const float* __restrict__ w_in,
                                                 __half* __restrict__ win_hi,
                                                 const float* __restrict__ w_out,
                                                 __half* __restrict__ wout_hi,
                                                 int n4_in, int n4_tot) {
    const int i = blockIdx.x * 256 + threadIdx.x;
    if (i >= n4_tot) return;
    const float* src; __half* dst; int k;
    if (i < n4_in) { src = w_in;  dst = win_hi;  k = i; }
    else           { src = w_out; dst = wout_hi; k = i - n4_in; }
    const float4 v = reinterpret_cast<const float4*>(src)[k];
    __half2* oh = reinterpret_cast<__half2*>(dst);
    oh[2 * k + 0] = __floats2half2_rn(v.x, v.y);
    oh[2 * k + 1] = __floats2half2_rn(v.z, v.w);
}

// ===================== fp16 GEMM via mma.sync (1-term) =====================
// C[m,n] = bias[n] + sum_k A[m,k]*Wh[n,k]. CTA 128x128, 8 warps 2(M)x4(N),
// warp 64x32, 3-stage cp.async, SINGLE sync per chunk:
//   sync; issue load(c+2) into stage freed last iteration; wait; compute.
template <typename OT>
__global__ __launch_bounds__(256, 2)
void gemm_mma(const __half* __restrict__ A, const __half* __restrict__ Wh,
              const float* __restrict__ bias, OT* __restrict__ C, const int N) {
    constexpr uint32_t WH_OFF = TILE_BYTES;
    constexpr uint32_t STAGE  = 2 * TILE_BYTES;
    constexpr int NST = 3;

    extern __shared__ char smem[];
    const uint32_t sbase = smem_u32(smem);
    const int tid  = threadIdx.x;
    const int wid  = tid >> 5;
    const int lane = tid & 31;
    const int bn = blockIdx.x * 128;
    const int bm = blockIdx.y * 128;

    const int lrow  = tid >> 1;
    const int lhalf = tid & 1;
    const __half* aS  = A  + (size_t)(bm + lrow) * K_DIM + lhalf * 32;
    const __half* wHS = Wh + (size_t)(bn + lrow) * K_DIM + lhalf * 32;
    uint32_t st_off[4];
    #pragma unroll
    for (int v = 0; v < 4; v++) {
        const uint32_t off = (uint32_t)lrow * 128u + (uint32_t)lhalf * 64u + (uint32_t)v * 16u;
        st_off[v] = swz(off);
    }

    auto load_stage = [&](int s, int c) {
        const uint32_t st = sbase + (uint32_t)s * STAGE;
        const int kc = c * KC;
        #pragma unroll
        for (int v = 0; v < 4; v++) {
            cp16(st + st_off[v],          aS  + kc + v * 8);
            cp16(st + WH_OFF + st_off[v], wHS + kc + v * 8);
        }
        CP_COMMIT();
    };

    const int wm = (wid & 1) * 64;
    const int wn = (wid >> 1) * 32;
    uint32_t a_rowoff[4], a_mask[4];
    #pragma unroll
    for (int mi = 0; mi < 4; mi++) {
        const uint32_t r = (uint32_t)(wm + mi * 16 + (lane & 15));
        a_rowoff[mi] = r * 128u;
        a_mask[mi]   = (a_rowoff[mi] >> 3) & 0x70u;
    }
    const uint32_t a_kb = ((uint32_t)lane >> 4) * 16u;
    const int b_lrow = (lane & 7) + ((lane >> 4) << 3);
    uint32_t b_rowoff[2], b_mask[2];
    #pragma unroll
    for (int np = 0; np < 2; np++) {
        const uint32_t r = (uint32_t)(wn + np * 16 + b_lrow);
        b_rowoff[np] = r * 128u;
        b_mask[np]   = (b_rowoff[np] >> 3) & 0x70u;
    }
    const uint32_t b_kb = (((uint32_t)lane >> 3) & 1u) * 16u;

    float acc[4][4][4];
    #pragma unroll
    for (int mi = 0; mi < 4; mi++)
        #pragma unroll
        for (int ni = 0; ni < 4; ni++)
            #pragma unroll
            for (int r = 0; r < 4; r++) acc[mi][ni][r] = 0.0f;

    // prologue: chunks 0,1 into stages 0,1
    load_stage(0, 0);
    load_stage(1, 1);

    for (int c = 0; c < NCHUNK; c++) {
        const int s = c % NST;
        const uint32_t st = sbase + (uint32_t)s * STAGE;

        // all warps finished reading stage (c+2)%NST == (c-1)%NST last iter
        __syncthreads();
        if (c + 2 < NCHUNK) load_stage((c + 2) % NST, c + 2);

        // need chunk c landed; pending groups after it: c+1, c+2 (if issued)
        if (c + 2 < NCHUNK)      CP_WAIT2();
        else if (c + 1 < NCHUNK) CP_WAIT1();
        else                     CP_WAIT0();

        #pragma unroll
        for (int ks = 0; ks < 4; ks++) {
            const uint32_t akb = (uint32_t)ks * 32u + a_kb;
            const uint32_t bkb = (uint32_t)ks * 32u + b_kb;
            uint32_t ar[4][4], bh[2][4];
            #pragma unroll
            for (int mi = 0; mi < 4; mi++)
                LDSM4(ar[mi], st + a_rowoff[mi] + (akb ^ a_mask[mi]));
            #pragma unroll
            for (int np = 0; np < 2; np++)
                LDSM4(bh[np], st + WH_OFF + b_rowoff[np] + (bkb ^ b_mask[np]));
            #pragma unroll
            for (int mi = 0; mi < 4; mi++)
                #pragma unroll
                for (int ni = 0; ni < 4; ni++) {
                    const int np = ni >> 1, po = (ni & 1) * 2;
                    MMA16816H(acc[mi][ni], ar[mi], bh[np][po], bh[np][po + 1]);
                }
        }
    }

    const int gid = lane >> 2;
    const int tig = lane & 3;
    #pragma unroll
    for (int mi = 0; mi < 4; mi++) {
        const int row0 = bm + wm + mi * 16 + gid;
        OT* C0 = C + (size_t)row0 * N;
        OT* C1 = C + (size_t)(row0 + 8) * N;
        #pragma unroll
        for (int ni = 0; ni < 4; ni++) {
            const int col = bn + wn + ni * 8 + tig * 2;
            const float b0 = bias[col], b1 = bias[col + 1];
            st_pair(C0 + col, acc[mi][ni][0] + b0, acc[mi][ni][1] + b1);
            st_pair(C1 + col, acc[mi][ni][2] + b0, acc[mi][ni][3] + b1);
        }
    }
}

// ================ Tensor-core windowed causal attention (R9) ===============
#define ATTN_SMEM (16384 + 32768 + 32768)

__global__ __launch_bounds__(256) void attn_mma(const __half* __restrict__ qkv) {
    extern __shared__ char sm[];
    const uint32_t sbase = smem_u32(sm);
    const uint32_t Qb = sbase, Kb = sbase + 16384u, Vb = sbase + 49152u;
    char* Kp = sm + 16384; char* Vp = sm + 49152;
    const int qt  = blockIdx.x * 128;
    const int h   = blockIdx.y;
    const int b   = blockIdx.z;
    const int tid = threadIdx.x;
    const int wid = tid >> 5;
    const int lane = tid & 31;

    if (tid < 128) {
        const __half* src = qkv + (size_t)(b * T_DIM + qt + tid) * QKV_W + h * D_DIM;
        const uint32_t rmask = (uint32_t)(tid & 7) * 16u;
        #pragma unroll
        for (int c = 0; c < 8; c++)
            cp16(Qb + (uint32_t)tid * 128u + (((uint32_t)c * 16u) ^ rmask), src + c * 8);
    }
    {
        const int j = qt - 128 + tid;
        const uint32_t rmask = (uint32_t)(tid & 7) * 16u;
        if (j >= 0) {
            const __half* ks = qkv + (size_t)(b * T_DIM + j) * QKV_W + E_DIM + h * D_DIM;
            const __half* vs = ks + E_DIM;
            #pragma unroll
            for (int c = 0; c < 8; c++) {
                const uint32_t so = (uint32_t)tid * 128u + (((uint32_t)c * 16u) ^ rmask);
                cp16(Kb + so, ks + c * 8);
                cp16(Vb + so, vs + c * 8);
            }
        } else {
            const uint4 z = make_uint4(0, 0, 0, 0);
            #pragma unroll
            for (int c = 0; c < 8; c++) {
                const uint32_t so = (uint32_t)tid * 128u + (((uint32_t)c * 16u) ^ rmask);
                *reinterpret_cast<uint4*>(Kp + so) = z;
                *reinterpret_cast<uint4*>(Vp + so) = z;
            }
        }
    }
    CP_COMMIT();
    CP_WAIT0();
    __syncthreads();

    uint32_t qf[4][4];
    {
        const uint32_t arow = (uint32_t)(wid * 16 + (lane & 15));
        const uint32_t amask = (arow & 7u) * 16u;
        const uint32_t acol = ((uint32_t)lane >> 4) * 16u;
        #pragma unroll
        for (int ki = 0; ki < 4; ki++)
            LDSM4(qf[ki], Qb + arow * 128u + (((uint32_t)ki * 32u + acol) ^ amask));
    }

    float o[8][4];
    #pragma unroll
    for (int u = 0; u < 8; u++)
        #pragma unroll
        for (int r = 0; r < 4; r++) o[u][r] = 0.0f;
    float l0 = 0.0f, l1 = 0.0f;
    const int i0 = qt + wid * 16 + (lane >> 2);
    const int i1 = i0 + 8;
    const int tq = lane & 3;
    const int wr0 = wid * 16;

    const uint32_t krow_l = (uint32_t)((lane & 7) + ((lane >> 4) << 3));
    const uint32_t kcol_l = (((uint32_t)lane >> 3) & 1u) * 16u;
    const uint32_t vrow_l = (uint32_t)((lane & 7) + (((lane >> 3) & 1) << 3));
    const uint32_t vcol_l = ((uint32_t)lane >> 4) * 16u;

    #pragma unroll
    for (int c = 0; c < 3; c++) {
        const int rk0 = wr0 + 48 * c;
        const int j0 = qt - 128 + rk0;

        float st[6][4];
        #pragma unroll
        for (int u = 0; u < 6; u++)
            #pragma unroll
            for (int r = 0; r < 4; r++) st[u][r] = 0.0f;

        #pragma unroll
        for (int ki = 0; ki < 4; ki++) {
            uint32_t kf[3][4];
            #pragma unroll
            for (int g2 = 0; g2 < 3; g2++) {
                const uint32_t row = (uint32_t)rk0 + (uint32_t)g2 * 16u + krow_l;
                LDSM4(kf[g2], Kb + row * 128u + (((uint32_t)ki * 32u + kcol_l) ^ ((row & 7u) * 16u)));
            }
            #pragma unroll
            for (int u = 0; u < 6; u++)
                MMA16816H(st[u], qf[ki], kf[u >> 1][(u & 1) * 2], kf[u >> 1][(u & 1) * 2 + 1]);
        }

        uint32_t pf[6][2];
        #pragma unroll
        for (int u = 0; u < 6; u++) {
            const int j = j0 + 8 * u + 2 * tq;
            const bool k0a = (j     <= i0) && (j     >= i0 - WIN) && (j     >= 0);
            const bool k0b = (j + 1 <= i0) && (j + 1 >= i0 - WIN) && (j + 1 >= 0);
            const bool k1a = (j     <= i1) && (j     >= i1 - WIN) && (j     >= 0);
            const bool k1b = (j + 1 <= i1) && (j + 1 >= i1 - WIN) && (j + 1 >= 0);
            const float p0 = k0a ? __expf(st[u][0] * 0.125f) : 0.0f;
            const float p1 = k0b ? __expf(st[u][1] * 0.125f) : 0.0f;
            const float p2 = k1a ? __expf(st[u][2] * 0.125f) : 0.0f;
            const float p3 = k1b ? __expf(st[u][3] * 0.125f) : 0.0f;
            l0 += p0 + p1;
            l1 += p2 + p3;
            pf[u][0] = h2u(__floats2half2_rn(p0, p1));
            pf[u][1] = h2u(__floats2half2_rn(p2, p3));
        }

        #pragma unroll
        for (int kk = 0; kk < 3; kk++) {
            uint32_t af[4] = {pf[2 * kk][0], pf[2 * kk][1], pf[2 * kk + 1][0], pf[2 * kk + 1][1]};
            const uint32_t row = (uint32_t)rk0 + (uint32_t)kk * 16u + vrow_l;
            const uint32_t rm = (row & 7u) * 16u;
            #pragma unroll
            for (int g2 = 0; g2 < 4; g2++) {
                uint32_t vf[4];
                LDSM4T(vf, Vb + row * 128u + (((uint32_t)g2 * 32u + vcol_l) ^ rm));
                MMA16816H(o[2 * g2],     af, vf[0], vf[1]);
                MMA16816H(o[2 * g2 + 1], af, vf[2], vf[3]);
            }
        }
    }

    l0 += __shfl_xor_sync(0xffffffffu, l0, 1);
    l0 += __shfl_xor_sync(0xffffffffu, l0, 2);
    l1 += __shfl_xor_sync(0xffffffffu, l1, 1);
    l1 += __shfl_xor_sync(0xffffffffu, l1, 2);
    const float r0 = 1.0f / l0, r1 = 1.0f / l1;
    __half2* d0 = reinterpret_cast<__half2*>(
        g_ctx + (size_t)(b * T_DIM + i0) * E_DIM + h * D_DIM);
    __half2* d1 = reinterpret_cast<__half2*>(
        g_ctx + (size_t)(b * T_DIM + i1) * E_DIM + h * D_DIM);
    #pragma unroll
    for (int u = 0; u < 8; u++) {
        d0[4 * u + tq] = __floats2half2_rn(o[u][0] * r0, o[u][1] * r0);
        d1[4 * u + tq] = __floats2half2_rn(o[u][2] * r1, o[u][3] * r1);
    }
}

// ============================== launch ====================================
extern "C" void kernel_launch(void* const* d_in, const int* in_sizes, int n_in,
                              void* d_out, int out_size) {
    const float* x     = (const float*)d_in[0];
    const float* gamma = (const float*)d_in[2];
    const float* beta  = (const float*)d_in[3];
    const float* w_in  = (const float*)d_in[4];
    const float* b_in  = (const float*)d_in[5];
    const float* w_out = (const float*)d_in[6];
    const float* b_out = (const float*)d_in[7];
    float* out = (float*)d_out;

    __half *xn, *qkvh, *ctx, *win_hi, *wout_hi;
    cudaGetSymbolAddress((void**)&xn,      g_xn);
    cudaGetSymbolAddress((void**)&qkvh,    g_qkv);
    cudaGetSymbolAddress((void**)&ctx,     g_ctx);
    cudaGetSymbolAddress((void**)&win_hi,  g_win_hi);
    cudaGetSymbolAddress((void**)&wout_hi, g_wout_hi);

    cudaFuncSetAttribute((void*)gemm_mma<__half>,
                         cudaFuncAttributeMaxDynamicSharedMemorySize, SMEM_GEMM);
    cudaFuncSetAttribute((void*)gemm_mma<float>,
                         cudaFuncAttributeMaxDynamicSharedMemorySize, SMEM_GEMM);
    cudaFuncSetAttribute(attn_mma, cudaFuncAttributeMaxDynamicSharedMemorySize, ATTN_SMEM);

    const int n4_in  = QKV_W * E_DIM / 4;
    const int n4_out = E_DIM * E_DIM / 4;

    ln_kernel<<<ROWS, 128>>>(x, gamma, beta);
    conv_both<<<(n4_in + n4_out + 255) / 256, 256>>>(w_in, win_hi, w_out, wout_hi,
                                                     n4_in, n4_in + n4_out);
    gemm_mma<__half><<<dim3(QKV_W / 128, ROWS / 128), 256, SMEM_GEMM>>>(
        xn, win_hi, b_in, qkvh, QKV_W);
    attn_mma<<<dim3(T_DIM / 128, H_DIM, B_DIM), 256, ATTN_SMEM>>>(qkvh);
    gemm_mma<float><<<dim3(E_DIM / 128, ROWS / 128), 256, SMEM_GEMM>>>(
        ctx, wout_hi, b_out, out, E_DIM);
}

// round 13
// speedup vs baseline: 4.0504x; 1.0161x over previous
#include <cuda_runtime.h>
#include <cuda_fp16.h>
#include <math.h>
#include <stdint.h>

#define E_DIM 512
#define T_DIM 1024
#define B_DIM 8
#define H_DIM 8
#define D_DIM 64
#define WIN   128
#define ROWS  (B_DIM * T_DIM)   // 8192
#define QKV_W (3 * E_DIM)       // 1536
#define K_DIM 512
#define KC    64
#define NCHUNK (K_DIM / KC)               // 8
#define TILE_BYTES (128 * 128)            // 16 KB
#define SMEM_GEMM (96 * 1024)

// -------------------- scratch (__device__ globals) -------------------------
__device__ __half g_xn  [ROWS * E_DIM];
__device__ __half g_qkv [ROWS * QKV_W];
__device__ __half g_ctx [ROWS * E_DIM];
__device__ __half g_win_hi[QKV_W * E_DIM];
__device__ __half g_wout_hi[E_DIM * E_DIM];

// ============================ helpers ======================================
__device__ __forceinline__ uint32_t smem_u32(const void* p) {
    uint32_t a;
    asm("{ .reg .u64 t; cvta.to.shared.u64 t, %1; cvt.u32.u64 %0, t; }" : "=r"(a) : "l"(p));
    return a;
}
__device__ __forceinline__ void cp16(uint32_t dst, const void* src) {
    asm volatile("cp.async.cg.shared.global [%0], [%1], 16;" :: "r"(dst), "l"(src));
}
#define CP_COMMIT() asm volatile("cp.async.commit_group;" ::: "memory")
#define CP_WAIT2()  asm volatile("cp.async.wait_group 2;" ::: "memory")
#define CP_WAIT1()  asm volatile("cp.async.wait_group 1;" ::: "memory")
#define CP_WAIT0()  asm volatile("cp.async.wait_group 0;" ::: "memory")

#define LDSM4(R, addr)                                                          \
    asm volatile("ldmatrix.sync.aligned.m8n8.x4.shared.b16 {%0,%1,%2,%3}, [%4];" \
        : "=r"((R)[0]), "=r"((R)[1]), "=r"((R)[2]), "=r"((R)[3]) : "r"(addr))

#define LDSM4T(R, addr)                                                         \
    asm volatile("ldmatrix.sync.aligned.m8n8.x4.trans.shared.b16 {%0,%1,%2,%3}, [%4];" \
        : "=r"((R)[0]), "=r"((R)[1]), "=r"((R)[2]), "=r"((R)[3]) : "r"(addr))

#define MMA16816H(D, A, B0, B1)                                                 \
    asm volatile("mma.sync.aligned.m16n8k16.row.col.f32.f16.f16.f32 "           \
        "{%0,%1,%2,%3},{%4,%5,%6,%7},{%8,%9},{%0,%1,%2,%3};"                    \
        : "+f"((D)[0]), "+f"((D)[1]), "+f"((D)[2]), "+f"((D)[3])                \
        : "r"((A)[0]), "r"((A)[1]), "r"((A)[2]), "r"((A)[3]), "r"(B0), "r"(B1))

__device__ __forceinline__ uint32_t swz(uint32_t off) {
    return off ^ ((off >> 3) & 0x70u);
}
__device__ __forceinline__ uint32_t h2u(__half2 v) { return *reinterpret_cast<uint32_t*>(&v); }

__device__ __forceinline__ void st_pair(float* p, float a, float b) {
    *reinterpret_cast<float2*>(p) = make_float2(a, b);
}
__device__ __forceinline__ void st_pair(__half* p, float a, float b) {
    *reinterpret_cast<__half2*>(p) = __floats2half2_rn(a, b);
}

// ======================= LayerNorm -> fp16 =================================
__global__ __launch_bounds__(128) void ln_kernel(const float* __restrict__ x,
                                                 const float* __restrict__ gamma,
                                                 const float* __restrict__ beta) {
    const int row = blockIdx.x;
    const int tid = threadIdx.x;
    const float4 v = reinterpret_cast<const float4*>(x + (size_t)row * E_DIM)[tid];
    float s  = v.x + v.y + v.z + v.w;
    float ss = v.x * v.x + v.y * v.y + v.z * v.z + v.w * v.w;
    #pragma unroll
    for (int o = 16; o > 0; o >>= 1) {
        s  += __shfl_down_sync(0xffffffffu, s,  o);
        ss += __shfl_down_sync(0xffffffffu, ss, o);
    }
    __shared__ float sh_s[4], sh_ss[4], sh_mu, sh_rstd;
    const int w = tid >> 5, lane = tid & 31;
    if (lane == 0) { sh_s[w] = s; sh_ss[w] = ss; }
    __syncthreads();
    if (tid == 0) {
        float ts  = sh_s[0] + sh_s[1] + sh_s[2] + sh_s[3];
        float tss = sh_ss[0] + sh_ss[1] + sh_ss[2] + sh_ss[3];
        float mu  = ts * (1.0f / E_DIM);
        float var = tss * (1.0f / E_DIM) - mu * mu;
        sh_mu = mu; sh_rstd = rsqrtf(var + 1e-5f);
    }
    __syncthreads();
    const float mu = sh_mu, rstd = sh_rstd;
    const float4 g  = reinterpret_cast<const float4*>(gamma)[tid];
    const float4 be = reinterpret_cast<const float4*>(beta)[tid];
    float2 a, b;
    a.x = (v.x - mu) * rstd * g.x + be.x;
    a.y = (v.y - mu) * rstd * g.y + be.y;
    b.x = (v.z - mu) * rstd * g.z + be.z;
    b.y = (v.w - mu) * rstd * g.w + be.w;
    __half2* o = reinterpret_cast<__half2*>(g_xn + (size_t)row * E_DIM);
    o[2 * tid + 0] = __float22half2_rn(a);
    o[2 * tid + 1] = __float22half2_rn(b);
}

// ============= weight fp32 -> fp16 (both weight matrices, one launch) ======
__global__ __launch_bounds__(256) void conv_both(const float* __restrict__ w_in,
                                                 __half* __restrict__ win_hi,
                                                 const float* __restrict__ w_out,
                                                 __half* __restrict__ wout_hi,
                                                 int n4_in, int n4_tot) {
    const int i = blockIdx.x * 256 + threadIdx.x;
    if (i >= n4_tot) return;
    const float* src; __half* dst; int k;
    if (i < n4_in) { src = w_in;  dst = win_hi;  k = i; }
    else           { src = w_out; dst = wout_hi; k = i - n4_in; }
    const float4 v = reinterpret_cast<const float4*>(src)[k];
    __half2* oh = reinterpret_cast<__half2*>(dst);
    oh[2 * k + 0] = __floats2half2_rn(v.x, v.y);
    oh[2 * k + 1] = __floats2half2_rn(v.z, v.w);
}

// ===================== fp16 GEMM via mma.sync (1-term, R12) ================
template <typename OT>
__global__ __launch_bounds__(256, 2)
void gemm_mma(const __half* __restrict__ A, const __half* __restrict__ Wh,
              const float* __restrict__ bias, OT* __restrict__ C, const int N) {
    constexpr uint32_t WH_OFF = TILE_BYTES;
    constexpr uint32_t STAGE  = 2 * TILE_BYTES;
    constexpr int NST = 3;

    extern __shared__ char smem[];
    const uint32_t sbase = smem_u32(smem);
    const int tid  = threadIdx.x;
    const int wid  = tid >> 5;
    const int lane = tid & 31;
    const int bn = blockIdx.x * 128;
    const int bm = blockIdx.y * 128;

    const int lrow  = tid >> 1;
    const int lhalf = tid & 1;
    const __half* aS  = A  + (size_t)(bm + lrow) * K_DIM + lhalf * 32;
    const __half* wHS = Wh + (size_t)(bn + lrow) * K_DIM + lhalf * 32;
    uint32_t st_off[4];
    #pragma unroll
    for (int v = 0; v < 4; v++) {
        const uint32_t off = (uint32_t)lrow * 128u + (uint32_t)lhalf * 64u + (uint32_t)v * 16u;
        st_off[v] = swz(off);
    }

    auto load_stage = [&](int s, int c) {
        const uint32_t st = sbase + (uint32_t)s * STAGE;
        const int kc = c * KC;
        #pragma unroll
        for (int v = 0; v < 4; v++) {
            cp16(st + st_off[v],          aS  + kc + v * 8);
            cp16(st + WH_OFF + st_off[v], wHS + kc + v * 8);
        }
        CP_COMMIT();
    };

    const int wm = (wid & 1) * 64;
    const int wn = (wid >> 1) * 32;
    uint32_t a_rowoff[4], a_mask[4];
    #pragma unroll
    for (int mi = 0; mi < 4; mi++) {
        const uint32_t r = (uint32_t)(wm + mi * 16 + (lane & 15));
        a_rowoff[mi] = r * 128u;
        a_mask[mi]   = (a_rowoff[mi] >> 3) & 0x70u;
    }
    const uint32_t a_kb = ((uint32_t)lane >> 4) * 16u;
    const int b_lrow = (lane & 7) + ((lane >> 4) << 3);
    uint32_t b_rowoff[2], b_mask[2];
    #pragma unroll
    for (int np = 0; np < 2; np++) {
        const uint32_t r = (uint32_t)(wn + np * 16 + b_lrow);
        b_rowoff[np] = r * 128u;
        b_mask[np]   = (b_rowoff[np] >> 3) & 0x70u;
    }
    const uint32_t b_kb = (((uint32_t)lane >> 3) & 1u) * 16u;

    float acc[4][4][4];
    #pragma unroll
    for (int mi = 0; mi < 4; mi++)
        #pragma unroll
        for (int ni = 0; ni < 4; ni++)
            #pragma unroll
            for (int r = 0; r < 4; r++) acc[mi][ni][r] = 0.0f;

    load_stage(0, 0);
    load_stage(1, 1);

    for (int c = 0; c < NCHUNK; c++) {
        const int s = c % NST;
        const uint32_t st = sbase + (uint32_t)s * STAGE;

        __syncthreads();
        if (c + 2 < NCHUNK) load_stage((c + 2) % NST, c + 2);

        if (c + 2 < NCHUNK)      CP_WAIT2();
        else if (c + 1 < NCHUNK) CP_WAIT1();
        else                     CP_WAIT0();

        #pragma unroll
        for (int ks = 0; ks < 4; ks++) {
            const uint32_t akb = (uint32_t)ks * 32u + a_kb;
            const uint32_t bkb = (uint32_t)ks * 32u + b_kb;
            uint32_t ar[4][4], bh[2][4];
            #pragma unroll
            for (int mi = 0; mi < 4; mi++)
                LDSM4(ar[mi], st + a_rowoff[mi] + (akb ^ a_mask[mi]));
            #pragma unroll
            for (int np = 0; np < 2; np++)
                LDSM4(bh[np], st + WH_OFF + b_rowoff[np] + (bkb ^ b_mask[np]));
            #pragma unroll
            for (int mi = 0; mi < 4; mi++)
                #pragma unroll
                for (int ni = 0; ni < 4; ni++) {
                    const int np = ni >> 1, po = (ni & 1) * 2;
                    MMA16816H(acc[mi][ni], ar[mi], bh[np][po], bh[np][po + 1]);
                }
        }
    }

    const int gid = lane >> 2;
    const int tig = lane & 3;
    #pragma unroll
    for (int mi = 0; mi < 4; mi++) {
        const int row0 = bm + wm + mi * 16 + gid;
        OT* C0 = C + (size_t)row0 * N;
        OT* C1 = C + (size_t)(row0 + 8) * N;
        #pragma unroll
        for (int ni = 0; ni < 4; ni++) {
            const int col = bn + wn + ni * 8 + tig * 2;
            const float b0 = bias[col], b1 = bias[col + 1];
            st_pair(C0 + col, acc[mi][ni][0] + b0, acc[mi][ni][1] + b1);
            st_pair(C1 + col, acc[mi][ni][2] + b0, acc[mi][ni][3] + b1);
        }
    }
}

// ================ Tensor-core windowed causal attention ====================
// CTA = (b, h, 64 queries), 128 threads / 4 warps; warp w owns queries
// [qt+16w, qt+16w+16) and keys rows [16w, 16w+144) of the 192-row K/V tiles
// (row r <-> key index qt-128+r). Q 8KB + K 24KB + V 24KB = 56KB smem ->
// 3 CTAs/SM (reg-limited), vs 1 CTA/SM for the 256-thread version.
#define AQ_ROWS 64
#define AK_ROWS 192
#define ATTN_SMEM (AQ_ROWS * 128 + 2 * AK_ROWS * 128)   // 57344 B

__global__ __launch_bounds__(128) void attn_mma(const __half* __restrict__ qkv) {
    extern __shared__ char sm[];
    const uint32_t sbase = smem_u32(sm);
    const uint32_t Qb = sbase;
    const uint32_t Kb = sbase + AQ_ROWS * 128u;
    const uint32_t Vb = Kb + AK_ROWS * 128u;
    char* Kp = sm + AQ_ROWS * 128;
    char* Vp = Kp + AK_ROWS * 128;
    const int qt  = blockIdx.x * AQ_ROWS;
    const int h   = blockIdx.y;
    const int b   = blockIdx.z;
    const int tid = threadIdx.x;
    const int wid = tid >> 5;
    const int lane = tid & 31;

    // ---- Q rows (threads 0..63) ----
    if (tid < AQ_ROWS) {
        const __half* src = qkv + (size_t)(b * T_DIM + qt + tid) * QKV_W + h * D_DIM;
        const uint32_t rmask = (uint32_t)(tid & 7) * 16u;
        #pragma unroll
        for (int c = 0; c < 8; c++)
            cp16(Qb + (uint32_t)tid * 128u + (((uint32_t)c * 16u) ^ rmask), src + c * 8);
    }
    // ---- K,V rows: thread t loads row t; threads 0..63 also row 128+t ----
    #pragma unroll
    for (int rep = 0; rep < 2; rep++) {
        const int row = tid + rep * 128;
        if (row >= AK_ROWS) break;
        const int j = qt - 128 + row;
        const uint32_t rmask = (uint32_t)(row & 7) * 16u;
        if (j >= 0) {
            const __half* ks = qkv + (size_t)(b * T_DIM + j) * QKV_W + E_DIM + h * D_DIM;
            const __half* vs = ks + E_DIM;
            #pragma unroll
            for (int c = 0; c < 8; c++) {
                const uint32_t so = (uint32_t)row * 128u + (((uint32_t)c * 16u) ^ rmask);
                cp16(Kb + so, ks + c * 8);
                cp16(Vb + so, vs + c * 8);
            }
        } else {
            const uint4 z = make_uint4(0, 0, 0, 0);
            #pragma unroll
            for (int c = 0; c < 8; c++) {
                const uint32_t so = (uint32_t)row * 128u + (((uint32_t)c * 16u) ^ rmask);
                *reinterpret_cast<uint4*>(Kp + so) = z;
                *reinterpret_cast<uint4*>(Vp + so) = z;
            }
        }
    }
    CP_COMMIT();
    CP_WAIT0();
    __syncthreads();

    // ---- Q fragments (persistent) ----
    uint32_t qf[4][4];
    {
        const uint32_t arow = (uint32_t)(wid * 16 + (lane & 15));
        const uint32_t amask = (arow & 7u) * 16u;
        const uint32_t acol = ((uint32_t)lane >> 4) * 16u;
        #pragma unroll
        for (int ki = 0; ki < 4; ki++)
            LDSM4(qf[ki], Qb + arow * 128u + (((uint32_t)ki * 32u + acol) ^ amask));
    }

    float o[8][4];
    #pragma unroll
    for (int u = 0; u < 8; u++)
        #pragma unroll
        for (int r = 0; r < 4; r++) o[u][r] = 0.0f;
    float l0 = 0.0f, l1 = 0.0f;
    const int i0 = qt + wid * 16 + (lane >> 2);
    const int i1 = i0 + 8;
    const int tq = lane & 3;
    const int wr0 = wid * 16;

    const uint32_t krow_l = (uint32_t)((lane & 7) + ((lane >> 4) << 3));
    const uint32_t kcol_l = (((uint32_t)lane >> 3) & 1u) * 16u;
    const uint32_t vrow_l = (uint32_t)((lane & 7) + (((lane >> 3) & 1) << 3));
    const uint32_t vcol_l = ((uint32_t)lane >> 4) * 16u;

    #pragma unroll
    for (int c = 0; c < 3; c++) {
        const int rk0 = wr0 + 48 * c;
        const int j0 = qt - 128 + rk0;

        float st[6][4];
        #pragma unroll
        for (int u = 0; u < 6; u++)
            #pragma unroll
            for (int r = 0; r < 4; r++) st[u][r] = 0.0f;

        #pragma unroll
        for (int ki = 0; ki < 4; ki++) {
            uint32_t kf[3][4];
            #pragma unroll
            for (int g2 = 0; g2 < 3; g2++) {
                const uint32_t row = (uint32_t)rk0 + (uint32_t)g2 * 16u + krow_l;
                LDSM4(kf[g2], Kb + row * 128u + (((uint32_t)ki * 32u + kcol_l) ^ ((row & 7u) * 16u)));
            }
            #pragma unroll
            for (int u = 0; u < 6; u++)
                MMA16816H(st[u], qf[ki], kf[u >> 1][(u & 1) * 2], kf[u >> 1][(u & 1) * 2 + 1]);
        }

        uint32_t pf[6][2];
        #pragma unroll
        for (int u = 0; u < 6; u++) {
            const int j = j0 + 8 * u + 2 * tq;
            const bool k0a = (j     <= i0) && (j     >= i0 - WIN) && (j     >= 0);
            const bool k0b = (j + 1 <= i0) && (j + 1 >= i0 - WIN) && (j + 1 >= 0);
            const bool k1a = (j     <= i1) && (j     >= i1 - WIN) && (j     >= 0);
            const bool k1b = (j + 1 <= i1) && (j + 1 >= i1 - WIN) && (j + 1 >= 0);
            const float p0 = k0a ? __expf(st[u][0] * 0.125f) : 0.0f;
            const float p1 = k0b ? __expf(st[u][1] * 0.125f) : 0.0f;
            const float p2 = k1a ? __expf(st[u][2] * 0.125f) : 0.0f;
            const float p3 = k1b ? __expf(st[u][3] * 0.125f) : 0.0f;
            l0 += p0 + p1;
            l1 += p2 + p3;
            pf[u][0] = h2u(__floats2half2_rn(p0, p1));
            pf[u][1] = h2u(__floats2half2_rn(p2, p3));
        }

        #pragma unroll
        for (int kk = 0; kk < 3; kk++) {
            uint32_t af[4] = {pf[2 * kk][0], pf[2 * kk][1], pf[2 * kk + 1][0], pf[2 * kk + 1][1]};
            const uint32_t row = (uint32_t)rk0 + (uint32_t)kk * 16u + vrow_l;
            const uint32_t rm = (row & 7u) * 16u;
            #pragma unroll
            for (int g2 = 0; g2 < 4; g2++) {
                uint32_t vf[4];
                LDSM4T(vf, Vb + row * 128u + (((uint32_t)g2 * 32u + vcol_l) ^ rm));
                MMA16816H(o[2 * g2],     af, vf[0], vf[1]);
                MMA16816H(o[2 * g2 + 1], af, vf[2], vf[3]);
            }
        }
    }

    l0 += __shfl_xor_sync(0xffffffffu, l0, 1);
    l0 += __shfl_xor_sync(0xffffffffu, l0, 2);
    l1 += __shfl_xor_sync(0xffffffffu, l1, 1);
    l1 += __shfl_xor_sync(0xffffffffu, l1, 2);
    const float r0 = 1.0f / l0, r1 = 1.0f / l1;
    __half2* d0 = reinterpret_cast<__half2*>(
        g_ctx + (size_t)(b * T_DIM + i0) * E_DIM + h * D_DIM);
    __half2* d1 = reinterpret_cast<__half2*>(
        g_ctx + (size_t)(b * T_DIM + i1) * E_DIM + h * D_DIM);
    #pragma unroll
    for (int u = 0; u < 8; u++) {
        d0[4 * u + tq] = __floats2half2_rn(o[u][0] * r0, o[u][1] * r0);
        d1[4 * u + tq] = __floats2half2_rn(o[u][2] * r1, o[u][3] * r1);
    }
}

// ============================== launch ====================================
extern "C" void kernel_launch(void* const* d_in, const int* in_sizes, int n_in,
                              void* d_out, int out_size) {
    const float* x     = (const float*)d_in[0];
    const float* gamma = (const float*)d_in[2];
    const float* beta  = (const float*)d_in[3];
    const float* w_in  = (const float*)d_in[4];
    const float* b_in  = (const float*)d_in[5];
    const float* w_out = (const float*)d_in[6];
    const float* b_out = (const float*)d_in[7];
    float* out = (float*)d_out;

    __half *xn, *qkvh, *ctx, *win_hi, *wout_hi;
    cudaGetSymbolAddress((void**)&xn,      g_xn);
    cudaGetSymbolAddress((void**)&qkvh,    g_qkv);
    cudaGetSymbolAddress((void**)&ctx,     g_ctx);
    cudaGetSymbolAddress((void**)&win_hi,  g_win_hi);
    cudaGetSymbolAddress((void**)&wout_hi, g_wout_hi);

    cudaFuncSetAttribute((void*)gemm_mma<__half>,
                         cudaFuncAttributeMaxDynamicSharedMemorySize, SMEM_GEMM);
    cudaFuncSetAttribute((void*)gemm_mma<float>,
                         cudaFuncAttributeMaxDynamicSharedMemorySize, SMEM_GEMM);
    cudaFuncSetAttribute(attn_mma, cudaFuncAttributeMaxDynamicSharedMemorySize, ATTN_SMEM);

    const int n4_in  = QKV_W * E_DIM / 4;
    const int n4_out = E_DIM * E_DIM / 4;

    ln_kernel<<<ROWS, 128>>>(x, gamma, beta);
    conv_both<<<(n4_in + n4_out + 255) / 256, 256>>>(w_in, win_hi, w_out, wout_hi,
                                                     n4_in, n4_in + n4_out);
    gemm_mma<__half><<<dim3(QKV_W / 128, ROWS / 128), 256, SMEM_GEMM>>>(
        xn, win_hi, b_in, qkvh, QKV_W);
    attn_mma<<<dim3(T_DIM / AQ_ROWS, H_DIM, B_DIM), 128, ATTN_SMEM>>>(qkvh);
    gemm_mma<float><<<dim3(E_DIM / 128, ROWS / 128), 256, SMEM_GEMM>>>(
        ctx, wout_hi, b_out, out, E_DIM);
}

// round 14
// speedup vs baseline: 4.1413x; 1.0224x over previous
#include <cuda_runtime.h>
#include <cuda_fp16.h>
#include <math.h>
#include <stdint.h>

#define E_DIM 512
#define T_DIM 1024
#define B_DIM 8
#define H_DIM 8
#define D_DIM 64
#define WIN   128
#define ROWS  (B_DIM * T_DIM)   // 8192
#define QKV_W (3 * E_DIM)       // 1536
#define K_DIM 512
#define KC    64
#define NCHUNK (K_DIM / KC)               // 8
#define TILE_BYTES (128 * 128)            // 16 KB
#define SMEM_GEMM (96 * 1024)

// exp2 constant: 0.125 * log2(e)
#define EXP_C 0.18033688011112042f

// -------------------- scratch (__device__ globals) -------------------------
__device__ __half g_xn  [ROWS * E_DIM];
__device__ __half g_qkv [ROWS * QKV_W];
__device__ __half g_ctx [ROWS * E_DIM];
__device__ __half g_win_hi[QKV_W * E_DIM];
__device__ __half g_wout_hi[E_DIM * E_DIM];

// ============================ helpers ======================================
__device__ __forceinline__ uint32_t smem_u32(const void* p) {
    uint32_t a;
    asm("{ .reg .u64 t; cvta.to.shared.u64 t, %1; cvt.u32.u64 %0, t; }" : "=r"(a) : "l"(p));
    return a;
}
__device__ __forceinline__ void cp16(uint32_t dst, const void* src) {
    asm volatile("cp.async.cg.shared.global [%0], [%1], 16;" :: "r"(dst), "l"(src));
}
#define CP_COMMIT() asm volatile("cp.async.commit_group;" ::: "memory")
#define CP_WAIT2()  asm volatile("cp.async.wait_group 2;" ::: "memory")
#define CP_WAIT1()  asm volatile("cp.async.wait_group 1;" ::: "memory")
#define CP_WAIT0()  asm volatile("cp.async.wait_group 0;" ::: "memory")

#define LDSM4(R, addr)                                                          \
    asm volatile("ldmatrix.sync.aligned.m8n8.x4.shared.b16 {%0,%1,%2,%3}, [%4];" \
        : "=r"((R)[0]), "=r"((R)[1]), "=r"((R)[2]), "=r"((R)[3]) : "r"(addr))

#define LDSM4T(R, addr)                                                         \
    asm volatile("ldmatrix.sync.aligned.m8n8.x4.trans.shared.b16 {%0,%1,%2,%3}, [%4];" \
        : "=r"((R)[0]), "=r"((R)[1]), "=r"((R)[2]), "=r"((R)[3]) : "r"(addr))

#define MMA16816H(D, A, B0, B1)                                                 \
    asm volatile("mma.sync.aligned.m16n8k16.row.col.f32.f16.f16.f32 "           \
        "{%0,%1,%2,%3},{%4,%5,%6,%7},{%8,%9},{%0,%1,%2,%3};"                    \
        : "+f"((D)[0]), "+f"((D)[1]), "+f"((D)[2]), "+f"((D)[3])                \
        : "r"((A)[0]), "r"((A)[1]), "r"((A)[2]), "r"((A)[3]), "r"(B0), "r"(B1))

__device__ __forceinline__ uint32_t swz(uint32_t off) {
    return off ^ ((off >> 3) & 0x70u);
}
__device__ __forceinline__ uint32_t h2u(__half2 v) { return *reinterpret_cast<uint32_t*>(&v); }

__device__ __forceinline__ void st_pair(float* p, float a, float b) {
    *reinterpret_cast<float2*>(p) = make_float2(a, b);
}
__device__ __forceinline__ void st_pair(__half* p, float a, float b) {
    *reinterpret_cast<__half2*>(p) = __floats2half2_rn(a, b);
}

// ============ fused LayerNorm (blocks < ROWS) + weight conv (rest) =========
__global__ __launch_bounds__(128) void ln_conv_kernel(
    const float* __restrict__ x,
    const float* __restrict__ gamma,
    const float* __restrict__ beta,
    const float* __restrict__ w_in,
    const float* __restrict__ w_out,
    int n4_in, int n4_tot) {
    const int bid = blockIdx.x;
    const int tid = threadIdx.x;

    if (bid >= ROWS) {
        // ---- weight fp32 -> fp16 ----
        const int i = (bid - ROWS) * 128 + tid;
        if (i < n4_tot) {
            const float* src; __half* dst; int k;
            if (i < n4_in) { src = w_in;  dst = g_win_hi;  k = i; }
            else           { src = w_out; dst = g_wout_hi; k = i - n4_in; }
            const float4 v = reinterpret_cast<const float4*>(src)[k];
            __half2* oh = reinterpret_cast<__half2*>(dst);
            oh[2 * k + 0] = __floats2half2_rn(v.x, v.y);
            oh[2 * k + 1] = __floats2half2_rn(v.z, v.w);
        }
        return;
    }

    // ---- LayerNorm row -> fp16 ----
    const int row = bid;
    const float4 v = reinterpret_cast<const float4*>(x + (size_t)row * E_DIM)[tid];
    float s  = v.x + v.y + v.z + v.w;
    float ss = v.x * v.x + v.y * v.y + v.z * v.z + v.w * v.w;
    #pragma unroll
    for (int o = 16; o > 0; o >>= 1) {
        s  += __shfl_down_sync(0xffffffffu, s,  o);
        ss += __shfl_down_sync(0xffffffffu, ss, o);
    }
    __shared__ float sh_s[4], sh_ss[4], sh_mu, sh_rstd;
    const int w = tid >> 5, lane = tid & 31;
    if (lane == 0) { sh_s[w] = s; sh_ss[w] = ss; }
    __syncthreads();
    if (tid == 0) {
        float ts  = sh_s[0] + sh_s[1] + sh_s[2] + sh_s[3];
        float tss = sh_ss[0] + sh_ss[1] + sh_ss[2] + sh_ss[3];
        float mu  = ts * (1.0f / E_DIM);
        float var = tss * (1.0f / E_DIM) - mu * mu;
        sh_mu = mu; sh_rstd = rsqrtf(var + 1e-5f);
    }
    __syncthreads();
    const float mu = sh_mu, rstd = sh_rstd;
    const float4 g  = reinterpret_cast<const float4*>(gamma)[tid];
    const float4 be = reinterpret_cast<const float4*>(beta)[tid];
    float2 a, b;
    a.x = (v.x - mu) * rstd * g.x + be.x;
    a.y = (v.y - mu) * rstd * g.y + be.y;
    b.x = (v.z - mu) * rstd * g.z + be.z;
    b.y = (v.w - mu) * rstd * g.w + be.w;
    __half2* o = reinterpret_cast<__half2*>(g_xn + (size_t)row * E_DIM);
    o[2 * tid + 0] = __float22half2_rn(a);
    o[2 * tid + 1] = __float22half2_rn(b);
}

// ===================== fp16 GEMM via mma.sync (1-term, R12) ================
template <typename OT>
__global__ __launch_bounds__(256, 2)
void gemm_mma(const __half* __restrict__ A, const __half* __restrict__ Wh,
              const float* __restrict__ bias, OT* __restrict__ C, const int N) {
    constexpr uint32_t WH_OFF = TILE_BYTES;
    constexpr uint32_t STAGE  = 2 * TILE_BYTES;
    constexpr int NST = 3;

    extern __shared__ char smem[];
    const uint32_t sbase = smem_u32(smem);
    const int tid  = threadIdx.x;
    const int wid  = tid >> 5;
    const int lane = tid & 31;
    const int bn = blockIdx.x * 128;
    const int bm = blockIdx.y * 128;

    const int lrow  = tid >> 1;
    const int lhalf = tid & 1;
    const __half* aS  = A  + (size_t)(bm + lrow) * K_DIM + lhalf * 32;
    const __half* wHS = Wh + (size_t)(bn + lrow) * K_DIM + lhalf * 32;
    uint32_t st_off[4];
    #pragma unroll
    for (int v = 0; v < 4; v++) {
        const uint32_t off = (uint32_t)lrow * 128u + (uint32_t)lhalf * 64u + (uint32_t)v * 16u;
        st_off[v] = swz(off);
    }

    auto load_stage = [&](int s, int c) {
        const uint32_t st = sbase + (uint32_t)s * STAGE;
        const int kc = c * KC;
        #pragma unroll
        for (int v = 0; v < 4; v++) {
            cp16(st + st_off[v],          aS  + kc + v * 8);
            cp16(st + WH_OFF + st_off[v], wHS + kc + v * 8);
        }
        CP_COMMIT();
    };

    const int wm = (wid & 1) * 64;
    const int wn = (wid >> 1) * 32;
    uint32_t a_rowoff[4], a_mask[4];
    #pragma unroll
    for (int mi = 0; mi < 4; mi++) {
        const uint32_t r = (uint32_t)(wm + mi * 16 + (lane & 15));
        a_rowoff[mi] = r * 128u;
        a_mask[mi]   = (a_rowoff[mi] >> 3) & 0x70u;
    }
    const uint32_t a_kb = ((uint32_t)lane >> 4) * 16u;
    const int b_lrow = (lane & 7) + ((lane >> 4) << 3);
    uint32_t b_rowoff[2], b_mask[2];
    #pragma unroll
    for (int np = 0; np < 2; np++) {
        const uint32_t r = (uint32_t)(wn + np * 16 + b_lrow);
        b_rowoff[np] = r * 128u;
        b_mask[np]   = (b_rowoff[np] >> 3) & 0x70u;
    }
    const uint32_t b_kb = (((uint32_t)lane >> 3) & 1u) * 16u;

    float acc[4][4][4];
    #pragma unroll
    for (int mi = 0; mi < 4; mi++)
        #pragma unroll
        for (int ni = 0; ni < 4; ni++)
            #pragma unroll
            for (int r = 0; r < 4; r++) acc[mi][ni][r] = 0.0f;

    load_stage(0, 0);
    load_stage(1, 1);

    for (int c = 0; c < NCHUNK; c++) {
        const int s = c % NST;
        const uint32_t st = sbase + (uint32_t)s * STAGE;

        __syncthreads();
        if (c + 2 < NCHUNK) load_stage((c + 2) % NST, c + 2);

        if (c + 2 < NCHUNK)      CP_WAIT2();
        else if (c + 1 < NCHUNK) CP_WAIT1();
        else                     CP_WAIT0();

        #pragma unroll
        for (int ks = 0; ks < 4; ks++) {
            const uint32_t akb = (uint32_t)ks * 32u + a_kb;
            const uint32_t bkb = (uint32_t)ks * 32u + b_kb;
            uint32_t ar[4][4], bh[2][4];
            #pragma unroll
            for (int mi = 0; mi < 4; mi++)
                LDSM4(ar[mi], st + a_rowoff[mi] + (akb ^ a_mask[mi]));
            #pragma unroll
            for (int np = 0; np < 2; np++)
                LDSM4(bh[np], st + WH_OFF + b_rowoff[np] + (bkb ^ b_mask[np]));
            #pragma unroll
            for (int mi = 0; mi < 4; mi++)
                #pragma unroll
                for (int ni = 0; ni < 4; ni++) {
                    const int np = ni >> 1, po = (ni & 1) * 2;
                    MMA16816H(acc[mi][ni], ar[mi], bh[np][po], bh[np][po + 1]);
                }
        }
    }

    const int gid = lane >> 2;
    const int tig = lane & 3;
    #pragma unroll
    for (int mi = 0; mi < 4; mi++) {
        const int row0 = bm + wm + mi * 16 + gid;
        OT* C0 = C + (size_t)row0 * N;
        OT* C1 = C + (size_t)(row0 + 8) * N;
        #pragma unroll
        for (int ni = 0; ni < 4; ni++) {
            const int col = bn + wn + ni * 8 + tig * 2;
            const float b0 = bias[col], b1 = bias[col + 1];
            st_pair(C0 + col, acc[mi][ni][0] + b0, acc[mi][ni][1] + b1);
            st_pair(C1 + col, acc[mi][ni][2] + b0, acc[mi][ni][3] + b1);
        }
    }
}

// ================ Tensor-core windowed causal attention ====================
// CTA = (b, h, 64 queries), 128 threads / 4 warps; warp w owns queries
// [qt+16w, qt+16w+16), keys rows [16w, 16w+144) of the 192-row K/V tiles.
// Chunk c=1 (keys wq-80..wq-33) is fully in-band for all 16 queries when
// j0 >= 0 -> unmasked exp path (warp-uniform branch).
#define AQ_ROWS 64
#define AK_ROWS 192
#define ATTN_SMEM (AQ_ROWS * 128 + 2 * AK_ROWS * 128)   // 57344 B

__global__ __launch_bounds__(128) void attn_mma(const __half* __restrict__ qkv) {
    extern __shared__ char sm[];
    const uint32_t sbase = smem_u32(sm);
    const uint32_t Qb = sbase;
    const uint32_t Kb = sbase + AQ_ROWS * 128u;
    const uint32_t Vb = Kb + AK_ROWS * 128u;
    char* Kp = sm + AQ_ROWS * 128;
    char* Vp = Kp + AK_ROWS * 128;
    const int qt  = blockIdx.x * AQ_ROWS;
    const int h   = blockIdx.y;
    const int b   = blockIdx.z;
    const int tid = threadIdx.x;
    const int wid = tid >> 5;
    const int lane = tid & 31;

    if (tid < AQ_ROWS) {
        const __half* src = qkv + (size_t)(b * T_DIM + qt + tid) * QKV_W + h * D_DIM;
        const uint32_t rmask = (uint32_t)(tid & 7) * 16u;
        #pragma unroll
        for (int c = 0; c < 8; c++)
            cp16(Qb + (uint32_t)tid * 128u + (((uint32_t)c * 16u) ^ rmask), src + c * 8);
    }
    #pragma unroll
    for (int rep = 0; rep < 2; rep++) {
        const int row = tid + rep * 128;
        if (row >= AK_ROWS) break;
        const int j = qt - 128 + row;
        const uint32_t rmask = (uint32_t)(row & 7) * 16u;
        if (j >= 0) {
            const __half* ks = qkv + (size_t)(b * T_DIM + j) * QKV_W + E_DIM + h * D_DIM;
            const __half* vs = ks + E_DIM;
            #pragma unroll
            for (int c = 0; c < 8; c++) {
                const uint32_t so = (uint32_t)row * 128u + (((uint32_t)c * 16u) ^ rmask);
                cp16(Kb + so, ks + c * 8);
                cp16(Vb + so, vs + c * 8);
            }
        } else {
            const uint4 z = make_uint4(0, 0, 0, 0);
            #pragma unroll
            for (int c = 0; c < 8; c++) {
                const uint32_t so = (uint32_t)row * 128u + (((uint32_t)c * 16u) ^ rmask);
                *reinterpret_cast<uint4*>(Kp + so) = z;
                *reinterpret_cast<uint4*>(Vp + so) = z;
            }
        }
    }
    CP_COMMIT();
    CP_WAIT0();
    __syncthreads();

    uint32_t qf[4][4];
    {
        const uint32_t arow = (uint32_t)(wid * 16 + (lane & 15));
        const uint32_t amask = (arow & 7u) * 16u;
        const uint32_t acol = ((uint32_t)lane >> 4) * 16u;
        #pragma unroll
        for (int ki = 0; ki < 4; ki++)
            LDSM4(qf[ki], Qb + arow * 128u + (((uint32_t)ki * 32u + acol) ^ amask));
    }

    float o[8][4];
    #pragma unroll
    for (int u = 0; u < 8; u++)
        #pragma unroll
        for (int r = 0; r < 4; r++) o[u][r] = 0.0f;
    float l0 = 0.0f, l1 = 0.0f;
    const int i0 = qt + wid * 16 + (lane >> 2);
    const int i1 = i0 + 8;
    const int tq = lane & 3;
    const int wr0 = wid * 16;

    const uint32_t krow_l = (uint32_t)((lane & 7) + ((lane >> 4) << 3));
    const uint32_t kcol_l = (((uint32_t)lane >> 3) & 1u) * 16u;
    const uint32_t vrow_l = (uint32_t)((lane & 7) + (((lane >> 3) & 1) << 3));
    const uint32_t vcol_l = ((uint32_t)lane >> 4) * 16u;

    #pragma unroll
    for (int c = 0; c < 3; c++) {
        const int rk0 = wr0 + 48 * c;
        const int j0 = qt - 128 + rk0;

        float st[6][4];
        #pragma unroll
        for (int u = 0; u < 6; u++)
            #pragma unroll
            for (int r = 0; r < 4; r++) st[u][r] = 0.0f;

        #pragma unroll
        for (int ki = 0; ki < 4; ki++) {
            uint32_t kf[3][4];
            #pragma unroll
            for (int g2 = 0; g2 < 3; g2++) {
                const uint32_t row = (uint32_t)rk0 + (uint32_t)g2 * 16u + krow_l;
                LDSM4(kf[g2], Kb + row * 128u + (((uint32_t)ki * 32u + kcol_l) ^ ((row & 7u) * 16u)));
            }
            #pragma unroll
            for (int u = 0; u < 6; u++)
                MMA16816H(st[u], qf[ki], kf[u >> 1][(u & 1) * 2], kf[u >> 1][(u & 1) * 2 + 1]);
        }

        uint32_t pf[6][2];
        if (c == 1 && j0 >= 0) {
            // middle chunk: every key in-band for all warp queries -> no mask
            #pragma unroll
            for (int u = 0; u < 6; u++) {
                const float p0 = exp2f(st[u][0] * EXP_C);
                const float p1 = exp2f(st[u][1] * EXP_C);
                const float p2 = exp2f(st[u][2] * EXP_C);
                const float p3 = exp2f(st[u][3] * EXP_C);
                l0 += p0 + p1;
                l1 += p2 + p3;
                pf[u][0] = h2u(__floats2half2_rn(p0, p1));
                pf[u][1] = h2u(__floats2half2_rn(p2, p3));
            }
        } else {
            #pragma unroll
            for (int u = 0; u < 6; u++) {
                const int j = j0 + 8 * u + 2 * tq;
                const bool k0a = (j     <= i0) && (j     >= i0 - WIN) && (j     >= 0);
                const bool k0b = (j + 1 <= i0) && (j + 1 >= i0 - WIN) && (j + 1 >= 0);
                const bool k1a = (j     <= i1) && (j     >= i1 - WIN) && (j     >= 0);
                const bool k1b = (j + 1 <= i1) && (j + 1 >= i1 - WIN) && (j + 1 >= 0);
                const float p0 = k0a ? exp2f(st[u][0] * EXP_C) : 0.0f;
                const float p1 = k0b ? exp2f(st[u][1] * EXP_C) : 0.0f;
                const float p2 = k1a ? exp2f(st[u][2] * EXP_C) : 0.0f;
                const float p3 = k1b ? exp2f(st[u][3] * EXP_C) : 0.0f;
                l0 += p0 + p1;
                l1 += p2 + p3;
                pf[u][0] = h2u(__floats2half2_rn(p0, p1));
                pf[u][1] = h2u(__floats2half2_rn(p2, p3));
            }
        }

        #pragma unroll
        for (int kk = 0; kk < 3; kk++) {
            uint32_t af[4] = {pf[2 * kk][0], pf[2 * kk][1], pf[2 * kk + 1][0], pf[2 * kk + 1][1]};
            const uint32_t row = (uint32_t)rk0 + (uint32_t)kk * 16u + vrow_l;
            const uint32_t rm = (row & 7u) * 16u;
            #pragma unroll
            for (int g2 = 0; g2 < 4; g2++) {
                uint32_t vf[4];
                LDSM4T(vf, Vb + row * 128u + (((uint32_t)g2 * 32u + vcol_l) ^ rm));
                MMA16816H(o[2 * g2],     af, vf[0], vf[1]);
                MMA16816H(o[2 * g2 + 1], af, vf[2], vf[3]);
            }
        }
    }

    l0 += __shfl_xor_sync(0xffffffffu, l0, 1);
    l0 += __shfl_xor_sync(0xffffffffu, l0, 2);
    l1 += __shfl_xor_sync(0xffffffffu, l1, 1);
    l1 += __shfl_xor_sync(0xffffffffu, l1, 2);
    const float r0 = 1.0f / l0, r1 = 1.0f / l1;
    __half2* d0 = reinterpret_cast<__half2*>(
        g_ctx + (size_t)(b * T_DIM + i0) * E_DIM + h * D_DIM);
    __half2* d1 = reinterpret_cast<__half2*>(
        g_ctx + (size_t)(b * T_DIM + i1) * E_DIM + h * D_DIM);
    #pragma unroll
    for (int u = 0; u < 8; u++) {
        d0[4 * u + tq] = __floats2half2_rn(o[u][0] * r0, o[u][1] * r0);
        d1[4 * u + tq] = __floats2half2_rn(o[u][2] * r1, o[u][3] * r1);
    }
}

// ============================== launch ====================================
extern "C" void kernel_launch(void* const* d_in, const int* in_sizes, int n_in,
                              void* d_out, int out_size) {
    const float* x     = (const float*)d_in[0];
    const float* gamma = (const float*)d_in[2];
    const float* beta  = (const float*)d_in[3];
    const float* w_in  = (const float*)d_in[4];
    const float* b_in  = (const float*)d_in[5];
    const float* w_out = (const float*)d_in[6];
    const float* b_out = (const float*)d_in[7];
    float* out = (float*)d_out;

    __half *xn, *qkvh, *ctx, *win_hi, *wout_hi;
    cudaGetSymbolAddress((void**)&xn,      g_xn);
    cudaGetSymbolAddress((void**)&qkvh,    g_qkv);
    cudaGetSymbolAddress((void**)&ctx,     g_ctx);
    cudaGetSymbolAddress((void**)&win_hi,  g_win_hi);
    cudaGetSymbolAddress((void**)&wout_hi, g_wout_hi);

    cudaFuncSetAttribute((void*)gemm_mma<__half>,
                         cudaFuncAttributeMaxDynamicSharedMemorySize, SMEM_GEMM);
    cudaFuncSetAttribute((void*)gemm_mma<float>,
                         cudaFuncAttributeMaxDynamicSharedMemorySize, SMEM_GEMM);
    cudaFuncSetAttribute(attn_mma, cudaFuncAttributeMaxDynamicSharedMemorySize, ATTN_SMEM);

    const int n4_in   = QKV_W * E_DIM / 4;   // 196608
    const int n4_out  = E_DIM * E_DIM / 4;   // 65536
    const int n4_tot  = n4_in + n4_out;      // 262144
    const int conv_blocks = (n4_tot + 127) / 128;   // 2048

    ln_conv_kernel<<<ROWS + conv_blocks, 128>>>(x, gamma, beta, w_in, w_out,
                                                n4_in, n4_tot);
    gemm_mma<__half><<<dim3(QKV_W / 128, ROWS / 128), 256, SMEM_GEMM>>>(
        xn, win_hi, b_in, qkvh, QKV_W);
    attn_mma<<<dim3(T_DIM / AQ_ROWS, H_DIM, B_DIM), 128, ATTN_SMEM>>>(qkvh);
    gemm_mma<float><<<dim3(E_DIM / 128, ROWS / 128), 256, SMEM_GEMM>>>(
        ctx, wout_hi, b_out, out, E_DIM);
}

// round 15
// speedup vs baseline: 4.2638x; 1.0296x over previous
#include <cuda_runtime.h>
#include <cuda_fp16.h>
#include <math.h>
#include <stdint.h>

#define E_DIM 512
#define T_DIM 1024
#define B_DIM 8
#define H_DIM 8
#define D_DIM 64
#define WIN   128
#define ROWS  (B_DIM * T_DIM)   // 8192
#define QKV_W (3 * E_DIM)       // 1536
#define K_DIM 512
#define KC    64
#define NCHUNK (K_DIM / KC)               // 8
#define TILE_BYTES (128 * 128)            // 16 KB
#define SMEM_GEMM (96 * 1024)

// exp2 constant: 0.125 * log2(e)
#define EXP_C 0.18033688011112042f

// -------------------- scratch (__device__ globals) -------------------------
__device__ __half g_xn  [ROWS * E_DIM];
__device__ __half g_qkv [ROWS * QKV_W];
__device__ __half g_ctx [ROWS * E_DIM];
__device__ __half g_win_hi[QKV_W * E_DIM];
__device__ __half g_wout_hi[E_DIM * E_DIM];

// ============================ helpers ======================================
__device__ __forceinline__ uint32_t smem_u32(const void* p) {
    uint32_t a;
    asm("{ .reg .u64 t; cvta.to.shared.u64 t, %1; cvt.u32.u64 %0, t; }" : "=r"(a) : "l"(p));
    return a;
}
__device__ __forceinline__ void cp16(uint32_t dst, const void* src) {
    asm volatile("cp.async.cg.shared.global [%0], [%1], 16;" :: "r"(dst), "l"(src));
}
#define CP_COMMIT() asm volatile("cp.async.commit_group;" ::: "memory")
#define CP_WAIT2()  asm volatile("cp.async.wait_group 2;" ::: "memory")
#define CP_WAIT1()  asm volatile("cp.async.wait_group 1;" ::: "memory")
#define CP_WAIT0()  asm volatile("cp.async.wait_group 0;" ::: "memory")

#define LDSM4(R, addr)                                                          \
    asm volatile("ldmatrix.sync.aligned.m8n8.x4.shared.b16 {%0,%1,%2,%3}, [%4];" \
        : "=r"((R)[0]), "=r"((R)[1]), "=r"((R)[2]), "=r"((R)[3]) : "r"(addr))

#define LDSM4T(R, addr)                                                         \
    asm volatile("ldmatrix.sync.aligned.m8n8.x4.trans.shared.b16 {%0,%1,%2,%3}, [%4];" \
        : "=r"((R)[0]), "=r"((R)[1]), "=r"((R)[2]), "=r"((R)[3]) : "r"(addr))

#define MMA16816H(D, A, B0, B1)                                                 \
    asm volatile("mma.sync.aligned.m16n8k16.row.col.f32.f16.f16.f32 "           \
        "{%0,%1,%2,%3},{%4,%5,%6,%7},{%8,%9},{%0,%1,%2,%3};"                    \
        : "+f"((D)[0]), "+f"((D)[1]), "+f"((D)[2]), "+f"((D)[3])                \
        : "r"((A)[0]), "r"((A)[1]), "r"((A)[2]), "r"((A)[3]), "r"(B0), "r"(B1))

__device__ __forceinline__ uint32_t swz(uint32_t off) {
    return off ^ ((off >> 3) & 0x70u);
}
__device__ __forceinline__ uint32_t h2u(__half2 v) { return *reinterpret_cast<uint32_t*>(&v); }

__device__ __forceinline__ void st_pair(float* p, float a, float b) {
    *reinterpret_cast<float2*>(p) = make_float2(a, b);
}
__device__ __forceinline__ void st_pair(__half* p, float a, float b) {
    *reinterpret_cast<__half2*>(p) = __floats2half2_rn(a, b);
}

// ============ fused LayerNorm (blocks < ROWS) + weight conv (rest) =========
__global__ __launch_bounds__(128) void ln_conv_kernel(
    const float* __restrict__ x,
    const float* __restrict__ gamma,
    const float* __restrict__ beta,
    const float* __restrict__ w_in,
    const float* __restrict__ w_out,
    int n4_in, int n4_tot) {
    const int bid = blockIdx.x;
    const int tid = threadIdx.x;

    if (bid >= ROWS) {
        const int i = (bid - ROWS) * 128 + tid;
        if (i < n4_tot) {
            const float* src; __half* dst; int k;
            if (i < n4_in) { src = w_in;  dst = g_win_hi;  k = i; }
            else           { src = w_out; dst = g_wout_hi; k = i - n4_in; }
            const float4 v = reinterpret_cast<const float4*>(src)[k];
            __half2* oh = reinterpret_cast<__half2*>(dst);
            oh[2 * k + 0] = __floats2half2_rn(v.x, v.y);
            oh[2 * k + 1] = __floats2half2_rn(v.z, v.w);
        }
        return;
    }

    const int row = bid;
    const float4 v = reinterpret_cast<const float4*>(x + (size_t)row * E_DIM)[tid];
    float s  = v.x + v.y + v.z + v.w;
    float ss = v.x * v.x + v.y * v.y + v.z * v.z + v.w * v.w;
    #pragma unroll
    for (int o = 16; o > 0; o >>= 1) {
        s  += __shfl_down_sync(0xffffffffu, s,  o);
        ss += __shfl_down_sync(0xffffffffu, ss, o);
    }
    __shared__ float sh_s[4], sh_ss[4], sh_mu, sh_rstd;
    const int w = tid >> 5, lane = tid & 31;
    if (lane == 0) { sh_s[w] = s; sh_ss[w] = ss; }
    __syncthreads();
    if (tid == 0) {
        float ts  = sh_s[0] + sh_s[1] + sh_s[2] + sh_s[3];
        float tss = sh_ss[0] + sh_ss[1] + sh_ss[2] + sh_ss[3];
        float mu  = ts * (1.0f / E_DIM);
        float var = tss * (1.0f / E_DIM) - mu * mu;
        sh_mu = mu; sh_rstd = rsqrtf(var + 1e-5f);
    }
    __syncthreads();
    const float mu = sh_mu, rstd = sh_rstd;
    const float4 g  = reinterpret_cast<const float4*>(gamma)[tid];
    const float4 be = reinterpret_cast<const float4*>(beta)[tid];
    float2 a, b;
    a.x = (v.x - mu) * rstd * g.x + be.x;
    a.y = (v.y - mu) * rstd * g.y + be.y;
    b.x = (v.z - mu) * rstd * g.z + be.z;
    b.y = (v.w - mu) * rstd * g.w + be.w;
    __half2* o = reinterpret_cast<__half2*>(g_xn + (size_t)row * E_DIM);
    o[2 * tid + 0] = __float22half2_rn(a);
    o[2 * tid + 1] = __float22half2_rn(b);
}

// ===================== fp16 GEMM via mma.sync (1-term, R12) ================
template <typename OT>
__global__ __launch_bounds__(256, 2)
void gemm_mma(const __half* __restrict__ A, const __half* __restrict__ Wh,
              const float* __restrict__ bias, OT* __restrict__ C, const int N) {
    constexpr uint32_t WH_OFF = TILE_BYTES;
    constexpr uint32_t STAGE  = 2 * TILE_BYTES;
    constexpr int NST = 3;

    extern __shared__ char smem[];
    const uint32_t sbase = smem_u32(smem);
    const int tid  = threadIdx.x;
    const int wid  = tid >> 5;
    const int lane = tid & 31;
    const int bn = blockIdx.x * 128;
    const int bm = blockIdx.y * 128;

    const int lrow  = tid >> 1;
    const int lhalf = tid & 1;
    const __half* aS  = A  + (size_t)(bm + lrow) * K_DIM + lhalf * 32;
    const __half* wHS = Wh + (size_t)(bn + lrow) * K_DIM + lhalf * 32;
    uint32_t st_off[4];
    #pragma unroll
    for (int v = 0; v < 4; v++) {
        const uint32_t off = (uint32_t)lrow * 128u + (uint32_t)lhalf * 64u + (uint32_t)v * 16u;
        st_off[v] = swz(off);
    }

    auto load_stage = [&](int s, int c) {
        const uint32_t st = sbase + (uint32_t)s * STAGE;
        const int kc = c * KC;
        #pragma unroll
        for (int v = 0; v < 4; v++) {
            cp16(st + st_off[v],          aS  + kc + v * 8);
            cp16(st + WH_OFF + st_off[v], wHS + kc + v * 8);
        }
        CP_COMMIT();
    };

    const int wm = (wid & 1) * 64;
    const int wn = (wid >> 1) * 32;
    uint32_t a_rowoff[4], a_mask[4];
    #pragma unroll
    for (int mi = 0; mi < 4; mi++) {
        const uint32_t r = (uint32_t)(wm + mi * 16 + (lane & 15));
        a_rowoff[mi] = r * 128u;
        a_mask[mi]   = (a_rowoff[mi] >> 3) & 0x70u;
    }
    const uint32_t a_kb = ((uint32_t)lane >> 4) * 16u;
    const int b_lrow = (lane & 7) + ((lane >> 4) << 3);
    uint32_t b_rowoff[2], b_mask[2];
    #pragma unroll
    for (int np = 0; np < 2; np++) {
        const uint32_t r = (uint32_t)(wn + np * 16 + b_lrow);
        b_rowoff[np] = r * 128u;
        b_mask[np]   = (b_rowoff[np] >> 3) & 0x70u;
    }
    const uint32_t b_kb = (((uint32_t)lane >> 3) & 1u) * 16u;

    float acc[4][4][4];
    #pragma unroll
    for (int mi = 0; mi < 4; mi++)
        #pragma unroll
        for (int ni = 0; ni < 4; ni++)
            #pragma unroll
            for (int r = 0; r < 4; r++) acc[mi][ni][r] = 0.0f;

    load_stage(0, 0);
    load_stage(1, 1);

    for (int c = 0; c < NCHUNK; c++) {
        const int s = c % NST;
        const uint32_t st = sbase + (uint32_t)s * STAGE;

        __syncthreads();
        if (c + 2 < NCHUNK) load_stage((c + 2) % NST, c + 2);

        if (c + 2 < NCHUNK)      CP_WAIT2();
        else if (c + 1 < NCHUNK) CP_WAIT1();
        else                     CP_WAIT0();

        #pragma unroll
        for (int ks = 0; ks < 4; ks++) {
            const uint32_t akb = (uint32_t)ks * 32u + a_kb;
            const uint32_t bkb = (uint32_t)ks * 32u + b_kb;
            uint32_t ar[4][4], bh[2][4];
            #pragma unroll
            for (int mi = 0; mi < 4; mi++)
                LDSM4(ar[mi], st + a_rowoff[mi] + (akb ^ a_mask[mi]));
            #pragma unroll
            for (int np = 0; np < 2; np++)
                LDSM4(bh[np], st + WH_OFF + b_rowoff[np] + (bkb ^ b_mask[np]));
            #pragma unroll
            for (int mi = 0; mi < 4; mi++)
                #pragma unroll
                for (int ni = 0; ni < 4; ni++) {
                    const int np = ni >> 1, po = (ni & 1) * 2;
                    MMA16816H(acc[mi][ni], ar[mi], bh[np][po], bh[np][po + 1]);
                }
        }
    }

    const int gid = lane >> 2;
    const int tig = lane & 3;
    #pragma unroll
    for (int mi = 0; mi < 4; mi++) {
        const int row0 = bm + wm + mi * 16 + gid;
        OT* C0 = C + (size_t)row0 * N;
        OT* C1 = C + (size_t)(row0 + 8) * N;
        #pragma unroll
        for (int ni = 0; ni < 4; ni++) {
            const int col = bn + wn + ni * 8 + tig * 2;
            const float b0 = bias[col], b1 = bias[col + 1];
            st_pair(C0 + col, acc[mi][ni][0] + b0, acc[mi][ni][1] + b1);
            st_pair(C1 + col, acc[mi][ni][2] + b0, acc[mi][ni][3] + b1);
        }
    }
}

// ================ Tensor-core windowed causal attention ====================
// CTA = (b, h, 64 queries), 128 threads / 4 warps; warp w owns queries
// [qt+16w, qt+16w+16), keys rows [16w, 16w+144) of 192-row K/V tiles.
// __launch_bounds__(128, 4): regs capped at 128 -> 4 CTAs/SM
// (smem 4 x 56KB = 224KB <= 228KB), 16 warps/SM.
#define AQ_ROWS 64
#define AK_ROWS 192
#define ATTN_SMEM (AQ_ROWS * 128 + 2 * AK_ROWS * 128)   // 57344 B

__global__ __launch_bounds__(128, 4) void attn_mma(const __half* __restrict__ qkv) {
    extern __shared__ char sm[];
    const uint32_t sbase = smem_u32(sm);
    const uint32_t Qb = sbase;
    const uint32_t Kb = sbase + AQ_ROWS * 128u;
    const uint32_t Vb = Kb + AK_ROWS * 128u;
    char* Kp = sm + AQ_ROWS * 128;
    char* Vp = Kp + AK_ROWS * 128;
    const int qt  = blockIdx.x * AQ_ROWS;
    const int h   = blockIdx.y;
    const int b   = blockIdx.z;
    const int tid = threadIdx.x;
    const int wid = tid >> 5;
    const int lane = tid & 31;

    // ---- Q rows: all 128 threads, 4 cp16 each (row tid/2, half tid&1) ----
    {
        const int qrow  = tid >> 1;
        const int qhalf = tid & 1;
        const __half* src = qkv + (size_t)(b * T_DIM + qt + qrow) * QKV_W + h * D_DIM + qhalf * 32;
        const uint32_t rmask = (uint32_t)(qrow & 7) * 16u;
        #pragma unroll
        for (int c = 0; c < 4; c++) {
            const uint32_t boff = (uint32_t)qhalf * 64u + (uint32_t)c * 16u;
            cp16(Qb + (uint32_t)qrow * 128u + (boff ^ rmask), src + c * 8);
        }
    }
    // ---- K,V rows: thread t loads row t; threads 0..63 also row 128+t ----
    #pragma unroll
    for (int rep = 0; rep < 2; rep++) {
        const int row = tid + rep * 128;
        if (row >= AK_ROWS) break;
        const int j = qt - 128 + row;
        const uint32_t rmask = (uint32_t)(row & 7) * 16u;
        if (j >= 0) {
            const __half* ks = qkv + (size_t)(b * T_DIM + j) * QKV_W + E_DIM + h * D_DIM;
            const __half* vs = ks + E_DIM;
            #pragma unroll
            for (int c = 0; c < 8; c++) {
                const uint32_t so = (uint32_t)row * 128u + (((uint32_t)c * 16u) ^ rmask);
                cp16(Kb + so, ks + c * 8);
                cp16(Vb + so, vs + c * 8);
            }
        } else {
            const uint4 z = make_uint4(0, 0, 0, 0);
            #pragma unroll
            for (int c = 0; c < 8; c++) {
                const uint32_t so = (uint32_t)row * 128u + (((uint32_t)c * 16u) ^ rmask);
                *reinterpret_cast<uint4*>(Kp + so) = z;
                *reinterpret_cast<uint4*>(Vp + so) = z;
            }
        }
    }
    CP_COMMIT();
    CP_WAIT0();
    __syncthreads();

    uint32_t qf[4][4];
    {
        const uint32_t arow = (uint32_t)(wid * 16 + (lane & 15));
        const uint32_t amask = (arow & 7u) * 16u;
        const uint32_t acol = ((uint32_t)lane >> 4) * 16u;
        #pragma unroll
        for (int ki = 0; ki < 4; ki++)
            LDSM4(qf[ki], Qb + arow * 128u + (((uint32_t)ki * 32u + acol) ^ amask));
    }

    float o[8][4];
    #pragma unroll
    for (int u = 0; u < 8; u++)
        #pragma unroll
        for (int r = 0; r < 4; r++) o[u][r] = 0.0f;
    float l0 = 0.0f, l1 = 0.0f;
    const int i0 = qt + wid * 16 + (lane >> 2);
    const int i1 = i0 + 8;
    const int tq = lane & 3;
    const int wr0 = wid * 16;

    const uint32_t krow_l = (uint32_t)((lane & 7) + ((lane >> 4) << 3));
    const uint32_t kcol_l = (((uint32_t)lane >> 3) & 1u) * 16u;
    const uint32_t vrow_l = (uint32_t)((lane & 7) + (((lane >> 3) & 1) << 3));
    const uint32_t vcol_l = ((uint32_t)lane >> 4) * 16u;

    #pragma unroll
    for (int c = 0; c < 3; c++) {
        const int rk0 = wr0 + 48 * c;
        const int j0 = qt - 128 + rk0;

        float st[6][4];
        #pragma unroll
        for (int u = 0; u < 6; u++)
            #pragma unroll
            for (int r = 0; r < 4; r++) st[u][r] = 0.0f;

        #pragma unroll
        for (int ki = 0; ki < 4; ki++) {
            uint32_t kf[3][4];
            #pragma unroll
            for (int g2 = 0; g2 < 3; g2++) {
                const uint32_t row = (uint32_t)rk0 + (uint32_t)g2 * 16u + krow_l;
                LDSM4(kf[g2], Kb + row * 128u + (((uint32_t)ki * 32u + kcol_l) ^ ((row & 7u) * 16u)));
            }
            #pragma unroll
            for (int u = 0; u < 6; u++)
                MMA16816H(st[u], qf[ki], kf[u >> 1][(u & 1) * 2], kf[u >> 1][(u & 1) * 2 + 1]);
        }

        uint32_t pf[6][2];
        if (c == 1 && j0 >= 0) {
            #pragma unroll
            for (int u = 0; u < 6; u++) {
                const float p0 = exp2f(st[u][0] * EXP_C);
                const float p1 = exp2f(st[u][1] * EXP_C);
                const float p2 = exp2f(st[u][2] * EXP_C);
                const float p3 = exp2f(st[u][3] * EXP_C);
                l0 += p0 + p1;
                l1 += p2 + p3;
                pf[u][0] = h2u(__floats2half2_rn(p0, p1));
                pf[u][1] = h2u(__floats2half2_rn(p2, p3));
            }
        } else {
            #pragma unroll
            for (int u = 0; u < 6; u++) {
                const int j = j0 + 8 * u + 2 * tq;
                const bool k0a = (j     <= i0) && (j     >= i0 - WIN) && (j     >= 0);
                const bool k0b = (j + 1 <= i0) && (j + 1 >= i0 - WIN) && (j + 1 >= 0);
                const bool k1a = (j     <= i1) && (j     >= i1 - WIN) && (j     >= 0);
                const bool k1b = (j + 1 <= i1) && (j + 1 >= i1 - WIN) && (j + 1 >= 0);
                const float p0 = k0a ? exp2f(st[u][0] * EXP_C) : 0.0f;
                const float p1 = k0b ? exp2f(st[u][1] * EXP_C) : 0.0f;
                const float p2 = k1a ? exp2f(st[u][2] * EXP_C) : 0.0f;
                const float p3 = k1b ? exp2f(st[u][3] * EXP_C) : 0.0f;
                l0 += p0 + p1;
                l1 += p2 + p3;
                pf[u][0] = h2u(__floats2half2_rn(p0, p1));
                pf[u][1] = h2u(__floats2half2_rn(p2, p3));
            }
        }

        #pragma unroll
        for (int kk = 0; kk < 3; kk++) {
            uint32_t af[4] = {pf[2 * kk][0], pf[2 * kk][1], pf[2 * kk + 1][0], pf[2 * kk + 1][1]};
            const uint32_t row = (uint32_t)rk0 + (uint32_t)kk * 16u + vrow_l;
            const uint32_t rm = (row & 7u) * 16u;
            #pragma unroll
            for (int g2 = 0; g2 < 4; g2++) {
                uint32_t vf[4];
                LDSM4T(vf, Vb + row * 128u + (((uint32_t)g2 * 32u + vcol_l) ^ rm));
                MMA16816H(o[2 * g2],     af, vf[0], vf[1]);
                MMA16816H(o[2 * g2 + 1], af, vf[2], vf[3]);
            }
        }
    }

    l0 += __shfl_xor_sync(0xffffffffu, l0, 1);
    l0 += __shfl_xor_sync(0xffffffffu, l0, 2);
    l1 += __shfl_xor_sync(0xffffffffu, l1, 1);
    l1 += __shfl_xor_sync(0xffffffffu, l1, 2);
    const float r0 = 1.0f / l0, r1 = 1.0f / l1;
    __half2* d0 = reinterpret_cast<__half2*>(
        g_ctx + (size_t)(b * T_DIM + i0) * E_DIM + h * D_DIM);
    __half2* d1 = reinterpret_cast<__half2*>(
        g_ctx + (size_t)(b * T_DIM + i1) * E_DIM + h * D_DIM);
    #pragma unroll
    for (int u = 0; u < 8; u++) {
        d0[4 * u + tq] = __floats2half2_rn(o[u][0] * r0, o[u][1] * r0);
        d1[4 * u + tq] = __floats2half2_rn(o[u][2] * r1, o[u][3] * r1);
    }
}

// ============================== launch ====================================
extern "C" void kernel_launch(void* const* d_in, const int* in_sizes, int n_in,
                              void* d_out, int out_size) {
    const float* x     = (const float*)d_in[0];
    const float* gamma = (const float*)d_in[2];
    const float* beta  = (const float*)d_in[3];
    const float* w_in  = (const float*)d_in[4];
    const float* b_in  = (const float*)d_in[5];
    const float* w_out = (const float*)d_in[6];
    const float* b_out = (const float*)d_in[7];
    float* out = (float*)d_out;

    __half *xn, *qkvh, *ctx, *win_hi, *wout_hi;
    cudaGetSymbolAddress((void**)&xn,      g_xn);
    cudaGetSymbolAddress((void**)&qkvh,    g_qkv);
    cudaGetSymbolAddress((void**)&ctx,     g_ctx);
    cudaGetSymbolAddress((void**)&win_hi,  g_win_hi);
    cudaGetSymbolAddress((void**)&wout_hi, g_wout_hi);

    cudaFuncSetAttribute((void*)gemm_mma<__half>,
                         cudaFuncAttributeMaxDynamicSharedMemorySize, SMEM_GEMM);
    cudaFuncSetAttribute((void*)gemm_mma<float>,
                         cudaFuncAttributeMaxDynamicSharedMemorySize, SMEM_GEMM);
    cudaFuncSetAttribute(attn_mma, cudaFuncAttributeMaxDynamicSharedMemorySize, ATTN_SMEM);

    const int n4_in   = QKV_W * E_DIM / 4;   // 196608
    const int n4_out  = E_DIM * E_DIM / 4;   // 65536
    const int n4_tot  = n4_in + n4_out;      // 262144
    const int conv_blocks = (n4_tot + 127) / 128;   // 2048

    ln_conv_kernel<<<ROWS + conv_blocks, 128>>>(x, gamma, beta, w_in, w_out,
                                                n4_in, n4_tot);
    gemm_mma<__half><<<dim3(QKV_W / 128, ROWS / 128), 256, SMEM_GEMM>>>(
        xn, win_hi, b_in, qkvh, QKV_W);
    attn_mma<<<dim3(T_DIM / AQ_ROWS, H_DIM, B_DIM), 128, ATTN_SMEM>>>(qkvh);
    gemm_mma<float><<<dim3(E_DIM / 128, ROWS / 128), 256, SMEM_GEMM>>>(
        ctx, wout_hi, b_out, out, E_DIM);
}

// round 16
// speedup vs baseline: 4.4318x; 1.0394x over previous
#include <cuda_runtime.h>
#include <cuda_fp16.h>
#include <math.h>
#include <stdint.h>

#define E_DIM 512
#define T_DIM 1024
#define B_DIM 8
#define H_DIM 8
#define D_DIM 64
#define WIN   128
#define ROWS  (B_DIM * T_DIM)   // 8192
#define QKV_W (3 * E_DIM)       // 1536
#define K_DIM 512
#define KC    64
#define NCHUNK (K_DIM / KC)               // 8
#define TILE_BYTES (128 * 128)            // 16 KB
#define SMEM_GEMM (96 * 1024)

// exp2 constant: 0.125 * log2(e)
#define EXP_C 0.18033688011112042f

// -------------------- scratch (__device__ globals) -------------------------
__device__ __half g_xn  [ROWS * E_DIM];
__device__ __half g_qkv [ROWS * QKV_W];
__device__ __half g_ctx [ROWS * E_DIM];
__device__ __half g_win_hi[QKV_W * E_DIM];
__device__ __half g_wout_hi[E_DIM * E_DIM];

// ============================ helpers ======================================
__device__ __forceinline__ uint32_t smem_u32(const void* p) {
    uint32_t a;
    asm("{ .reg .u64 t; cvta.to.shared.u64 t, %1; cvt.u32.u64 %0, t; }" : "=r"(a) : "l"(p));
    return a;
}
__device__ __forceinline__ void cp16(uint32_t dst, const void* src) {
    asm volatile("cp.async.cg.shared.global [%0], [%1], 16;" :: "r"(dst), "l"(src));
}
#define CP_COMMIT() asm volatile("cp.async.commit_group;" ::: "memory")
#define CP_WAIT2()  asm volatile("cp.async.wait_group 2;" ::: "memory")
#define CP_WAIT1()  asm volatile("cp.async.wait_group 1;" ::: "memory")
#define CP_WAIT0()  asm volatile("cp.async.wait_group 0;" ::: "memory")

#define LDSM4(R, addr)                                                          \
    asm volatile("ldmatrix.sync.aligned.m8n8.x4.shared.b16 {%0,%1,%2,%3}, [%4];" \
        : "=r"((R)[0]), "=r"((R)[1]), "=r"((R)[2]), "=r"((R)[3]) : "r"(addr))

#define LDSM4T(R, addr)                                                         \
    asm volatile("ldmatrix.sync.aligned.m8n8.x4.trans.shared.b16 {%0,%1,%2,%3}, [%4];" \
        : "=r"((R)[0]), "=r"((R)[1]), "=r"((R)[2]), "=r"((R)[3]) : "r"(addr))

#define MMA16816H(D, A, B0, B1)                                                 \
    asm volatile("mma.sync.aligned.m16n8k16.row.col.f32.f16.f16.f32 "           \
        "{%0,%1,%2,%3},{%4,%5,%6,%7},{%8,%9},{%0,%1,%2,%3};"                    \
        : "+f"((D)[0]), "+f"((D)[1]), "+f"((D)[2]), "+f"((D)[3])                \
        : "r"((A)[0]), "r"((A)[1]), "r"((A)[2]), "r"((A)[3]), "r"(B0), "r"(B1))

__device__ __forceinline__ uint32_t swz(uint32_t off) {
    return off ^ ((off >> 3) & 0x70u);
}
__device__ __forceinline__ uint32_t h2u(__half2 v) { return *reinterpret_cast<uint32_t*>(&v); }

__device__ __forceinline__ void st_pair(float* p, float a, float b) {
    *reinterpret_cast<float2*>(p) = make_float2(a, b);
}
__device__ __forceinline__ void st_pair(__half* p, float a, float b) {
    *reinterpret_cast<__half2*>(p) = __floats2half2_rn(a, b);
}

// ====== fused LayerNorm (warp-per-row, no block sync) + weight conv ========
#define LN_BLOCKS (ROWS / 4)     // 2048 blocks, 4 warps = 4 rows each
__global__ __launch_bounds__(128) void ln_conv_kernel(
    const float* __restrict__ x,
    const float* __restrict__ gamma,
    const float* __restrict__ beta,
    const float* __restrict__ w_in,
    const float* __restrict__ w_out,
    int n4_in, int n4_tot) {
    const int bid = blockIdx.x;
    const int tid = threadIdx.x;

    if (bid < LN_BLOCKS) {
        const int warp = tid >> 5, lane = tid & 31;
        const int row = bid * 4 + warp;
        const float4* xr = reinterpret_cast<const float4*>(x + (size_t)row * E_DIM);
        float4 v[4];
        float s = 0.f, ss = 0.f;
        #pragma unroll
        for (int k = 0; k < 4; k++) {
            v[k] = xr[lane + 32 * k];
            s  += v[k].x + v[k].y + v[k].z + v[k].w;
            ss += v[k].x * v[k].x + v[k].y * v[k].y + v[k].z * v[k].z + v[k].w * v[k].w;
        }
        #pragma unroll
        for (int o = 16; o > 0; o >>= 1) {
            s  += __shfl_xor_sync(0xffffffffu, s,  o);
            ss += __shfl_xor_sync(0xffffffffu, ss, o);
        }
        const float mu   = s * (1.0f / E_DIM);
        const float var  = ss * (1.0f / E_DIM) - mu * mu;
        const float rstd = rsqrtf(var + 1e-5f);
        __half2* orow = reinterpret_cast<__half2*>(g_xn + (size_t)row * E_DIM);
        #pragma unroll
        for (int k = 0; k < 4; k++) {
            const int idx = lane + 32 * k;
            const float4 g  = reinterpret_cast<const float4*>(gamma)[idx];
            const float4 be = reinterpret_cast<const float4*>(beta)[idx];
            float2 a, b;
            a.x = (v[k].x - mu) * rstd * g.x + be.x;
            a.y = (v[k].y - mu) * rstd * g.y + be.y;
            b.x = (v[k].z - mu) * rstd * g.z + be.z;
            b.y = (v[k].w - mu) * rstd * g.w + be.w;
            orow[2 * idx + 0] = __float22half2_rn(a);
            orow[2 * idx + 1] = __float22half2_rn(b);
        }
        return;
    }

    // ---- weight fp32 -> fp16, 2 float4 per thread ----
    const int base = (bid - LN_BLOCKS) * 256 + tid;
    #pragma unroll
    for (int rep = 0; rep < 2; rep++) {
        const int i = base + rep * 128;
        if (i < n4_tot) {
            const float* src; __half* dst; int k;
            if (i < n4_in) { src = w_in;  dst = g_win_hi;  k = i; }
            else           { src = w_out; dst = g_wout_hi; k = i - n4_in; }
            const float4 v = reinterpret_cast<const float4*>(src)[k];
            __half2* oh = reinterpret_cast<__half2*>(dst);
            oh[2 * k + 0] = __floats2half2_rn(v.x, v.y);
            oh[2 * k + 1] = __floats2half2_rn(v.z, v.w);
        }
    }
}

// ===================== fp16 GEMM via mma.sync (1-term) =====================
template <typename OT>
__global__ __launch_bounds__(256, 2)
void gemm_mma(const __half* __restrict__ A, const __half* __restrict__ Wh,
              const float* __restrict__ bias, OT* __restrict__ C, const int N) {
    constexpr uint32_t WH_OFF = TILE_BYTES;
    constexpr uint32_t STAGE  = 2 * TILE_BYTES;
    constexpr int NST = 3;

    extern __shared__ char smem[];
    const uint32_t sbase = smem_u32(smem);
    const int tid  = threadIdx.x;
    const int wid  = tid >> 5;
    const int lane = tid & 31;
    const int bn = blockIdx.x * 128;
    const int bm = blockIdx.y * 128;

    const int lrow  = tid >> 1;
    const int lhalf = tid & 1;
    const __half* aS  = A  + (size_t)(bm + lrow) * K_DIM + lhalf * 32;
    const __half* wHS = Wh + (size_t)(bn + lrow) * K_DIM + lhalf * 32;
    uint32_t st_off[4];
    #pragma unroll
    for (int v = 0; v < 4; v++) {
        const uint32_t off = (uint32_t)lrow * 128u + (uint32_t)lhalf * 64u + (uint32_t)v * 16u;
        st_off[v] = swz(off);
    }

    auto load_stage = [&](int s, int c) {
        const uint32_t st = sbase + (uint32_t)s * STAGE;
        const int kc = c * KC;
        #pragma unroll
        for (int v = 0; v < 4; v++) {
            cp16(st + st_off[v],          aS  + kc + v * 8);
            cp16(st + WH_OFF + st_off[v], wHS + kc + v * 8);
        }
        CP_COMMIT();
    };

    const int wm = (wid & 1) * 64;
    const int wn = (wid >> 1) * 32;
    uint32_t a_rowoff[4], a_mask[4];
    #pragma unroll
    for (int mi = 0; mi < 4; mi++) {
        const uint32_t r = (uint32_t)(wm + mi * 16 + (lane & 15));
        a_rowoff[mi] = r * 128u;
        a_mask[mi]   = (a_rowoff[mi] >> 3) & 0x70u;
    }
    const uint32_t a_kb = ((uint32_t)lane >> 4) * 16u;
    const int b_lrow = (lane & 7) + ((lane >> 4) << 3);
    uint32_t b_rowoff[2], b_mask[2];
    #pragma unroll
    for (int np = 0; np < 2; np++) {
        const uint32_t r = (uint32_t)(wn + np * 16 + b_lrow);
        b_rowoff[np] = r * 128u;
        b_mask[np]   = (b_rowoff[np] >> 3) & 0x70u;
    }
    const uint32_t b_kb = (((uint32_t)lane >> 3) & 1u) * 16u;

    float acc[4][4][4];
    #pragma unroll
    for (int mi = 0; mi < 4; mi++)
        #pragma unroll
        for (int ni = 0; ni < 4; ni++)
            #pragma unroll
            for (int r = 0; r < 4; r++) acc[mi][ni][r] = 0.0f;

    load_stage(0, 0);
    load_stage(1, 1);

    #pragma unroll
    for (int c = 0; c < NCHUNK; c++) {
        const int s = c % NST;
        const uint32_t st = sbase + (uint32_t)s * STAGE;

        __syncthreads();
        if (c + 2 < NCHUNK) load_stage((c + 2) % NST, c + 2);

        if (c + 2 < NCHUNK)      CP_WAIT2();
        else if (c + 1 < NCHUNK) CP_WAIT1();
        else                     CP_WAIT0();

        #pragma unroll
        for (int ks = 0; ks < 4; ks++) {
            const uint32_t akb = (uint32_t)ks * 32u + a_kb;
            const uint32_t bkb = (uint32_t)ks * 32u + b_kb;
            uint32_t ar[4][4], bh[2][4];
            #pragma unroll
            for (int mi = 0; mi < 4; mi++)
                LDSM4(ar[mi], st + a_rowoff[mi] + (akb ^ a_mask[mi]));
            #pragma unroll
            for (int np = 0; np < 2; np++)
                LDSM4(bh[np], st + WH_OFF + b_rowoff[np] + (bkb ^ b_mask[np]));
            #pragma unroll
            for (int mi = 0; mi < 4; mi++)
                #pragma unroll
                for (int ni = 0; ni < 4; ni++) {
                    const int np = ni >> 1, po = (ni & 1) * 2;
                    MMA16816H(acc[mi][ni], ar[mi], bh[np][po], bh[np][po + 1]);
                }
        }
    }

    const int gid = lane >> 2;
    const int tig = lane & 3;
    #pragma unroll
    for (int mi = 0; mi < 4; mi++) {
        const int row0 = bm + wm + mi * 16 + gid;
        OT* C0 = C + (size_t)row0 * N;
        OT* C1 = C + (size_t)(row0 + 8) * N;
        #pragma unroll
        for (int ni = 0; ni < 4; ni++) {
            const int col = bn + wn + ni * 8 + tig * 2;
            const float b0 = bias[col], b1 = bias[col + 1];
            st_pair(C0 + col, acc[mi][ni][0] + b0, acc[mi][ni][1] + b1);
            st_pair(C1 + col, acc[mi][ni][2] + b0, acc[mi][ni][3] + b1);
        }
    }
}

// ================ Tensor-core windowed causal attention ====================
// CTA = (b, h, 64 queries), 128 threads / 4 warps; warp w owns queries
// [qt+16w, qt+16w+16), keys rows [16w, 16w+144) of 192-row K/V tiles.
// 4 CTAs/SM (regs capped 128, smem 4 x 56KB). Fully-OOB chunks skipped.
#define AQ_ROWS 64
#define AK_ROWS 192
#define ATTN_SMEM (AQ_ROWS * 128 + 2 * AK_ROWS * 128)   // 57344 B

__global__ __launch_bounds__(128, 4) void attn_mma(const __half* __restrict__ qkv) {
    extern __shared__ char sm[];
    const uint32_t sbase = smem_u32(sm);
    const uint32_t Qb = sbase;
    const uint32_t Kb = sbase + AQ_ROWS * 128u;
    const uint32_t Vb = Kb + AK_ROWS * 128u;
    char* Kp = sm + AQ_ROWS * 128;
    char* Vp = Kp + AK_ROWS * 128;
    const int qt  = blockIdx.x * AQ_ROWS;
    const int h   = blockIdx.y;
    const int b   = blockIdx.z;
    const int tid = threadIdx.x;
    const int wid = tid >> 5;
    const int lane = tid & 31;

    // ---- Q rows: all 128 threads, 4 cp16 each ----
    {
        const int qrow  = tid >> 1;
        const int qhalf = tid & 1;
        const __half* src = qkv + (size_t)(b * T_DIM + qt + qrow) * QKV_W + h * D_DIM + qhalf * 32;
        const uint32_t rmask = (uint32_t)(qrow & 7) * 16u;
        #pragma unroll
        for (int c = 0; c < 4; c++) {
            const uint32_t boff = (uint32_t)qhalf * 64u + (uint32_t)c * 16u;
            cp16(Qb + (uint32_t)qrow * 128u + (boff ^ rmask), src + c * 8);
        }
    }
    // ---- K,V rows ----
    #pragma unroll
    for (int rep = 0; rep < 2; rep++) {
        const int row = tid + rep * 128;
        if (row >= AK_ROWS) break;
        const int j = qt - 128 + row;
        const uint32_t rmask = (uint32_t)(row & 7) * 16u;
        if (j >= 0) {
            const __half* ks = qkv + (size_t)(b * T_DIM + j) * QKV_W + E_DIM + h * D_DIM;
            const __half* vs = ks + E_DIM;
            #pragma unroll
            for (int c = 0; c < 8; c++) {
                const uint32_t so = (uint32_t)row * 128u + (((uint32_t)c * 16u) ^ rmask);
                cp16(Kb + so, ks + c * 8);
                cp16(Vb + so, vs + c * 8);
            }
        } else {
            const uint4 z = make_uint4(0, 0, 0, 0);
            #pragma unroll
            for (int c = 0; c < 8; c++) {
                const uint32_t so = (uint32_t)row * 128u + (((uint32_t)c * 16u) ^ rmask);
                *reinterpret_cast<uint4*>(Kp + so) = z;
                *reinterpret_cast<uint4*>(Vp + so) = z;
            }
        }
    }
    CP_COMMIT();
    CP_WAIT0();
    __syncthreads();

    uint32_t qf[4][4];
    {
        const uint32_t arow = (uint32_t)(wid * 16 + (lane & 15));
        const uint32_t amask = (arow & 7u) * 16u;
        const uint32_t acol = ((uint32_t)lane >> 4) * 16u;
        #pragma unroll
        for (int ki = 0; ki < 4; ki++)
            LDSM4(qf[ki], Qb + arow * 128u + (((uint32_t)ki * 32u + acol) ^ amask));
    }

    float o[8][4];
    #pragma unroll
    for (int u = 0; u < 8; u++)
        #pragma unroll
        for (int r = 0; r < 4; r++) o[u][r] = 0.0f;
    float l0 = 0.0f, l1 = 0.0f;
    const int i0 = qt + wid * 16 + (lane >> 2);
    const int i1 = i0 + 8;
    const int tq = lane & 3;
    const int wr0 = wid * 16;

    const uint32_t krow_l = (uint32_t)((lane & 7) + ((lane >> 4) << 3));
    const uint32_t kcol_l = (((uint32_t)lane >> 3) & 1u) * 16u;
    const uint32_t vrow_l = (uint32_t)((lane & 7) + (((lane >> 3) & 1) << 3));
    const uint32_t vcol_l = ((uint32_t)lane >> 4) * 16u;

    #pragma unroll
    for (int c = 0; c < 3; c++) {
        const int rk0 = wr0 + 48 * c;
        const int j0 = qt - 128 + rk0;
        if (j0 <= -48) continue;          // whole chunk precedes sequence start

        float st[6][4];
        #pragma unroll
        for (int u = 0; u < 6; u++)
            #pragma unroll
            for (int r = 0; r < 4; r++) st[u][r] = 0.0f;

        #pragma unroll
        for (int ki = 0; ki < 4; ki++) {
            uint32_t kf[3][4];
            #pragma unroll
            for (int g2 = 0; g2 < 3; g2++) {
                const uint32_t row = (uint32_t)rk0 + (uint32_t)g2 * 16u + krow_l;
                LDSM4(kf[g2], Kb + row * 128u + (((uint32_t)ki * 32u + kcol_l) ^ ((row & 7u) * 16u)));
            }
            #pragma unroll
            for (int u = 0; u < 6; u++)
                MMA16816H(st[u], qf[ki], kf[u >> 1][(u & 1) * 2], kf[u >> 1][(u & 1) * 2 + 1]);
        }

        uint32_t pf[6][2];
        if (c == 1 && j0 >= 0) {
            #pragma unroll
            for (int u = 0; u < 6; u++) {
                const float p0 = exp2f(st[u][0] * EXP_C);
                const float p1 = exp2f(st[u][1] * EXP_C);
                const float p2 = exp2f(st[u][2] * EXP_C);
                const float p3 = exp2f(st[u][3] * EXP_C);
                l0 += p0 + p1;
                l1 += p2 + p3;
                pf[u][0] = h2u(__floats2half2_rn(p0, p1));
                pf[u][1] = h2u(__floats2half2_rn(p2, p3));
            }
        } else {
            #pragma unroll
            for (int u = 0; u < 6; u++) {
                const int j = j0 + 8 * u + 2 * tq;
                const bool k0a = (j     <= i0) && (j     >= i0 - WIN) && (j     >= 0);
                const bool k0b = (j + 1 <= i0) && (j + 1 >= i0 - WIN) && (j + 1 >= 0);
                const bool k1a = (j     <= i1) && (j     >= i1 - WIN) && (j     >= 0);
                const bool k1b = (j + 1 <= i1) && (j + 1 >= i1 - WIN) && (j + 1 >= 0);
                const float p0 = k0a ? exp2f(st[u][0] * EXP_C) : 0.0f;
                const float p1 = k0b ? exp2f(st[u][1] * EXP_C) : 0.0f;
                const float p2 = k1a ? exp2f(st[u][2] * EXP_C) : 0.0f;
                const float p3 = k1b ? exp2f(st[u][3] * EXP_C) : 0.0f;
                l0 += p0 + p1;
                l1 += p2 + p3;
                pf[u][0] = h2u(__floats2half2_rn(p0, p1));
                pf[u][1] = h2u(__floats2half2_rn(p2, p3));
            }
        }

        #pragma unroll
        for (int kk = 0; kk < 3; kk++) {
            uint32_t af[4] = {pf[2 * kk][0], pf[2 * kk][1], pf[2 * kk + 1][0], pf[2 * kk + 1][1]};
            const uint32_t row = (uint32_t)rk0 + (uint32_t)kk * 16u + vrow_l;
            const uint32_t rm = (row & 7u) * 16u;
            #pragma unroll
            for (int g2 = 0; g2 < 4; g2++) {
                uint32_t vf[4];
                LDSM4T(vf, Vb + row * 128u + (((uint32_t)g2 * 32u + vcol_l) ^ rm));
                MMA16816H(o[2 * g2],     af, vf[0], vf[1]);
                MMA16816H(o[2 * g2 + 1], af, vf[2], vf[3]);
            }
        }
    }

    l0 += __shfl_xor_sync(0xffffffffu, l0, 1);
    l0 += __shfl_xor_sync(0xffffffffu, l0, 2);
    l1 += __shfl_xor_sync(0xffffffffu, l1, 1);
    l1 += __shfl_xor_sync(0xffffffffu, l1, 2);
    const float r0 = 1.0f / l0, r1 = 1.0f / l1;
    __half2* d0 = reinterpret_cast<__half2*>(
        g_ctx + (size_t)(b * T_DIM + i0) * E_DIM + h * D_DIM);
    __half2* d1 = reinterpret_cast<__half2*>(
        g_ctx + (size_t)(b * T_DIM + i1) * E_DIM + h * D_DIM);
    #pragma unroll
    for (int u = 0; u < 8; u++) {
        d0[4 * u + tq] = __floats2half2_rn(o[u][0] * r0, o[u][1] * r0);
        d1[4 * u + tq] = __floats2half2_rn(o[u][2] * r1, o[u][3] * r1);
    }
}

// ============================== launch ====================================
extern "C" void kernel_launch(void* const* d_in, const int* in_sizes, int n_in,
                              void* d_out, int out_size) {
    const float* x     = (const float*)d_in[0];
    const float* gamma = (const float*)d_in[2];
    const float* beta  = (const float*)d_in[3];
    const float* w_in  = (const float*)d_in[4];
    const float* b_in  = (const float*)d_in[5];
    const float* w_out = (const float*)d_in[6];
    const float* b_out = (const float*)d_in[7];
    float* out = (float*)d_out;

    __half *xn, *qkvh, *ctx, *win_hi, *wout_hi;
    cudaGetSymbolAddress((void**)&xn,      g_xn);
    cudaGetSymbolAddress((void**)&qkvh,    g_qkv);
    cudaGetSymbolAddress((void**)&ctx,     g_ctx);
    cudaGetSymbolAddress((void**)&win_hi,  g_win_hi);
    cudaGetSymbolAddress((void**)&wout_hi, g_wout_hi);

    cudaFuncSetAttribute((void*)gemm_mma<__half>,
                         cudaFuncAttributeMaxDynamicSharedMemorySize, SMEM_GEMM);
    cudaFuncSetAttribute((void*)gemm_mma<float>,
                         cudaFuncAttributeMaxDynamicSharedMemorySize, SMEM_GEMM);
    cudaFuncSetAttribute(attn_mma, cudaFuncAttributeMaxDynamicSharedMemorySize, ATTN_SMEM);

    const int n4_in   = QKV_W * E_DIM / 4;   // 196608
    const int n4_out  = E_DIM * E_DIM / 4;   // 65536
    const int n4_tot  = n4_in + n4_out;      // 262144
    const int conv_blocks = (n4_tot + 255) / 256;   // 1024

    ln_conv_kernel<<<LN_BLOCKS + conv_blocks, 128>>>(x, gamma, beta, w_in, w_out,
                                                     n4_in, n4_tot);
    gemm_mma<__half><<<dim3(QKV_W / 128, ROWS / 128), 256, SMEM_GEMM>>>(
        xn, win_hi, b_in, qkvh, QKV_W);
    attn_mma<<<dim3(T_DIM / AQ_ROWS, H_DIM, B_DIM), 128, ATTN_SMEM>>>(qkvh);
    gemm_mma<float><<<dim3(E_DIM / 128, ROWS / 128), 256, SMEM_GEMM>>>(
        ctx, wout_hi, b_out, out, E_DIM);
}

// round 17
// speedup vs baseline: 4.4690x; 1.0084x over previous
#include <cuda_runtime.h>
#include <cuda_fp16.h>
#include <math.h>
#include <stdint.h>

#define E_DIM 512
#define T_DIM 1024
#define B_DIM 8
#define H_DIM 8
#define D_DIM 64
#define WIN   128
#define ROWS  (B_DIM * T_DIM)   // 8192
#define QKV_W (3 * E_DIM)       // 1536
#define K_DIM 512
#define KC    64
#define NCHUNK (K_DIM / KC)               // 8
#define TILE_BYTES (128 * 128)            // 16 KB
#define SMEM_GEMM (96 * 1024)

// exp2 constant: 0.125 * log2(e)
#define EXP_C 0.18033688011112042f

// -------------------- scratch (__device__ globals) -------------------------
__device__ __half g_xn  [ROWS * E_DIM];
__device__ __half g_qkv [ROWS * QKV_W];
__device__ __half g_ctx [ROWS * E_DIM];
__device__ __half g_win_hi[QKV_W * E_DIM];
__device__ __half g_wout_hi[E_DIM * E_DIM];

// ============================ helpers ======================================
__device__ __forceinline__ uint32_t smem_u32(const void* p) {
    uint32_t a;
    asm("{ .reg .u64 t; cvta.to.shared.u64 t, %1; cvt.u32.u64 %0, t; }" : "=r"(a) : "l"(p));
    return a;
}
__device__ __forceinline__ void cp16(uint32_t dst, const void* src) {
    asm volatile("cp.async.cg.shared.global [%0], [%1], 16;" :: "r"(dst), "l"(src));
}
#define CP_COMMIT() asm volatile("cp.async.commit_group;" ::: "memory")
#define CP_WAIT2()  asm volatile("cp.async.wait_group 2;" ::: "memory")
#define CP_WAIT1()  asm volatile("cp.async.wait_group 1;" ::: "memory")
#define CP_WAIT0()  asm volatile("cp.async.wait_group 0;" ::: "memory")

#define LDSM4(R, addr)                                                          \
    asm volatile("ldmatrix.sync.aligned.m8n8.x4.shared.b16 {%0,%1,%2,%3}, [%4];" \
        : "=r"((R)[0]), "=r"((R)[1]), "=r"((R)[2]), "=r"((R)[3]) : "r"(addr))

#define LDSM4T(R, addr)                                                         \
    asm volatile("ldmatrix.sync.aligned.m8n8.x4.trans.shared.b16 {%0,%1,%2,%3}, [%4];" \
        : "=r"((R)[0]), "=r"((R)[1]), "=r"((R)[2]), "=r"((R)[3]) : "r"(addr))

#define MMA16816H(D, A, B0, B1)                                                 \
    asm volatile("mma.sync.aligned.m16n8k16.row.col.f32.f16.f16.f32 "           \
        "{%0,%1,%2,%3},{%4,%5,%6,%7},{%8,%9},{%0,%1,%2,%3};"                    \
        : "+f"((D)[0]), "+f"((D)[1]), "+f"((D)[2]), "+f"((D)[3])                \
        : "r"((A)[0]), "r"((A)[1]), "r"((A)[2]), "r"((A)[3]), "r"(B0), "r"(B1))

__device__ __forceinline__ uint32_t swz(uint32_t off) {
    return off ^ ((off >> 3) & 0x70u);
}
__device__ __forceinline__ uint32_t h2u(__half2 v) { return *reinterpret_cast<uint32_t*>(&v); }

__device__ __forceinline__ void st_pair(float* p, float a, float b) {
    *reinterpret_cast<float2*>(p) = make_float2(a, b);
}
__device__ __forceinline__ void st_pair(__half* p, float a, float b) {
    *reinterpret_cast<__half2*>(p) = __floats2half2_rn(a, b);
}

// ====== fused LayerNorm (warp-per-row, no block sync) + weight conv ========
#define LN_BLOCKS (ROWS / 4)     // 2048 blocks, 4 warps = 4 rows each
__global__ __launch_bounds__(128) void ln_conv_kernel(
    const float* __restrict__ x,
    const float* __restrict__ gamma,
    const float* __restrict__ beta,
    const float* __restrict__ w_in,
    const float* __restrict__ w_out,
    int n4_in, int n4_tot) {
    const int bid = blockIdx.x;
    const int tid = threadIdx.x;

    if (bid < LN_BLOCKS) {
        const int warp = tid >> 5, lane = tid & 31;
        const int row = bid * 4 + warp;
        const float4* xr = reinterpret_cast<const float4*>(x + (size_t)row * E_DIM);
        float4 v[4];
        float s = 0.f, ss = 0.f;
        #pragma unroll
        for (int k = 0; k < 4; k++) {
            v[k] = xr[lane + 32 * k];
            s  += v[k].x + v[k].y + v[k].z + v[k].w;
            ss += v[k].x * v[k].x + v[k].y * v[k].y + v[k].z * v[k].z + v[k].w * v[k].w;
        }
        #pragma unroll
        for (int o = 16; o > 0; o >>= 1) {
            s  += __shfl_xor_sync(0xffffffffu, s,  o);
            ss += __shfl_xor_sync(0xffffffffu, ss, o);
        }
        const float mu   = s * (1.0f / E_DIM);
        const float var  = ss * (1.0f / E_DIM) - mu * mu;
        const float rstd = rsqrtf(var + 1e-5f);
        __half2* orow = reinterpret_cast<__half2*>(g_xn + (size_t)row * E_DIM);
        #pragma unroll
        for (int k = 0; k < 4; k++) {
            const int idx = lane + 32 * k;
            const float4 g  = reinterpret_cast<const float4*>(gamma)[idx];
            const float4 be = reinterpret_cast<const float4*>(beta)[idx];
            float2 a, b;
            a.x = (v[k].x - mu) * rstd * g.x + be.x;
            a.y = (v[k].y - mu) * rstd * g.y + be.y;
            b.x = (v[k].z - mu) * rstd * g.z + be.z;
            b.y = (v[k].w - mu) * rstd * g.w + be.w;
            orow[2 * idx + 0] = __float22half2_rn(a);
            orow[2 * idx + 1] = __float22half2_rn(b);
        }
        return;
    }

    const int base = (bid - LN_BLOCKS) * 256 + tid;
    #pragma unroll
    for (int rep = 0; rep < 2; rep++) {
        const int i = base + rep * 128;
        if (i < n4_tot) {
            const float* src; __half* dst; int k;
            if (i < n4_in) { src = w_in;  dst = g_win_hi;  k = i; }
            else           { src = w_out; dst = g_wout_hi; k = i - n4_in; }
            const float4 v = reinterpret_cast<const float4*>(src)[k];
            __half2* oh = reinterpret_cast<__half2*>(dst);
            oh[2 * k + 0] = __floats2half2_rn(v.x, v.y);
            oh[2 * k + 1] = __floats2half2_rn(v.z, v.w);
        }
    }
}

// ===================== fp16 GEMM via mma.sync (1-term) =====================
template <typename OT>
__global__ __launch_bounds__(256, 2)
void gemm_mma(const __half* __restrict__ A, const __half* __restrict__ Wh,
              const float* __restrict__ bias, OT* __restrict__ C, const int N) {
    constexpr uint32_t WH_OFF = TILE_BYTES;
    constexpr uint32_t STAGE  = 2 * TILE_BYTES;
    constexpr int NST = 3;

    extern __shared__ char smem[];
    const uint32_t sbase = smem_u32(smem);
    const int tid  = threadIdx.x;
    const int wid  = tid >> 5;
    const int lane = tid & 31;
    const int bn = blockIdx.x * 128;
    const int bm = blockIdx.y * 128;

    const int lrow  = tid >> 1;
    const int lhalf = tid & 1;
    const __half* aS  = A  + (size_t)(bm + lrow) * K_DIM + lhalf * 32;
    const __half* wHS = Wh + (size_t)(bn + lrow) * K_DIM + lhalf * 32;
    uint32_t st_off[4];
    #pragma unroll
    for (int v = 0; v < 4; v++) {
        const uint32_t off = (uint32_t)lrow * 128u + (uint32_t)lhalf * 64u + (uint32_t)v * 16u;
        st_off[v] = swz(off);
    }

    auto load_stage = [&](int s, int c) {
        const uint32_t st = sbase + (uint32_t)s * STAGE;
        const int kc = c * KC;
        #pragma unroll
        for (int v = 0; v < 4; v++) {
            cp16(st + st_off[v],          aS  + kc + v * 8);
            cp16(st + WH_OFF + st_off[v], wHS + kc + v * 8);
        }
        CP_COMMIT();
    };

    const int wm = (wid & 1) * 64;
    const int wn = (wid >> 1) * 32;
    uint32_t a_rowoff[4], a_mask[4];
    #pragma unroll
    for (int mi = 0; mi < 4; mi++) {
        const uint32_t r = (uint32_t)(wm + mi * 16 + (lane & 15));
        a_rowoff[mi] = r * 128u;
        a_mask[mi]   = (a_rowoff[mi] >> 3) & 0x70u;
    }
    const uint32_t a_kb = ((uint32_t)lane >> 4) * 16u;
    const int b_lrow = (lane & 7) + ((lane >> 4) << 3);
    uint32_t b_rowoff[2], b_mask[2];
    #pragma unroll
    for (int np = 0; np < 2; np++) {
        const uint32_t r = (uint32_t)(wn + np * 16 + b_lrow);
        b_rowoff[np] = r * 128u;
        b_mask[np]   = (b_rowoff[np] >> 3) & 0x70u;
    }
    const uint32_t b_kb = (((uint32_t)lane >> 3) & 1u) * 16u;

    float acc[4][4][4];
    #pragma unroll
    for (int mi = 0; mi < 4; mi++)
        #pragma unroll
        for (int ni = 0; ni < 4; ni++)
            #pragma unroll
            for (int r = 0; r < 4; r++) acc[mi][ni][r] = 0.0f;

    load_stage(0, 0);
    load_stage(1, 1);

    #pragma unroll
    for (int c = 0; c < NCHUNK; c++) {
        const int s = c % NST;
        const uint32_t st = sbase + (uint32_t)s * STAGE;

        __syncthreads();
        if (c + 2 < NCHUNK) load_stage((c + 2) % NST, c + 2);

        if (c + 2 < NCHUNK)      CP_WAIT2();
        else if (c + 1 < NCHUNK) CP_WAIT1();
        else                     CP_WAIT0();

        #pragma unroll
        for (int ks = 0; ks < 4; ks++) {
            const uint32_t akb = (uint32_t)ks * 32u + a_kb;
            const uint32_t bkb = (uint32_t)ks * 32u + b_kb;
            uint32_t ar[4][4], bh[2][4];
            #pragma unroll
            for (int mi = 0; mi < 4; mi++)
                LDSM4(ar[mi], st + a_rowoff[mi] + (akb ^ a_mask[mi]));
            #pragma unroll
            for (int np = 0; np < 2; np++)
                LDSM4(bh[np], st + WH_OFF + b_rowoff[np] + (bkb ^ b_mask[np]));
            #pragma unroll
            for (int mi = 0; mi < 4; mi++)
                #pragma unroll
                for (int ni = 0; ni < 4; ni++) {
                    const int np = ni >> 1, po = (ni & 1) * 2;
                    MMA16816H(acc[mi][ni], ar[mi], bh[np][po], bh[np][po + 1]);
                }
        }
    }

    const int gid = lane >> 2;
    const int tig = lane & 3;
    #pragma unroll
    for (int mi = 0; mi < 4; mi++) {
        const int row0 = bm + wm + mi * 16 + gid;
        OT* C0 = C + (size_t)row0 * N;
        OT* C1 = C + (size_t)(row0 + 8) * N;
        #pragma unroll
        for (int ni = 0; ni < 4; ni++) {
            const int col = bn + wn + ni * 8 + tig * 2;
            const float b0 = bias[col], b1 = bias[col + 1];
            st_pair(C0 + col, acc[mi][ni][0] + b0, acc[mi][ni][1] + b1);
            st_pair(C1 + col, acc[mi][ni][2] + b0, acc[mi][ni][3] + b1);
        }
    }
}

// ================ Tensor-core windowed causal attention ====================
// CTA = (b, h, 64 queries), 128 threads / 4 warps; warp w owns queries
// [qt+16w, qt+16w+16), keys rows [16w, 16w+144) of 192-row K/V tiles.
// Q fragments loaded DIRECTLY from gmem (A-frag layout = per-thread half2
// at (row, k) — qkv is K-major so each reg is one aligned 4B load).
// Smem = K 24KB + V 24KB = 48KB -> 4 CTAs/SM (regs capped 128).
#define AQ_ROWS 64
#define AK_ROWS 192
#define ATTN_SMEM (2 * AK_ROWS * 128)   // 49152 B

__global__ __launch_bounds__(128, 4) void attn_mma(const __half* __restrict__ qkv) {
    extern __shared__ char sm[];
    const uint32_t sbase = smem_u32(sm);
    const uint32_t Kb = sbase;
    const uint32_t Vb = sbase + AK_ROWS * 128u;
    char* Kp = sm;
    char* Vp = sm + AK_ROWS * 128;
    const int qt  = blockIdx.x * AQ_ROWS;
    const int h   = blockIdx.y;
    const int b   = blockIdx.z;
    const int tid = threadIdx.x;
    const int wid = tid >> 5;
    const int lane = tid & 31;
    const int tq = lane & 3;

    // ---- Q fragments: direct gmem loads (overlap with K/V cp.async) ----
    const int q_row0 = wid * 16 + (lane >> 2);
    const __half* qr0 = qkv + (size_t)(b * T_DIM + qt + q_row0) * QKV_W + h * D_DIM + tq * 2;
    const __half* qr1 = qr0 + 8 * QKV_W;
    uint32_t qf[4][4];
    #pragma unroll
    for (int ki = 0; ki < 4; ki++) {
        qf[ki][0] = *reinterpret_cast<const uint32_t*>(qr0 + ki * 16);
        qf[ki][1] = *reinterpret_cast<const uint32_t*>(qr1 + ki * 16);
        qf[ki][2] = *reinterpret_cast<const uint32_t*>(qr0 + ki * 16 + 8);
        qf[ki][3] = *reinterpret_cast<const uint32_t*>(qr1 + ki * 16 + 8);
    }

    // ---- K,V rows: thread t loads row t; threads 0..63 also row 128+t ----
    #pragma unroll
    for (int rep = 0; rep < 2; rep++) {
        const int row = tid + rep * 128;
        if (row >= AK_ROWS) break;
        const int j = qt - 128 + row;
        const uint32_t rmask = (uint32_t)(row & 7) * 16u;
        if (j >= 0) {
            const __half* ks = qkv + (size_t)(b * T_DIM + j) * QKV_W + E_DIM + h * D_DIM;
            const __half* vs = ks + E_DIM;
            #pragma unroll
            for (int c = 0; c < 8; c++) {
                const uint32_t so = (uint32_t)row * 128u + (((uint32_t)c * 16u) ^ rmask);
                cp16(Kb + so, ks + c * 8);
                cp16(Vb + so, vs + c * 8);
            }
        } else {
            const uint4 z = make_uint4(0, 0, 0, 0);
            #pragma unroll
            for (int c = 0; c < 8; c++) {
                const uint32_t so = (uint32_t)row * 128u + (((uint32_t)c * 16u) ^ rmask);
                *reinterpret_cast<uint4*>(Kp + so) = z;
                *reinterpret_cast<uint4*>(Vp + so) = z;
            }
        }
    }
    CP_COMMIT();
    CP_WAIT0();
    __syncthreads();

    float o[8][4];
    #pragma unroll
    for (int u = 0; u < 8; u++)
        #pragma unroll
        for (int r = 0; r < 4; r++) o[u][r] = 0.0f;
    float l0 = 0.0f, l1 = 0.0f;
    const int i0 = qt + q_row0;
    const int i1 = i0 + 8;
    const int wr0 = wid * 16;

    const uint32_t krow_l = (uint32_t)((lane & 7) + ((lane >> 4) << 3));
    const uint32_t kcol_l = (((uint32_t)lane >> 3) & 1u) * 16u;
    const uint32_t vrow_l = (uint32_t)((lane & 7) + (((lane >> 3) & 1) << 3));
    const uint32_t vcol_l = ((uint32_t)lane >> 4) * 16u;

    #pragma unroll
    for (int c = 0; c < 3; c++) {
        const int rk0 = wr0 + 48 * c;
        const int j0 = qt - 128 + rk0;
        if (j0 <= -48) continue;          // whole chunk precedes sequence start

        float st[6][4];
        #pragma unroll
        for (int u = 0; u < 6; u++)
            #pragma unroll
            for (int r = 0; r < 4; r++) st[u][r] = 0.0f;

        #pragma unroll
        for (int ki = 0; ki < 4; ki++) {
            uint32_t kf[3][4];
            #pragma unroll
            for (int g2 = 0; g2 < 3; g2++) {
                const uint32_t row = (uint32_t)rk0 + (uint32_t)g2 * 16u + krow_l;
                LDSM4(kf[g2], Kb + row * 128u + (((uint32_t)ki * 32u + kcol_l) ^ ((row & 7u) * 16u)));
            }
            #pragma unroll
            for (int u = 0; u < 6; u++)
                MMA16816H(st[u], qf[ki], kf[u >> 1][(u & 1) * 2], kf[u >> 1][(u & 1) * 2 + 1]);
        }

        uint32_t pf[6][2];
        if (c == 1 && j0 >= 0) {
            #pragma unroll
            for (int u = 0; u < 6; u++) {
                const float p0 = exp2f(st[u][0] * EXP_C);
                const float p1 = exp2f(st[u][1] * EXP_C);
                const float p2 = exp2f(st[u][2] * EXP_C);
                const float p3 = exp2f(st[u][3] * EXP_C);
                l0 += p0 + p1;
                l1 += p2 + p3;
                pf[u][0] = h2u(__floats2half2_rn(p0, p1));
                pf[u][1] = h2u(__floats2half2_rn(p2, p3));
            }
        } else {
            #pragma unroll
            for (int u = 0; u < 6; u++) {
                const int j = j0 + 8 * u + 2 * tq;
                const bool k0a = (j     <= i0) && (j     >= i0 - WIN) && (j     >= 0);
                const bool k0b = (j + 1 <= i0) && (j + 1 >= i0 - WIN) && (j + 1 >= 0);
                const bool k1a = (j     <= i1) && (j     >= i1 - WIN) && (j     >= 0);
                const bool k1b = (j + 1 <= i1) && (j + 1 >= i1 - WIN) && (j + 1 >= 0);
                const float p0 = k0a ? exp2f(st[u][0] * EXP_C) : 0.0f;
                const float p1 = k0b ? exp2f(st[u][1] * EXP_C) : 0.0f;
                const float p2 = k1a ? exp2f(st[u][2] * EXP_C) : 0.0f;
                const float p3 = k1b ? exp2f(st[u][3] * EXP_C) : 0.0f;
                l0 += p0 + p1;
                l1 += p2 + p3;
                pf[u][0] = h2u(__floats2half2_rn(p0, p1));
                pf[u][1] = h2u(__floats2half2_rn(p2, p3));
            }
        }

        #pragma unroll
        for (int kk = 0; kk < 3; kk++) {
            uint32_t af[4] = {pf[2 * kk][0], pf[2 * kk][1], pf[2 * kk + 1][0], pf[2 * kk + 1][1]};
            const uint32_t row = (uint32_t)rk0 + (uint32_t)kk * 16u + vrow_l;
            const uint32_t rm = (row & 7u) * 16u;
            #pragma unroll
            for (int g2 = 0; g2 < 4; g2++) {
                uint32_t vf[4];
                LDSM4T(vf, Vb + row * 128u + (((uint32_t)g2 * 32u + vcol_l) ^ rm));
                MMA16816H(o[2 * g2],     af, vf[0], vf[1]);
                MMA16816H(o[2 * g2 + 1], af, vf[2], vf[3]);
            }
        }
    }

    l0 += __shfl_xor_sync(0xffffffffu, l0, 1);
    l0 += __shfl_xor_sync(0xffffffffu, l0, 2);
    l1 += __shfl_xor_sync(0xffffffffu, l1, 1);
    l1 += __shfl_xor_sync(0xffffffffu, l1, 2);
    const float r0 = 1.0f / l0, r1 = 1.0f / l1;
    __half2* d0 = reinterpret_cast<__half2*>(
        g_ctx + (size_t)(b * T_DIM + i0) * E_DIM + h * D_DIM);
    __half2* d1 = reinterpret_cast<__half2*>(
        g_ctx + (size_t)(b * T_DIM + i1) * E_DIM + h * D_DIM);
    #pragma unroll
    for (int u = 0; u < 8; u++) {
        d0[4 * u + tq] = __floats2half2_rn(o[u][0] * r0, o[u][1] * r0);
        d1[4 * u + tq] = __floats2half2_rn(o[u][2] * r1, o[u][3] * r1);
    }
}

// ============================== launch ====================================
extern "C" void kernel_launch(void* const* d_in, const int* in_sizes, int n_in,
                              void* d_out, int out_size) {
    const float* x     = (const float*)d_in[0];
    const float* gamma = (const float*)d_in[2];
    const float* beta  = (const float*)d_in[3];
    const float* w_in  = (const float*)d_in[4];
    const float* b_in  = (const float*)d_in[5];
    const float* w_out = (const float*)d_in[6];
    const float* b_out = (const float*)d_in[7];
    float* out = (float*)d_out;

    __half *xn, *qkvh, *ctx, *win_hi, *wout_hi;
    cudaGetSymbolAddress((void**)&xn,      g_xn);
    cudaGetSymbolAddress((void**)&qkvh,    g_qkv);
    cudaGetSymbolAddress((void**)&ctx,     g_ctx);
    cudaGetSymbolAddress((void**)&win_hi,  g_win_hi);
    cudaGetSymbolAddress((void**)&wout_hi, g_wout_hi);

    cudaFuncSetAttribute((void*)gemm_mma<__half>,
                         cudaFuncAttributeMaxDynamicSharedMemorySize, SMEM_GEMM);
    cudaFuncSetAttribute((void*)gemm_mma<float>,
                         cudaFuncAttributeMaxDynamicSharedMemorySize, SMEM_GEMM);
    cudaFuncSetAttribute(attn_mma, cudaFuncAttributeMaxDynamicSharedMemorySize, ATTN_SMEM);

    const int n4_in   = QKV_W * E_DIM / 4;   // 196608
    const int n4_out  = E_DIM * E_DIM / 4;   // 65536
    const int n4_tot  = n4_in + n4_out;      // 262144
    const int conv_blocks = (n4_tot + 255) / 256;   // 1024

    ln_conv_kernel<<<LN_BLOCKS + conv_blocks, 128>>>(x, gamma, beta, w_in, w_out,
                                                     n4_in, n4_tot);
    gemm_mma<__half><<<dim3(QKV_W / 128, ROWS / 128), 256, SMEM_GEMM>>>(
        xn, win_hi, b_in, qkvh, QKV_W);
    attn_mma<<<dim3(T_DIM / AQ_ROWS, H_DIM, B_DIM), 128, ATTN_SMEM>>>(qkvh);
    gemm_mma<float><<<dim3(E_DIM / 128, ROWS / 128), 256, SMEM_GEMM>>>(
        ctx, wout_hi, b_out, out, E_DIM);
}